// round 1
// baseline (speedup 1.0000x reference)
#include <cuda_runtime.h>
#include <cstdint>

#define N_NODES 100000
#define N_EDGES 1600000
#define E_TOT   (N_EDGES + N_NODES)   // + self loops
#define N_FEAT  165
#define HIDDEN  128
#define NEG_SLOPE 0.2f

// ---------------- scratch (static __device__ arrays; no allocation) -------
__device__ float g_xl[(size_t)N_NODES * HIDDEN];
__device__ float g_xr[(size_t)N_NODES * HIDDEN];
__device__ float g_h [(size_t)N_NODES * HIDDEN];
__device__ float g_score[E_TOT];
__device__ float g_m[N_NODES];
__device__ float g_denom[N_NODES];
__device__ float g_hl[N_NODES * 2];
__device__ float g_hr[N_NODES * 2];

// ---------------- helpers ----------------
__device__ __forceinline__ void atomicMaxF(float* addr, float v) {
    if (v >= 0.f) atomicMax((int*)addr, __float_as_int(v));
    else          atomicMin((unsigned int*)addr, __float_as_uint(v));
}

__device__ __forceinline__ float warpSum(float v) {
    #pragma unroll
    for (int o = 16; o > 0; o >>= 1) v += __shfl_xor_sync(0xffffffffu, v, o);
    return v;
}

__device__ __forceinline__ void redAdd4(float* p, float a, float b, float c, float d) {
    asm volatile("red.global.add.v4.f32 [%0], {%1,%2,%3,%4};"
                 :: "l"(p), "f"(a), "f"(b), "f"(c), "f"(d) : "memory");
}

__device__ __forceinline__ float lrelu(float v) {
    return v > 0.f ? v : NEG_SLOPE * v;
}

// ---------------- GEMM: Y = X[100k x 165] @ W[165 x 128] + b ----------------
// 128x128 output tile per block, 256 threads, 8x8 microtile per thread.
template<int TARGET>   // 0 -> g_xl, 1 -> g_xr
__global__ void __launch_bounds__(256) gemm1(const float* __restrict__ X,
                                             const float* __restrict__ W,
                                             const float* __restrict__ bias) {
    __shared__ float Xs[32][129];   // [k][m], padded
    __shared__ float Ws[32][128];   // [k][n]

    float* __restrict__ Y = (TARGET == 0) ? g_xl : g_xr;

    const int tid = threadIdx.x;
    const int tx = tid & 15;        // 16 cols of threads
    const int ty = tid >> 4;        // 16 rows of threads
    const int row0 = blockIdx.x * 128;

    float acc[8][8];
    #pragma unroll
    for (int i = 0; i < 8; i++)
        #pragma unroll
        for (int j = 0; j < 8; j++) acc[i][j] = 0.f;

    for (int k0 = 0; k0 < N_FEAT; k0 += 32) {
        // load X tile: 128 rows x 32 k
        #pragma unroll
        for (int i = 0; i < 16; i++) {
            int lin = tid + i * 256;
            int m = lin >> 5, k = lin & 31;
            int gr = row0 + m, gk = k0 + k;
            float v = 0.f;
            if (gr < N_NODES && gk < N_FEAT) v = X[(size_t)gr * N_FEAT + gk];
            Xs[k][m] = v;
        }
        // load W tile: 32 k x 128 n
        #pragma unroll
        for (int i = 0; i < 16; i++) {
            int lin = tid + i * 256;
            int k = lin >> 7, n = lin & 127;
            int gk = k0 + k;
            Ws[k][n] = (gk < N_FEAT) ? W[gk * HIDDEN + n] : 0.f;
        }
        __syncthreads();

        #pragma unroll
        for (int k = 0; k < 32; k++) {
            float a[8], b[8];
            #pragma unroll
            for (int i = 0; i < 8; i++) a[i] = Xs[k][ty * 8 + i];
            #pragma unroll
            for (int j = 0; j < 8; j++) b[j] = Ws[k][tx * 8 + j];
            #pragma unroll
            for (int i = 0; i < 8; i++)
                #pragma unroll
                for (int j = 0; j < 8; j++) acc[i][j] += a[i] * b[j];
        }
        __syncthreads();
    }

    #pragma unroll
    for (int i = 0; i < 8; i++) {
        int r = row0 + ty * 8 + i;
        if (r < N_NODES) {
            #pragma unroll
            for (int j = 0; j < 8; j++) {
                int c = tx * 8 + j;
                Y[(size_t)r * HIDDEN + c] = acc[i][j] + bias[c];
            }
        }
    }
}

// ---------------- init kernels ----------------
__global__ void init_l1() {
    int i = blockIdx.x * blockDim.x + threadIdx.x;
    if (i < N_NODES * HIDDEN) g_h[i] = 0.f;
    if (i < N_NODES) {
        g_m[i] = __int_as_float(0xff800000);  // -inf
        g_denom[i] = 0.f;
    }
}

__global__ void init_l2(const float* __restrict__ bias2, float* __restrict__ out) {
    int i = blockIdx.x * blockDim.x + threadIdx.x;
    if (i < N_NODES) {
        g_m[i] = __int_as_float(0xff800000);
        g_denom[i] = 0.f;
        out[2 * i + 0] = bias2[0];
        out[2 * i + 1] = bias2[1];
    }
}

// ---------------- layer 1 edge kernels ----------------
__global__ void edge_score1(const int* __restrict__ src, const int* __restrict__ dst,
                            const float* __restrict__ att) {
    int w = (blockIdx.x * blockDim.x + threadIdx.x) >> 5;
    int lane = threadIdx.x & 31;
    if (w >= E_TOT) return;
    int s, d;
    if (w < N_EDGES) { s = src[w]; d = dst[w]; }
    else             { s = w - N_EDGES; d = s; }

    float4 a = ((const float4*)(g_xl + (size_t)s * HIDDEN))[lane];
    float4 b = ((const float4*)(g_xr + (size_t)d * HIDDEN))[lane];
    float4 t = ((const float4*)att)[lane];

    float p = 0.f;
    p += lrelu(a.x + b.x) * t.x;
    p += lrelu(a.y + b.y) * t.y;
    p += lrelu(a.z + b.z) * t.z;
    p += lrelu(a.w + b.w) * t.w;
    p = warpSum(p);

    if (lane == 0) {
        g_score[w] = p;
        atomicMaxF(&g_m[d], p);
    }
}

__global__ void edge_exp(const int* __restrict__ dst) {
    int e = blockIdx.x * blockDim.x + threadIdx.x;
    if (e >= E_TOT) return;
    int d = (e < N_EDGES) ? dst[e] : e - N_EDGES;
    float a = __expf(g_score[e] - g_m[d]);
    g_score[e] = a;
    atomicAdd(&g_denom[d], a);
}

__global__ void edge_agg1(const int* __restrict__ src, const int* __restrict__ dst) {
    int w = (blockIdx.x * blockDim.x + threadIdx.x) >> 5;
    int lane = threadIdx.x & 31;
    if (w >= E_TOT) return;
    int s, d;
    if (w < N_EDGES) { s = src[w]; d = dst[w]; }
    else             { s = w - N_EDGES; d = s; }

    float alpha = g_score[w] / g_denom[d];
    float4 a = ((const float4*)(g_xl + (size_t)s * HIDDEN))[lane];
    float* p = g_h + (size_t)d * HIDDEN + lane * 4;
    redAdd4(p, alpha * a.x, alpha * a.y, alpha * a.z, alpha * a.w);
}

__global__ void relu_bias(const float* __restrict__ bias1) {
    int i = blockIdx.x * blockDim.x + threadIdx.x;
    if (i < N_NODES * HIDDEN) {
        float v = g_h[i] + bias1[i & 127];
        g_h[i] = v > 0.f ? v : 0.f;
    }
}

// ---------------- layer 2 ----------------
__global__ void lin2(const float* __restrict__ W2l, const float* __restrict__ b2l,
                     const float* __restrict__ W2r, const float* __restrict__ b2r) {
    int w = (blockIdx.x * blockDim.x + threadIdx.x) >> 5;
    int lane = threadIdx.x & 31;
    if (w >= N_NODES) return;

    float4 h = ((const float4*)(g_h + (size_t)w * HIDDEN))[lane];
    int k = lane * 4;
    float s0 = h.x * W2l[(k + 0) * 2 + 0] + h.y * W2l[(k + 1) * 2 + 0]
             + h.z * W2l[(k + 2) * 2 + 0] + h.w * W2l[(k + 3) * 2 + 0];
    float s1 = h.x * W2l[(k + 0) * 2 + 1] + h.y * W2l[(k + 1) * 2 + 1]
             + h.z * W2l[(k + 2) * 2 + 1] + h.w * W2l[(k + 3) * 2 + 1];
    float s2 = h.x * W2r[(k + 0) * 2 + 0] + h.y * W2r[(k + 1) * 2 + 0]
             + h.z * W2r[(k + 2) * 2 + 0] + h.w * W2r[(k + 3) * 2 + 0];
    float s3 = h.x * W2r[(k + 0) * 2 + 1] + h.y * W2r[(k + 1) * 2 + 1]
             + h.z * W2r[(k + 2) * 2 + 1] + h.w * W2r[(k + 3) * 2 + 1];
    s0 = warpSum(s0); s1 = warpSum(s1); s2 = warpSum(s2); s3 = warpSum(s3);
    if (lane == 0) {
        g_hl[2 * w + 0] = s0 + b2l[0];
        g_hl[2 * w + 1] = s1 + b2l[1];
        g_hr[2 * w + 0] = s2 + b2r[0];
        g_hr[2 * w + 1] = s3 + b2r[1];
    }
}

__global__ void edge_score2(const int* __restrict__ src, const int* __restrict__ dst,
                            const float* __restrict__ att2) {
    int e = blockIdx.x * blockDim.x + threadIdx.x;
    if (e >= E_TOT) return;
    int s, d;
    if (e < N_EDGES) { s = src[e]; d = dst[e]; }
    else             { s = e - N_EDGES; d = s; }
    float e0 = lrelu(g_hl[2 * s + 0] + g_hr[2 * d + 0]);
    float e1 = lrelu(g_hl[2 * s + 1] + g_hr[2 * d + 1]);
    float sc = e0 * att2[0] + e1 * att2[1];
    g_score[e] = sc;
    atomicMaxF(&g_m[d], sc);
}

__global__ void edge_agg2(const int* __restrict__ src, const int* __restrict__ dst,
                          float* __restrict__ out) {
    int e = blockIdx.x * blockDim.x + threadIdx.x;
    if (e >= E_TOT) return;
    int s, d;
    if (e < N_EDGES) { s = src[e]; d = dst[e]; }
    else             { s = e - N_EDGES; d = s; }
    float alpha = g_score[e] / g_denom[d];
    atomicAdd(&out[2 * d + 0], alpha * g_hl[2 * s + 0]);
    atomicAdd(&out[2 * d + 1], alpha * g_hl[2 * s + 1]);
}

// ---------------- launch ----------------
extern "C" void kernel_launch(void* const* d_in, const int* in_sizes, int n_in,
                              void* d_out, int out_size) {
    const float* x    = (const float*)d_in[0];
    const int*   src  = (const int*)  d_in[1];
    const int*   dst  = (const int*)  d_in[2];
    const float* W1l  = (const float*)d_in[3];
    const float* b1l  = (const float*)d_in[4];
    const float* W1r  = (const float*)d_in[5];
    const float* b1r  = (const float*)d_in[6];
    const float* att1 = (const float*)d_in[7];
    const float* bias1= (const float*)d_in[8];
    const float* W2l  = (const float*)d_in[9];
    const float* b2l  = (const float*)d_in[10];
    const float* W2r  = (const float*)d_in[11];
    const float* b2r  = (const float*)d_in[12];
    const float* att2 = (const float*)d_in[13];
    const float* bias2= (const float*)d_in[14];
    float* out = (float*)d_out;

    const int gemmBlocks = (N_NODES + 127) / 128;          // 782
    const int nhBlocks   = (N_NODES * HIDDEN + 255) / 256; // 50000
    const int edgeWarpBlocks   = (E_TOT * 32 + 255) / 256; // 212500
    const int edgeThreadBlocks = (E_TOT + 255) / 256;      // 6641
    const int nodeBlocks = (N_NODES + 255) / 256;          // 391
    const int nodeWarpBlocks = (N_NODES * 32 + 255) / 256; // 12500

    // layer 1
    gemm1<0><<<gemmBlocks, 256>>>(x, W1l, b1l);
    gemm1<1><<<gemmBlocks, 256>>>(x, W1r, b1r);
    init_l1<<<nhBlocks, 256>>>();
    edge_score1<<<edgeWarpBlocks, 256>>>(src, dst, att1);
    edge_exp<<<edgeThreadBlocks, 256>>>(dst);
    edge_agg1<<<edgeWarpBlocks, 256>>>(src, dst);
    relu_bias<<<nhBlocks, 256>>>(bias1);

    // layer 2
    lin2<<<nodeWarpBlocks, 256>>>(W2l, b2l, W2r, b2r);
    init_l2<<<nodeBlocks, 256>>>(bias2, out);
    edge_score2<<<edgeThreadBlocks, 256>>>(src, dst, att2);
    edge_exp<<<edgeThreadBlocks, 256>>>(dst);
    edge_agg2<<<edgeThreadBlocks, 256>>>(src, dst, out);
}

// round 4
// speedup vs baseline: 1.2173x; 1.2173x over previous
#include <cuda_runtime.h>
#include <cstdint>

#define N_NODES 100000
#define N_EDGES 1600000
#define E_TOT   (N_EDGES + N_NODES)   // + self loops
#define N_FEAT  165
#define HIDDEN  128
#define NEG_SLOPE 0.2f

// ---------------- scratch (static __device__ arrays; no allocation) -------
__device__ float g_xl[(size_t)N_NODES * HIDDEN];
__device__ float g_xr[(size_t)N_NODES * HIDDEN];
__device__ float g_h [(size_t)N_NODES * HIDDEN];
__device__ float g_score[E_TOT];
__device__ float g_m[N_NODES];
__device__ float g_denom[N_NODES];
__device__ float g_hl[N_NODES * 2];
__device__ float g_hr[N_NODES * 2];

// ---------------- helpers ----------------
__device__ __forceinline__ void atomicMaxF(float* addr, float v) {
    if (v >= 0.f) atomicMax((int*)addr, __float_as_int(v));
    else          atomicMin((unsigned int*)addr, __float_as_uint(v));
}

__device__ __forceinline__ float warpSum(float v) {
    #pragma unroll
    for (int o = 16; o > 0; o >>= 1) v += __shfl_xor_sync(0xffffffffu, v, o);
    return v;
}

__device__ __forceinline__ void redAdd4(float* p, float a, float b, float c, float d) {
    asm volatile("red.global.add.v4.f32 [%0], {%1,%2,%3,%4};"
                 :: "l"(p), "f"(a), "f"(b), "f"(c), "f"(d) : "memory");
}

__device__ __forceinline__ float lrelu(float v) {
    return v > 0.f ? v : NEG_SLOPE * v;
}

// ---------------- GEMM: Y = X[100k x 165] @ W[165 x 128] + b ----------------
// (identical to the round-1 kernel that passed at rel_err 1e-7)
template<int TARGET>   // 0 -> g_xl, 1 -> g_xr
__global__ void __launch_bounds__(256) gemm1(const float* __restrict__ X,
                                             const float* __restrict__ W,
                                             const float* __restrict__ bias) {
    __shared__ float Xs[32][129];   // [k][m], padded
    __shared__ float Ws[32][128];   // [k][n]

    float* __restrict__ Y = (TARGET == 0) ? g_xl : g_xr;

    const int tid = threadIdx.x;
    const int tx = tid & 15;        // 16 cols of threads
    const int ty = tid >> 4;        // 16 rows of threads
    const int row0 = blockIdx.x * 128;

    float acc[8][8];
    #pragma unroll
    for (int i = 0; i < 8; i++)
        #pragma unroll
        for (int j = 0; j < 8; j++) acc[i][j] = 0.f;

    for (int k0 = 0; k0 < N_FEAT; k0 += 32) {
        #pragma unroll
        for (int i = 0; i < 16; i++) {
            int lin = tid + i * 256;
            int m = lin >> 5, k = lin & 31;
            int gr = row0 + m, gk = k0 + k;
            float v = 0.f;
            if (gr < N_NODES && gk < N_FEAT) v = X[(size_t)gr * N_FEAT + gk];
            Xs[k][m] = v;
        }
        #pragma unroll
        for (int i = 0; i < 16; i++) {
            int lin = tid + i * 256;
            int k = lin >> 7, n = lin & 127;
            int gk = k0 + k;
            Ws[k][n] = (gk < N_FEAT) ? W[gk * HIDDEN + n] : 0.f;
        }
        __syncthreads();

        #pragma unroll
        for (int k = 0; k < 32; k++) {
            float a[8], b[8];
            #pragma unroll
            for (int i = 0; i < 8; i++) a[i] = Xs[k][ty * 8 + i];
            #pragma unroll
            for (int j = 0; j < 8; j++) b[j] = Ws[k][tx * 8 + j];
            #pragma unroll
            for (int i = 0; i < 8; i++)
                #pragma unroll
                for (int j = 0; j < 8; j++) acc[i][j] += a[i] * b[j];
        }
        __syncthreads();
    }

    #pragma unroll
    for (int i = 0; i < 8; i++) {
        int r = row0 + ty * 8 + i;
        if (r < N_NODES) {
            #pragma unroll
            for (int j = 0; j < 8; j++) {
                int c = tx * 8 + j;
                Y[(size_t)r * HIDDEN + c] = acc[i][j] + bias[c];
            }
        }
    }
}

// ---------------- init kernels ----------------
__global__ void init_l1() {
    int i = blockIdx.x * blockDim.x + threadIdx.x;
    if (i < N_NODES * HIDDEN) g_h[i] = 0.f;
    if (i < N_NODES) {
        g_m[i] = __int_as_float(0xff800000);  // -inf
        g_denom[i] = 0.f;
    }
}

__global__ void init_l2(const float* __restrict__ bias2, float* __restrict__ out) {
    int i = blockIdx.x * blockDim.x + threadIdx.x;
    if (i < N_NODES) {
        g_m[i] = __int_as_float(0xff800000);
        g_denom[i] = 0.f;
        out[2 * i + 0] = bias2[0];
        out[2 * i + 1] = bias2[1];
    }
}

// ---------------- layer 1 edge kernels: 8 lanes per edge, 4 edges per warp -
// Each lane handles 4 float4 chunks: gl, gl+8, gl+16, gl+24  (32 chunks = 128 floats)
__global__ void edge_score1(const int* __restrict__ src, const int* __restrict__ dst,
                            const float* __restrict__ att) {
    int gwarp = (blockIdx.x * blockDim.x + threadIdx.x) >> 5;
    int lane = threadIdx.x & 31;
    int grp = lane >> 3;   // 0..3
    int gl  = lane & 7;    // lane within group
    int e = gwarp * 4 + grp;
    if (e >= E_TOT) return;

    int s, d;
    if (e < N_EDGES) { s = src[e]; d = dst[e]; }
    else             { s = e - N_EDGES; d = s; }

    const float4* pa = (const float4*)(g_xl + (size_t)s * HIDDEN);
    const float4* pb = (const float4*)(g_xr + (size_t)d * HIDDEN);
    const float4* pt = (const float4*)att;   // global, well-aligned buffer

    float p = 0.f;
    #pragma unroll
    for (int c = 0; c < 4; c++) {
        int idx = gl + c * 8;
        float4 a = pa[idx];
        float4 b = pb[idx];
        float4 t = __ldg(&pt[idx]);
        p += lrelu(a.x + b.x) * t.x + lrelu(a.y + b.y) * t.y;
        p += lrelu(a.z + b.z) * t.z + lrelu(a.w + b.w) * t.w;
    }

    // reduce within 8-lane group (3 butterfly steps serve all 4 groups at once)
    p += __shfl_xor_sync(0xffffffffu, p, 1);
    p += __shfl_xor_sync(0xffffffffu, p, 2);
    p += __shfl_xor_sync(0xffffffffu, p, 4);

    if (gl == 0) {
        g_score[e] = p;
        atomicMaxF(&g_m[d], p);
    }
}

__global__ void edge_exp(const int* __restrict__ dst) {
    int e = blockIdx.x * blockDim.x + threadIdx.x;
    if (e >= E_TOT) return;
    int d = (e < N_EDGES) ? dst[e] : e - N_EDGES;
    float a = __expf(g_score[e] - g_m[d]);
    g_score[e] = a;
    atomicAdd(&g_denom[d], a);
}

__global__ void edge_agg1(const int* __restrict__ src, const int* __restrict__ dst) {
    int gwarp = (blockIdx.x * blockDim.x + threadIdx.x) >> 5;
    int lane = threadIdx.x & 31;
    int grp = lane >> 3;
    int gl  = lane & 7;
    int e = gwarp * 4 + grp;
    if (e >= E_TOT) return;

    int s, d;
    if (e < N_EDGES) { s = src[e]; d = dst[e]; }
    else             { s = e - N_EDGES; d = s; }

    float alpha = __fdividef(g_score[e], g_denom[d]);

    const float4* pa = (const float4*)(g_xl + (size_t)s * HIDDEN);
    float* po = g_h + (size_t)d * HIDDEN;

    #pragma unroll
    for (int c = 0; c < 4; c++) {
        int idx = gl + c * 8;
        float4 a = pa[idx];
        redAdd4(po + idx * 4, alpha * a.x, alpha * a.y, alpha * a.z, alpha * a.w);
    }
}

__global__ void relu_bias(const float* __restrict__ bias1) {
    int i = blockIdx.x * blockDim.x + threadIdx.x;
    if (i < N_NODES * HIDDEN) {
        float v = g_h[i] + bias1[i & 127];
        g_h[i] = v > 0.f ? v : 0.f;
    }
}

// ---------------- layer 2 ----------------
__global__ void lin2(const float* __restrict__ W2l, const float* __restrict__ b2l,
                     const float* __restrict__ W2r, const float* __restrict__ b2r) {
    int w = (blockIdx.x * blockDim.x + threadIdx.x) >> 5;
    int lane = threadIdx.x & 31;
    if (w >= N_NODES) return;

    float4 h = ((const float4*)(g_h + (size_t)w * HIDDEN))[lane];
    int k = lane * 4;
    float s0 = h.x * W2l[(k + 0) * 2 + 0] + h.y * W2l[(k + 1) * 2 + 0]
             + h.z * W2l[(k + 2) * 2 + 0] + h.w * W2l[(k + 3) * 2 + 0];
    float s1 = h.x * W2l[(k + 0) * 2 + 1] + h.y * W2l[(k + 1) * 2 + 1]
             + h.z * W2l[(k + 2) * 2 + 1] + h.w * W2l[(k + 3) * 2 + 1];
    float s2 = h.x * W2r[(k + 0) * 2 + 0] + h.y * W2r[(k + 1) * 2 + 0]
             + h.z * W2r[(k + 2) * 2 + 0] + h.w * W2r[(k + 3) * 2 + 0];
    float s3 = h.x * W2r[(k + 0) * 2 + 1] + h.y * W2r[(k + 1) * 2 + 1]
             + h.z * W2r[(k + 2) * 2 + 1] + h.w * W2r[(k + 3) * 2 + 1];
    s0 = warpSum(s0); s1 = warpSum(s1); s2 = warpSum(s2); s3 = warpSum(s3);
    if (lane == 0) {
        g_hl[2 * w + 0] = s0 + b2l[0];
        g_hl[2 * w + 1] = s1 + b2l[1];
        g_hr[2 * w + 0] = s2 + b2r[0];
        g_hr[2 * w + 1] = s3 + b2r[1];
    }
}

__global__ void edge_score2(const int* __restrict__ src, const int* __restrict__ dst,
                            const float* __restrict__ att2) {
    int e = blockIdx.x * blockDim.x + threadIdx.x;
    if (e >= E_TOT) return;
    int s, d;
    if (e < N_EDGES) { s = src[e]; d = dst[e]; }
    else             { s = e - N_EDGES; d = s; }
    float2 hl = *(const float2*)(g_hl + 2 * s);
    float2 hr = *(const float2*)(g_hr + 2 * d);
    float sc = lrelu(hl.x + hr.x) * att2[0] + lrelu(hl.y + hr.y) * att2[1];
    g_score[e] = sc;
    atomicMaxF(&g_m[d], sc);
}

__global__ void edge_agg2(const int* __restrict__ src, const int* __restrict__ dst,
                          float* __restrict__ out) {
    int e = blockIdx.x * blockDim.x + threadIdx.x;
    if (e >= E_TOT) return;
    int s, d;
    if (e < N_EDGES) { s = src[e]; d = dst[e]; }
    else             { s = e - N_EDGES; d = s; }
    float alpha = __fdividef(g_score[e], g_denom[d]);
    float2 hl = *(const float2*)(g_hl + 2 * s);
    atomicAdd(&out[2 * d + 0], alpha * hl.x);
    atomicAdd(&out[2 * d + 1], alpha * hl.y);
}

// ---------------- launch ----------------
extern "C" void kernel_launch(void* const* d_in, const int* in_sizes, int n_in,
                              void* d_out, int out_size) {
    const float* x    = (const float*)d_in[0];
    const int*   src  = (const int*)  d_in[1];
    const int*   dst  = (const int*)  d_in[2];
    const float* W1l  = (const float*)d_in[3];
    const float* b1l  = (const float*)d_in[4];
    const float* W1r  = (const float*)d_in[5];
    const float* b1r  = (const float*)d_in[6];
    const float* att1 = (const float*)d_in[7];
    const float* bias1= (const float*)d_in[8];
    const float* W2l  = (const float*)d_in[9];
    const float* b2l  = (const float*)d_in[10];
    const float* W2r  = (const float*)d_in[11];
    const float* b2r  = (const float*)d_in[12];
    const float* att2 = (const float*)d_in[13];
    const float* bias2= (const float*)d_in[14];
    float* out = (float*)d_out;

    const int gemmBlocks = (N_NODES + 127) / 128;             // 782
    const int nhBlocks   = (N_NODES * HIDDEN + 255) / 256;    // 50000
    const int edgeGrpBlocks    = (E_TOT * 8 + 255) / 256;     // 53125
    const int edgeThreadBlocks = (E_TOT + 255) / 256;         // 6641
    const int nodeBlocks = (N_NODES + 255) / 256;             // 391
    const int nodeWarpBlocks = (N_NODES * 32 + 255) / 256;    // 12500

    // layer 1
    gemm1<0><<<gemmBlocks, 256>>>(x, W1l, b1l);
    gemm1<1><<<gemmBlocks, 256>>>(x, W1r, b1r);
    init_l1<<<nhBlocks, 256>>>();
    edge_score1<<<edgeGrpBlocks, 256>>>(src, dst, att1);
    edge_exp<<<edgeThreadBlocks, 256>>>(dst);
    edge_agg1<<<edgeGrpBlocks, 256>>>(src, dst);
    relu_bias<<<nhBlocks, 256>>>(bias1);

    // layer 2
    lin2<<<nodeWarpBlocks, 256>>>(W2l, b2l, W2r, b2r);
    init_l2<<<nodeBlocks, 256>>>(bias2, out);
    edge_score2<<<edgeThreadBlocks, 256>>>(src, dst, att2);
    edge_exp<<<edgeThreadBlocks, 256>>>(dst);
    edge_agg2<<<edgeThreadBlocks, 256>>>(src, dst, out);
}

// round 5
// speedup vs baseline: 1.2351x; 1.0146x over previous
#include <cuda_runtime.h>
#include <cstdint>

#define N_NODES 100000
#define N_EDGES 1600000
#define E_TOT   (N_EDGES + N_NODES)   // + self loops
#define N_FEAT  165
#define HIDDEN  128
#define NEG_SLOPE 0.2f

// ---------------- scratch (static __device__ arrays; no allocation) -------
__device__ float g_xl[(size_t)N_NODES * HIDDEN];
__device__ float g_xr[(size_t)N_NODES * HIDDEN];
__device__ float g_h [(size_t)N_NODES * HIDDEN];
__device__ float g_score[E_TOT];
__device__ float g_denom[N_NODES];
__device__ float g_hl[N_NODES * 2];
__device__ float g_hr[N_NODES * 2];

// ---------------- helpers ----------------
__device__ __forceinline__ float warpSum(float v) {
    #pragma unroll
    for (int o = 16; o > 0; o >>= 1) v += __shfl_xor_sync(0xffffffffu, v, o);
    return v;
}

__device__ __forceinline__ void redAdd4(float* p, float a, float b, float c, float d) {
    asm volatile("red.global.add.v4.f32 [%0], {%1,%2,%3,%4};"
                 :: "l"(p), "f"(a), "f"(b), "f"(c), "f"(d) : "memory");
}

__device__ __forceinline__ float lrelu(float v) {
    return v > 0.f ? v : NEG_SLOPE * v;
}

// ---------------- fused GEMM: [Yl|Yr] = X[100k x 165] @ [W1l|W1r] + b ------
// 128 x 256 output tile per block, 512 threads, 8x8 microtile per thread.
// Shared = 128*32 + 32*256 floats = 49152 bytes (static 48KB limit).
__global__ void __launch_bounds__(512) gemm_fused(const float* __restrict__ X,
                                                  const float* __restrict__ W1l,
                                                  const float* __restrict__ b1l,
                                                  const float* __restrict__ W1r,
                                                  const float* __restrict__ b1r) {
    __shared__ float Xs[128][32];   // [m][k]
    __shared__ float Ws[32][256];   // [k][n]  n<128 -> W1l, n>=128 -> W1r

    const int tid = threadIdx.x;
    const int tx = tid & 31;        // 32 col-groups * 8 = 256 cols
    const int ty = tid >> 5;        // 16 row-groups * 8 = 128 rows
    const int row0 = blockIdx.x * 128;

    float acc[8][8];
    #pragma unroll
    for (int i = 0; i < 8; i++)
        #pragma unroll
        for (int j = 0; j < 8; j++) acc[i][j] = 0.f;

    for (int k0 = 0; k0 < N_FEAT; k0 += 32) {
        // X tile: 128 m x 32 k  (8 iters * 512 threads = 4096 elements)
        #pragma unroll
        for (int i = 0; i < 8; i++) {
            int lin = tid + i * 512;
            int m = lin >> 5, k = lin & 31;
            int gr = row0 + m, gk = k0 + k;
            float v = 0.f;
            if (gr < N_NODES && gk < N_FEAT) v = X[(size_t)gr * N_FEAT + gk];
            Xs[m][k] = v;
        }
        // W tiles: 32 k x 256 n  (16 iters * 512 = 8192 elements)
        #pragma unroll
        for (int i = 0; i < 16; i++) {
            int lin = tid + i * 512;
            int k = lin >> 8, n = lin & 255;
            int gk = k0 + k;
            float v = 0.f;
            if (gk < N_FEAT)
                v = (n < 128) ? W1l[gk * HIDDEN + n] : W1r[gk * HIDDEN + (n - 128)];
            Ws[k][n] = v;
        }
        __syncthreads();

        #pragma unroll
        for (int k = 0; k < 32; k++) {
            float a[8];
            #pragma unroll
            for (int i = 0; i < 8; i++) a[i] = Xs[ty * 8 + i][k];  // warp-broadcast
            float4 b0 = *(const float4*)&Ws[k][tx * 8];
            float4 b1 = *(const float4*)&Ws[k][tx * 8 + 4];
            float b[8] = {b0.x, b0.y, b0.z, b0.w, b1.x, b1.y, b1.z, b1.w};
            #pragma unroll
            for (int i = 0; i < 8; i++)
                #pragma unroll
                for (int j = 0; j < 8; j++) acc[i][j] += a[i] * b[j];
        }
        __syncthreads();
    }

    #pragma unroll
    for (int i = 0; i < 8; i++) {
        int r = row0 + ty * 8 + i;
        if (r < N_NODES) {
            #pragma unroll
            for (int j = 0; j < 8; j++) {
                int c = tx * 8 + j;
                if (c < 128) g_xl[(size_t)r * HIDDEN + c] = acc[i][j] + b1l[c];
                else         g_xr[(size_t)r * HIDDEN + (c - 128)] = acc[i][j] + b1r[c - 128];
            }
        }
    }
}

// ---------------- init kernels ----------------
__global__ void init_l1() {
    int i = blockIdx.x * blockDim.x + threadIdx.x;
    if (i < N_NODES * HIDDEN) g_h[i] = 0.f;
    if (i < N_NODES) g_denom[i] = 0.f;
}

__global__ void init_l2(const float* __restrict__ bias2, float* __restrict__ out) {
    int i = blockIdx.x * blockDim.x + threadIdx.x;
    if (i < N_NODES) {
        g_denom[i] = 0.f;
        out[2 * i + 0] = bias2[0];
        out[2 * i + 1] = bias2[1];
    }
}

// ---------------- layer 1 edge kernels: 8 lanes per edge, 4 edges per warp -
// Scores are O(1) in magnitude (see analysis) -> exp without max-subtraction
// is exact up to fp32 rounding; alpha = exp(s)/sum exp(s) is identical math.
__global__ void edge_score1(const int* __restrict__ src, const int* __restrict__ dst,
                            const float* __restrict__ att) {
    int gwarp = (blockIdx.x * blockDim.x + threadIdx.x) >> 5;
    int lane = threadIdx.x & 31;
    int grp = lane >> 3;   // 0..3
    int gl  = lane & 7;    // lane within group
    int e = gwarp * 4 + grp;
    if (e >= E_TOT) return;

    int s, d;
    if (e < N_EDGES) { s = src[e]; d = dst[e]; }
    else             { s = e - N_EDGES; d = s; }

    const float4* pa = (const float4*)(g_xl + (size_t)s * HIDDEN);
    const float4* pb = (const float4*)(g_xr + (size_t)d * HIDDEN);
    const float4* pt = (const float4*)att;

    float p = 0.f;
    #pragma unroll
    for (int c = 0; c < 4; c++) {
        int idx = gl + c * 8;
        float4 a = pa[idx];
        float4 b = pb[idx];
        float4 t = __ldg(&pt[idx]);
        p += lrelu(a.x + b.x) * t.x + lrelu(a.y + b.y) * t.y;
        p += lrelu(a.z + b.z) * t.z + lrelu(a.w + b.w) * t.w;
    }

    p += __shfl_xor_sync(0xffffffffu, p, 1);
    p += __shfl_xor_sync(0xffffffffu, p, 2);
    p += __shfl_xor_sync(0xffffffffu, p, 4);

    if (gl == 0) {
        float a = __expf(p);
        g_score[e] = a;
        atomicAdd(&g_denom[d], a);
    }
}

__global__ void edge_agg1(const int* __restrict__ src, const int* __restrict__ dst) {
    int gwarp = (blockIdx.x * blockDim.x + threadIdx.x) >> 5;
    int lane = threadIdx.x & 31;
    int grp = lane >> 3;
    int gl  = lane & 7;
    int e = gwarp * 4 + grp;
    if (e >= E_TOT) return;

    int s, d;
    if (e < N_EDGES) { s = src[e]; d = dst[e]; }
    else             { s = e - N_EDGES; d = s; }

    float alpha = __fdividef(g_score[e], g_denom[d]);

    const float4* pa = (const float4*)(g_xl + (size_t)s * HIDDEN);
    float* po = g_h + (size_t)d * HIDDEN;

    #pragma unroll
    for (int c = 0; c < 4; c++) {
        int idx = gl + c * 8;
        float4 a = pa[idx];
        redAdd4(po + idx * 4, alpha * a.x, alpha * a.y, alpha * a.z, alpha * a.w);
    }
}

__global__ void relu_bias(const float* __restrict__ bias1) {
    int i = blockIdx.x * blockDim.x + threadIdx.x;
    if (i < N_NODES * HIDDEN) {
        float v = g_h[i] + bias1[i & 127];
        g_h[i] = v > 0.f ? v : 0.f;
    }
}

// ---------------- layer 2 ----------------
__global__ void lin2(const float* __restrict__ W2l, const float* __restrict__ b2l,
                     const float* __restrict__ W2r, const float* __restrict__ b2r) {
    int w = (blockIdx.x * blockDim.x + threadIdx.x) >> 5;
    int lane = threadIdx.x & 31;
    if (w >= N_NODES) return;

    float4 h = ((const float4*)(g_h + (size_t)w * HIDDEN))[lane];
    int k = lane * 4;
    float s0 = h.x * W2l[(k + 0) * 2 + 0] + h.y * W2l[(k + 1) * 2 + 0]
             + h.z * W2l[(k + 2) * 2 + 0] + h.w * W2l[(k + 3) * 2 + 0];
    float s1 = h.x * W2l[(k + 0) * 2 + 1] + h.y * W2l[(k + 1) * 2 + 1]
             + h.z * W2l[(k + 2) * 2 + 1] + h.w * W2l[(k + 3) * 2 + 1];
    float s2 = h.x * W2r[(k + 0) * 2 + 0] + h.y * W2r[(k + 1) * 2 + 0]
             + h.z * W2r[(k + 2) * 2 + 0] + h.w * W2r[(k + 3) * 2 + 0];
    float s3 = h.x * W2r[(k + 0) * 2 + 1] + h.y * W2r[(k + 1) * 2 + 1]
             + h.z * W2r[(k + 2) * 2 + 1] + h.w * W2r[(k + 3) * 2 + 1];
    s0 = warpSum(s0); s1 = warpSum(s1); s2 = warpSum(s2); s3 = warpSum(s3);
    if (lane == 0) {
        g_hl[2 * w + 0] = s0 + b2l[0];
        g_hl[2 * w + 1] = s1 + b2l[1];
        g_hr[2 * w + 0] = s2 + b2r[0];
        g_hr[2 * w + 1] = s3 + b2r[1];
    }
}

__global__ void edge_score2(const int* __restrict__ src, const int* __restrict__ dst,
                            const float* __restrict__ att2) {
    int e = blockIdx.x * blockDim.x + threadIdx.x;
    if (e >= E_TOT) return;
    int s, d;
    if (e < N_EDGES) { s = src[e]; d = dst[e]; }
    else             { s = e - N_EDGES; d = s; }
    float2 hl = *(const float2*)(g_hl + 2 * s);
    float2 hr = *(const float2*)(g_hr + 2 * d);
    float sc = lrelu(hl.x + hr.x) * att2[0] + lrelu(hl.y + hr.y) * att2[1];
    float a = __expf(sc);
    g_score[e] = a;
    atomicAdd(&g_denom[d], a);
}

__global__ void edge_agg2(const int* __restrict__ src, const int* __restrict__ dst,
                          float* __restrict__ out) {
    int e = blockIdx.x * blockDim.x + threadIdx.x;
    if (e >= E_TOT) return;
    int s, d;
    if (e < N_EDGES) { s = src[e]; d = dst[e]; }
    else             { s = e - N_EDGES; d = s; }
    float alpha = __fdividef(g_score[e], g_denom[d]);
    float2 hl = *(const float2*)(g_hl + 2 * s);
    atomicAdd(&out[2 * d + 0], alpha * hl.x);
    atomicAdd(&out[2 * d + 1], alpha * hl.y);
}

// ---------------- launch ----------------
extern "C" void kernel_launch(void* const* d_in, const int* in_sizes, int n_in,
                              void* d_out, int out_size) {
    const float* x    = (const float*)d_in[0];
    const int*   src  = (const int*)  d_in[1];
    const int*   dst  = (const int*)  d_in[2];
    const float* W1l  = (const float*)d_in[3];
    const float* b1l  = (const float*)d_in[4];
    const float* W1r  = (const float*)d_in[5];
    const float* b1r  = (const float*)d_in[6];
    const float* att1 = (const float*)d_in[7];
    const float* bias1= (const float*)d_in[8];
    const float* W2l  = (const float*)d_in[9];
    const float* b2l  = (const float*)d_in[10];
    const float* W2r  = (const float*)d_in[11];
    const float* b2r  = (const float*)d_in[12];
    const float* att2 = (const float*)d_in[13];
    const float* bias2= (const float*)d_in[14];
    float* out = (float*)d_out;

    const int gemmBlocks = (N_NODES + 127) / 128;             // 782
    const int nhBlocks   = (N_NODES * HIDDEN + 255) / 256;    // 50000
    const int edgeGrpBlocks    = (E_TOT * 8 + 255) / 256;     // 53125
    const int edgeThreadBlocks = (E_TOT + 255) / 256;         // 6641
    const int nodeBlocks = (N_NODES + 255) / 256;             // 391
    const int nodeWarpBlocks = (N_NODES * 32 + 255) / 256;    // 12500

    // layer 1
    gemm_fused<<<gemmBlocks, 512>>>(x, W1l, b1l, W1r, b1r);
    init_l1<<<nhBlocks, 256>>>();
    edge_score1<<<edgeGrpBlocks, 256>>>(src, dst, att1);
    edge_agg1<<<edgeGrpBlocks, 256>>>(src, dst);
    relu_bias<<<nhBlocks, 256>>>(bias1);

    // layer 2
    lin2<<<nodeWarpBlocks, 256>>>(W2l, b2l, W2r, b2r);
    init_l2<<<nodeBlocks, 256>>>(bias2, out);
    edge_score2<<<edgeThreadBlocks, 256>>>(src, dst, att2);
    edge_agg2<<<edgeThreadBlocks, 256>>>(src, dst, out);
}

// round 6
// speedup vs baseline: 1.3217x; 1.0701x over previous
#include <cuda_runtime.h>
#include <cstdint>

#define N_NODES 100000
#define N_EDGES 1600000
#define E_TOT   (N_EDGES + N_NODES)   // + self loops
#define N_FEAT  165
#define HIDDEN  128
#define NEG_SLOPE 0.2f

// ---------------- scratch (static __device__ arrays; no allocation) -------
__device__ float g_xl[(size_t)N_NODES * HIDDEN];
__device__ float g_xr[(size_t)N_NODES * HIDDEN];
__device__ float g_h [(size_t)N_NODES * HIDDEN];   // layer-1 numerator
__device__ float g_denom[N_NODES];
__device__ float g_hl[N_NODES * 2];
__device__ float g_hr[N_NODES * 2];
__device__ float g_num2[N_NODES * 2];              // layer-2 numerator

// ---------------- helpers ----------------
__device__ __forceinline__ float warpSum(float v) {
    #pragma unroll
    for (int o = 16; o > 0; o >>= 1) v += __shfl_xor_sync(0xffffffffu, v, o);
    return v;
}

__device__ __forceinline__ void redAdd4(float* p, float a, float b, float c, float d) {
    asm volatile("red.global.add.v4.f32 [%0], {%1,%2,%3,%4};"
                 :: "l"(p), "f"(a), "f"(b), "f"(c), "f"(d) : "memory");
}

__device__ __forceinline__ void redAdd2(float* p, float a, float b) {
    asm volatile("red.global.add.v2.f32 [%0], {%1,%2};"
                 :: "l"(p), "f"(a), "f"(b) : "memory");
}

__device__ __forceinline__ float lrelu(float v) {
    return v > 0.f ? v : NEG_SLOPE * v;
}

// ---------------- fused GEMM: [Yl|Yr] = X[100k x 165] @ [W1l|W1r] + b ------
__global__ void __launch_bounds__(512) gemm_fused(const float* __restrict__ X,
                                                  const float* __restrict__ W1l,
                                                  const float* __restrict__ b1l,
                                                  const float* __restrict__ W1r,
                                                  const float* __restrict__ b1r) {
    __shared__ float Xs[128][32];   // [m][k]
    __shared__ float Ws[32][256];   // [k][n]

    const int tid = threadIdx.x;
    const int tx = tid & 31;
    const int ty = tid >> 5;
    const int row0 = blockIdx.x * 128;

    float acc[8][8];
    #pragma unroll
    for (int i = 0; i < 8; i++)
        #pragma unroll
        for (int j = 0; j < 8; j++) acc[i][j] = 0.f;

    for (int k0 = 0; k0 < N_FEAT; k0 += 32) {
        #pragma unroll
        for (int i = 0; i < 8; i++) {
            int lin = tid + i * 512;
            int m = lin >> 5, k = lin & 31;
            int gr = row0 + m, gk = k0 + k;
            float v = 0.f;
            if (gr < N_NODES && gk < N_FEAT) v = X[(size_t)gr * N_FEAT + gk];
            Xs[m][k] = v;
        }
        #pragma unroll
        for (int i = 0; i < 16; i++) {
            int lin = tid + i * 512;
            int k = lin >> 8, n = lin & 255;
            int gk = k0 + k;
            float v = 0.f;
            if (gk < N_FEAT)
                v = (n < 128) ? W1l[gk * HIDDEN + n] : W1r[gk * HIDDEN + (n - 128)];
            Ws[k][n] = v;
        }
        __syncthreads();

        #pragma unroll
        for (int k = 0; k < 32; k++) {
            float a[8];
            #pragma unroll
            for (int i = 0; i < 8; i++) a[i] = Xs[ty * 8 + i][k];
            float4 b0 = *(const float4*)&Ws[k][tx * 8];
            float4 b1 = *(const float4*)&Ws[k][tx * 8 + 4];
            float b[8] = {b0.x, b0.y, b0.z, b0.w, b1.x, b1.y, b1.z, b1.w};
            #pragma unroll
            for (int i = 0; i < 8; i++)
                #pragma unroll
                for (int j = 0; j < 8; j++) acc[i][j] += a[i] * b[j];
        }
        __syncthreads();
    }

    #pragma unroll
    for (int i = 0; i < 8; i++) {
        int r = row0 + ty * 8 + i;
        if (r < N_NODES) {
            #pragma unroll
            for (int j = 0; j < 8; j++) {
                int c = tx * 8 + j;
                if (c < 128) g_xl[(size_t)r * HIDDEN + c] = acc[i][j] + b1l[c];
                else         g_xr[(size_t)r * HIDDEN + (c - 128)] = acc[i][j] + b1r[c - 128];
            }
        }
    }
}

// ---------------- init kernels ----------------
__global__ void init_l1() {
    int i = blockIdx.x * blockDim.x + threadIdx.x;
    if (i < N_NODES * HIDDEN) g_h[i] = 0.f;
    if (i < N_NODES) g_denom[i] = 0.f;
}

__global__ void init_l2() {
    int i = blockIdx.x * blockDim.x + threadIdx.x;
    if (i < N_NODES) {
        g_denom[i] = 0.f;
        g_num2[2 * i + 0] = 0.f;
        g_num2[2 * i + 1] = 0.f;
    }
}

// ---------------- layer 1: single fused edge pass ----------------
// 8 lanes/edge, 4 edges/warp. Computes w=exp(score) and immediately
// accumulates w*xl[src] into g_h[dst] and w into g_denom[dst].
__global__ void edge_fused1(const int* __restrict__ src, const int* __restrict__ dst,
                            const float* __restrict__ att) {
    int gwarp = (blockIdx.x * blockDim.x + threadIdx.x) >> 5;
    int lane = threadIdx.x & 31;
    int gl  = lane & 7;
    int e = gwarp * 4 + (lane >> 3);
    if (e >= E_TOT) return;

    int s, d;
    if (e < N_EDGES) { s = src[e]; d = dst[e]; }
    else             { s = e - N_EDGES; d = s; }

    const float4* pa = (const float4*)(g_xl + (size_t)s * HIDDEN);
    const float4* pb = (const float4*)(g_xr + (size_t)d * HIDDEN);
    const float4* pt = (const float4*)att;

    float4 a[4];
    float p = 0.f;
    #pragma unroll
    for (int c = 0; c < 4; c++) {
        int idx = gl + c * 8;
        a[c] = pa[idx];
        float4 b = pb[idx];
        float4 t = __ldg(&pt[idx]);
        p += lrelu(a[c].x + b.x) * t.x + lrelu(a[c].y + b.y) * t.y;
        p += lrelu(a[c].z + b.z) * t.z + lrelu(a[c].w + b.w) * t.w;
    }

    // butterfly: ALL 8 lanes of the group end with the full sum
    p += __shfl_xor_sync(0xffffffffu, p, 1);
    p += __shfl_xor_sync(0xffffffffu, p, 2);
    p += __shfl_xor_sync(0xffffffffu, p, 4);

    float w = __expf(p);
    if (gl == 0) atomicAdd(&g_denom[d], w);

    float* po = g_h + (size_t)d * HIDDEN;
    #pragma unroll
    for (int c = 0; c < 4; c++) {
        int idx = gl + c * 8;
        redAdd4(po + idx * 4, w * a[c].x, w * a[c].y, w * a[c].z, w * a[c].w);
    }
}

// finalize layer 1: h = relu(num/denom + bias1)
__global__ void finalize1(const float* __restrict__ bias1) {
    int i = blockIdx.x * blockDim.x + threadIdx.x;
    if (i < N_NODES * HIDDEN) {
        float v = __fdividef(g_h[i], g_denom[i >> 7]) + bias1[i & 127];
        g_h[i] = v > 0.f ? v : 0.f;
    }
}

// ---------------- layer 2 ----------------
__global__ void lin2(const float* __restrict__ W2l, const float* __restrict__ b2l,
                     const float* __restrict__ W2r, const float* __restrict__ b2r) {
    int w = (blockIdx.x * blockDim.x + threadIdx.x) >> 5;
    int lane = threadIdx.x & 31;
    if (w >= N_NODES) return;

    float4 h = ((const float4*)(g_h + (size_t)w * HIDDEN))[lane];
    int k = lane * 4;
    float s0 = h.x * W2l[(k + 0) * 2 + 0] + h.y * W2l[(k + 1) * 2 + 0]
             + h.z * W2l[(k + 2) * 2 + 0] + h.w * W2l[(k + 3) * 2 + 0];
    float s1 = h.x * W2l[(k + 0) * 2 + 1] + h.y * W2l[(k + 1) * 2 + 1]
             + h.z * W2l[(k + 2) * 2 + 1] + h.w * W2l[(k + 3) * 2 + 1];
    float s2 = h.x * W2r[(k + 0) * 2 + 0] + h.y * W2r[(k + 1) * 2 + 0]
             + h.z * W2r[(k + 2) * 2 + 0] + h.w * W2r[(k + 3) * 2 + 0];
    float s3 = h.x * W2r[(k + 0) * 2 + 1] + h.y * W2r[(k + 1) * 2 + 1]
             + h.z * W2r[(k + 2) * 2 + 1] + h.w * W2r[(k + 3) * 2 + 1];
    s0 = warpSum(s0); s1 = warpSum(s1); s2 = warpSum(s2); s3 = warpSum(s3);
    if (lane == 0) {
        g_hl[2 * w + 0] = s0 + b2l[0];
        g_hl[2 * w + 1] = s1 + b2l[1];
        g_hr[2 * w + 0] = s2 + b2r[0];
        g_hr[2 * w + 1] = s3 + b2r[1];
    }
}

// fused layer-2 edge pass: accumulate numerator + denominator directly
__global__ void edge_fused2(const int* __restrict__ src, const int* __restrict__ dst,
                            const float* __restrict__ att2) {
    int e = blockIdx.x * blockDim.x + threadIdx.x;
    if (e >= E_TOT) return;
    int s, d;
    if (e < N_EDGES) { s = src[e]; d = dst[e]; }
    else             { s = e - N_EDGES; d = s; }
    float2 hl = *(const float2*)(g_hl + 2 * s);
    float2 hr = *(const float2*)(g_hr + 2 * d);
    float sc = lrelu(hl.x + hr.x) * att2[0] + lrelu(hl.y + hr.y) * att2[1];
    float w = __expf(sc);
    atomicAdd(&g_denom[d], w);
    redAdd2(g_num2 + 2 * d, w * hl.x, w * hl.y);
}

// finalize layer 2: out = num/denom + bias2
__global__ void finalize2(const float* __restrict__ bias2, float* __restrict__ out) {
    int i = blockIdx.x * blockDim.x + threadIdx.x;
    if (i < N_NODES) {
        float inv = __fdividef(1.f, g_denom[i]);
        out[2 * i + 0] = g_num2[2 * i + 0] * inv + bias2[0];
        out[2 * i + 1] = g_num2[2 * i + 1] * inv + bias2[1];
    }
}

// ---------------- launch ----------------
extern "C" void kernel_launch(void* const* d_in, const int* in_sizes, int n_in,
                              void* d_out, int out_size) {
    const float* x    = (const float*)d_in[0];
    const int*   src  = (const int*)  d_in[1];
    const int*   dst  = (const int*)  d_in[2];
    const float* W1l  = (const float*)d_in[3];
    const float* b1l  = (const float*)d_in[4];
    const float* W1r  = (const float*)d_in[5];
    const float* b1r  = (const float*)d_in[6];
    const float* att1 = (const float*)d_in[7];
    const float* bias1= (const float*)d_in[8];
    const float* W2l  = (const float*)d_in[9];
    const float* b2l  = (const float*)d_in[10];
    const float* W2r  = (const float*)d_in[11];
    const float* b2r  = (const float*)d_in[12];
    const float* att2 = (const float*)d_in[13];
    const float* bias2= (const float*)d_in[14];
    float* out = (float*)d_out;

    const int gemmBlocks = (N_NODES + 127) / 128;             // 782
    const int nhBlocks   = (N_NODES * HIDDEN + 255) / 256;    // 50000
    const int edgeGrpBlocks    = (E_TOT * 8 + 255) / 256;     // 53125
    const int edgeThreadBlocks = (E_TOT + 255) / 256;         // 6641
    const int nodeBlocks = (N_NODES + 255) / 256;             // 391
    const int nodeWarpBlocks = (N_NODES * 32 + 255) / 256;    // 12500

    // layer 1
    gemm_fused<<<gemmBlocks, 512>>>(x, W1l, b1l, W1r, b1r);
    init_l1<<<nhBlocks, 256>>>();
    edge_fused1<<<edgeGrpBlocks, 256>>>(src, dst, att1);
    finalize1<<<nhBlocks, 256>>>(bias1);

    // layer 2
    lin2<<<nodeWarpBlocks, 256>>>(W2l, b2l, W2r, b2r);
    init_l2<<<nodeBlocks, 256>>>();
    edge_fused2<<<edgeThreadBlocks, 256>>>(src, dst, att2);
    finalize2<<<nodeBlocks, 256>>>(bias2, out);
}

// round 7
// speedup vs baseline: 1.3820x; 1.0456x over previous
#include <cuda_runtime.h>
#include <cstdint>

#define N_NODES 100000
#define N_EDGES 1600000
#define E_TOT   (N_EDGES + N_NODES)   // + self loops
#define N_FEAT  165
#define HIDDEN  128
#define NEG_SLOPE 0.2f

// ---------------- scratch (static __device__ arrays; no allocation) -------
__device__ float g_xl[(size_t)N_NODES * HIDDEN];
__device__ float g_xr[(size_t)N_NODES * HIDDEN];
__device__ float g_h [(size_t)N_NODES * HIDDEN];   // layer-1 numerator
__device__ float g_denom[N_NODES];
__device__ float g_hl[N_NODES * 2];
__device__ float g_hr[N_NODES * 2];
__device__ float g_num2[N_NODES * 2];              // layer-2 numerator

// ---------------- helpers ----------------
__device__ __forceinline__ float warpSum(float v) {
    #pragma unroll
    for (int o = 16; o > 0; o >>= 1) v += __shfl_xor_sync(0xffffffffu, v, o);
    return v;
}

__device__ __forceinline__ void redAdd4(float* p, float a, float b, float c, float d) {
    asm volatile("red.global.add.v4.f32 [%0], {%1,%2,%3,%4};"
                 :: "l"(p), "f"(a), "f"(b), "f"(c), "f"(d) : "memory");
}

__device__ __forceinline__ void redAdd2(float* p, float a, float b) {
    asm volatile("red.global.add.v2.f32 [%0], {%1,%2};"
                 :: "l"(p), "f"(a), "f"(b) : "memory");
}

__device__ __forceinline__ float lrelu(float v) {
    return v > 0.f ? v : NEG_SLOPE * v;
}

// ---------------- fused GEMM + scratch zeroing ------------------------------
// [Yl|Yr] = X[100k x 165] @ [W1l|W1r] + b.  Also zeroes g_h rows + g_denom
// for this block's 128 rows (consumed by the edge pass that runs next).
__global__ void __launch_bounds__(512) gemm_fused(const float* __restrict__ X,
                                                  const float* __restrict__ W1l,
                                                  const float* __restrict__ b1l,
                                                  const float* __restrict__ W1r,
                                                  const float* __restrict__ b1r) {
    __shared__ float Xs[128][32];   // [m][k]
    __shared__ float Ws[32][256];   // [k][n]

    const int tid = threadIdx.x;
    const int tx = tid & 31;
    const int ty = tid >> 5;
    const int row0 = blockIdx.x * 128;

    // zero this block's slice of g_h (128 rows x 32 float4) and g_denom
    {
        const float4 z4 = make_float4(0.f, 0.f, 0.f, 0.f);
        #pragma unroll
        for (int i = tid; i < 128 * 32; i += 512) {
            int r = row0 + (i >> 5);
            if (r < N_NODES) ((float4*)g_h)[(size_t)r * 32 + (i & 31)] = z4;
        }
        if (tid < 128) {
            int r = row0 + tid;
            if (r < N_NODES) g_denom[r] = 0.f;
        }
    }

    float acc[8][8];
    #pragma unroll
    for (int i = 0; i < 8; i++)
        #pragma unroll
        for (int j = 0; j < 8; j++) acc[i][j] = 0.f;

    for (int k0 = 0; k0 < N_FEAT; k0 += 32) {
        #pragma unroll
        for (int i = 0; i < 8; i++) {
            int lin = tid + i * 512;
            int m = lin >> 5, k = lin & 31;
            int gr = row0 + m, gk = k0 + k;
            float v = 0.f;
            if (gr < N_NODES && gk < N_FEAT) v = X[(size_t)gr * N_FEAT + gk];
            Xs[m][k] = v;
        }
        #pragma unroll
        for (int i = 0; i < 16; i++) {
            int lin = tid + i * 512;
            int k = lin >> 8, n = lin & 255;
            int gk = k0 + k;
            float v = 0.f;
            if (gk < N_FEAT)
                v = (n < 128) ? W1l[gk * HIDDEN + n] : W1r[gk * HIDDEN + (n - 128)];
            Ws[k][n] = v;
        }
        __syncthreads();

        #pragma unroll
        for (int k = 0; k < 32; k++) {
            float a[8];
            #pragma unroll
            for (int i = 0; i < 8; i++) a[i] = Xs[ty * 8 + i][k];
            float4 b0 = *(const float4*)&Ws[k][tx * 8];
            float4 b1 = *(const float4*)&Ws[k][tx * 8 + 4];
            float b[8] = {b0.x, b0.y, b0.z, b0.w, b1.x, b1.y, b1.z, b1.w};
            #pragma unroll
            for (int i = 0; i < 8; i++)
                #pragma unroll
                for (int j = 0; j < 8; j++) acc[i][j] += a[i] * b[j];
        }
        __syncthreads();
    }

    #pragma unroll
    for (int i = 0; i < 8; i++) {
        int r = row0 + ty * 8 + i;
        if (r < N_NODES) {
            #pragma unroll
            for (int j = 0; j < 8; j++) {
                int c = tx * 8 + j;
                if (c < 128) g_xl[(size_t)r * HIDDEN + c] = acc[i][j] + b1l[c];
                else         g_xr[(size_t)r * HIDDEN + (c - 128)] = acc[i][j] + b1r[c - 128];
            }
        }
    }
}

// ---------------- layer 1: single fused edge pass ----------------
__global__ void edge_fused1(const int* __restrict__ src, const int* __restrict__ dst,
                            const float* __restrict__ att) {
    int gwarp = (blockIdx.x * blockDim.x + threadIdx.x) >> 5;
    int lane = threadIdx.x & 31;
    int gl  = lane & 7;
    int e = gwarp * 4 + (lane >> 3);
    if (e >= E_TOT) return;

    int s, d;
    if (e < N_EDGES) { s = src[e]; d = dst[e]; }
    else             { s = e - N_EDGES; d = s; }

    const float4* pa = (const float4*)(g_xl + (size_t)s * HIDDEN);
    const float4* pb = (const float4*)(g_xr + (size_t)d * HIDDEN);
    const float4* pt = (const float4*)att;

    float4 a[4];
    float p = 0.f;
    #pragma unroll
    for (int c = 0; c < 4; c++) {
        int idx = gl + c * 8;
        a[c] = pa[idx];
        float4 b = pb[idx];
        float4 t = __ldg(&pt[idx]);
        p += lrelu(a[c].x + b.x) * t.x + lrelu(a[c].y + b.y) * t.y;
        p += lrelu(a[c].z + b.z) * t.z + lrelu(a[c].w + b.w) * t.w;
    }

    p += __shfl_xor_sync(0xffffffffu, p, 1);
    p += __shfl_xor_sync(0xffffffffu, p, 2);
    p += __shfl_xor_sync(0xffffffffu, p, 4);

    float w = __expf(p);
    if (gl == 0) atomicAdd(&g_denom[d], w);

    float* po = g_h + (size_t)d * HIDDEN;
    #pragma unroll
    for (int c = 0; c < 4; c++) {
        int idx = gl + c * 8;
        redAdd4(po + idx * 4, w * a[c].x, w * a[c].y, w * a[c].z, w * a[c].w);
    }
}

// ---------------- layer 2 linear (fused with layer-1 finalize + layer-2 init)
// h = relu(g_h/denom + bias1) computed at load; also zeroes denom/num2 for
// the layer-2 edge pass.
__global__ void lin2(const float* __restrict__ bias1,
                     const float* __restrict__ W2l, const float* __restrict__ b2l,
                     const float* __restrict__ W2r, const float* __restrict__ b2r) {
    int w = (blockIdx.x * blockDim.x + threadIdx.x) >> 5;
    int lane = threadIdx.x & 31;
    if (w >= N_NODES) return;

    float inv = __fdividef(1.f, g_denom[w]);   // broadcast load
    float4 n4 = ((const float4*)(g_h + (size_t)w * HIDDEN))[lane];
    float4 b4 = __ldg(&((const float4*)bias1)[lane]);

    float h0 = n4.x * inv + b4.x;  h0 = h0 > 0.f ? h0 : 0.f;
    float h1 = n4.y * inv + b4.y;  h1 = h1 > 0.f ? h1 : 0.f;
    float h2 = n4.z * inv + b4.z;  h2 = h2 > 0.f ? h2 : 0.f;
    float h3 = n4.w * inv + b4.w;  h3 = h3 > 0.f ? h3 : 0.f;

    int k = lane * 4;
    float s0 = h0 * W2l[(k + 0) * 2 + 0] + h1 * W2l[(k + 1) * 2 + 0]
             + h2 * W2l[(k + 2) * 2 + 0] + h3 * W2l[(k + 3) * 2 + 0];
    float s1 = h0 * W2l[(k + 0) * 2 + 1] + h1 * W2l[(k + 1) * 2 + 1]
             + h2 * W2l[(k + 2) * 2 + 1] + h3 * W2l[(k + 3) * 2 + 1];
    float s2 = h0 * W2r[(k + 0) * 2 + 0] + h1 * W2r[(k + 1) * 2 + 0]
             + h2 * W2r[(k + 2) * 2 + 0] + h3 * W2r[(k + 3) * 2 + 0];
    float s3 = h0 * W2r[(k + 0) * 2 + 1] + h1 * W2r[(k + 1) * 2 + 1]
             + h2 * W2r[(k + 2) * 2 + 1] + h3 * W2r[(k + 3) * 2 + 1];
    s0 = warpSum(s0); s1 = warpSum(s1); s2 = warpSum(s2); s3 = warpSum(s3);
    if (lane == 0) {
        g_hl[2 * w + 0] = s0 + b2l[0];
        g_hl[2 * w + 1] = s1 + b2l[1];
        g_hr[2 * w + 0] = s2 + b2r[0];
        g_hr[2 * w + 1] = s3 + b2r[1];
        // init for layer-2 edge pass (denom already consumed above)
        g_denom[w] = 0.f;
        g_num2[2 * w + 0] = 0.f;
        g_num2[2 * w + 1] = 0.f;
    }
}

// fused layer-2 edge pass
__global__ void edge_fused2(const int* __restrict__ src, const int* __restrict__ dst,
                            const float* __restrict__ att2) {
    int e = blockIdx.x * blockDim.x + threadIdx.x;
    if (e >= E_TOT) return;
    int s, d;
    if (e < N_EDGES) { s = src[e]; d = dst[e]; }
    else             { s = e - N_EDGES; d = s; }
    float2 hl = *(const float2*)(g_hl + 2 * s);
    float2 hr = *(const float2*)(g_hr + 2 * d);
    float sc = lrelu(hl.x + hr.x) * att2[0] + lrelu(hl.y + hr.y) * att2[1];
    float w = __expf(sc);
    atomicAdd(&g_denom[d], w);
    redAdd2(g_num2 + 2 * d, w * hl.x, w * hl.y);
}

// finalize layer 2: out = num/denom + bias2
__global__ void finalize2(const float* __restrict__ bias2, float* __restrict__ out) {
    int i = blockIdx.x * blockDim.x + threadIdx.x;
    if (i < N_NODES) {
        float inv = __fdividef(1.f, g_denom[i]);
        out[2 * i + 0] = g_num2[2 * i + 0] * inv + bias2[0];
        out[2 * i + 1] = g_num2[2 * i + 1] * inv + bias2[1];
    }
}

// ---------------- launch ----------------
extern "C" void kernel_launch(void* const* d_in, const int* in_sizes, int n_in,
                              void* d_out, int out_size) {
    const float* x    = (const float*)d_in[0];
    const int*   src  = (const int*)  d_in[1];
    const int*   dst  = (const int*)  d_in[2];
    const float* W1l  = (const float*)d_in[3];
    const float* b1l  = (const float*)d_in[4];
    const float* W1r  = (const float*)d_in[5];
    const float* b1r  = (const float*)d_in[6];
    const float* att1 = (const float*)d_in[7];
    const float* bias1= (const float*)d_in[8];
    const float* W2l  = (const float*)d_in[9];
    const float* b2l  = (const float*)d_in[10];
    const float* W2r  = (const float*)d_in[11];
    const float* b2r  = (const float*)d_in[12];
    const float* att2 = (const float*)d_in[13];
    const float* bias2= (const float*)d_in[14];
    float* out = (float*)d_out;

    const int gemmBlocks = (N_NODES + 127) / 128;             // 782
    const int edgeGrpBlocks    = (E_TOT * 8 + 255) / 256;     // 53125
    const int edgeThreadBlocks = (E_TOT + 255) / 256;         // 6641
    const int nodeBlocks = (N_NODES + 255) / 256;             // 391
    const int nodeWarpBlocks = (N_NODES * 32 + 255) / 256;    // 12500

    gemm_fused<<<gemmBlocks, 512>>>(x, W1l, b1l, W1r, b1r);
    edge_fused1<<<edgeGrpBlocks, 256>>>(src, dst, att1);
    lin2<<<nodeWarpBlocks, 256>>>(bias1, W2l, b2l, W2r, b2r);
    edge_fused2<<<edgeThreadBlocks, 256>>>(src, dst, att2);
    finalize2<<<nodeBlocks, 256>>>(bias2, out);
}

// round 8
// speedup vs baseline: 1.8133x; 1.3120x over previous
#include <cuda_runtime.h>
#include <cstdint>

#define N_NODES 100000
#define N_EDGES 1600000
#define N_FEAT  165
#define HIDDEN  128
#define NEG_SLOPE 0.2f
#define SCAN_BLK 512
#define N_SCAN_BLOCKS ((N_NODES + SCAN_BLK - 1) / SCAN_BLK)   // 196

// ---------------- scratch (static __device__ arrays; no allocation) -------
__device__ float g_xl[(size_t)N_NODES * HIDDEN];
__device__ float g_xr[(size_t)N_NODES * HIDDEN];
__device__ float g_hl[N_NODES * 2];
__device__ float g_hr[N_NODES * 2];
__device__ int   g_cnt[N_NODES];
__device__ int   g_rowstart[N_NODES + 1];
__device__ int   g_cursor[N_NODES];
__device__ int   g_blocksum[N_SCAN_BLOCKS];
__device__ int   g_csrsrc[N_EDGES];

// ---------------- helpers ----------------
__device__ __forceinline__ float warpSum(float v) {
    #pragma unroll
    for (int o = 16; o > 0; o >>= 1) v += __shfl_xor_sync(0xffffffffu, v, o);
    return v;
}

// two interleaved warp reductions (doubles shuffle ILP)
__device__ __forceinline__ void warpSum2(float& a, float& b) {
    #pragma unroll
    for (int o = 16; o > 0; o >>= 1) {
        a += __shfl_xor_sync(0xffffffffu, a, o);
        b += __shfl_xor_sync(0xffffffffu, b, o);
    }
}

__device__ __forceinline__ float lrelu(float v) {
    return v > 0.f ? v : NEG_SLOPE * v;
}

__device__ __forceinline__ float dot_lrelu(float4 a, float4 b, float4 t) {
    return lrelu(a.x + b.x) * t.x + lrelu(a.y + b.y) * t.y
         + lrelu(a.z + b.z) * t.z + lrelu(a.w + b.w) * t.w;
}

// ================= CSR build =================
__global__ void csr_zero() {
    int i = blockIdx.x * blockDim.x + threadIdx.x;
    if (i < N_NODES) g_cnt[i] = 0;
}

__global__ void csr_hist(const int* __restrict__ dst) {
    int e = blockIdx.x * blockDim.x + threadIdx.x;
    if (e < N_EDGES) atomicAdd(&g_cnt[dst[e]], 1);
}

// per-block exclusive scan (Hillis-Steele inclusive, then subtract own value)
__global__ void __launch_bounds__(SCAN_BLK) csr_scan1() {
    __shared__ int sh[SCAN_BLK];
    int t = threadIdx.x;
    int i = blockIdx.x * SCAN_BLK + t;
    int v = (i < N_NODES) ? g_cnt[i] : 0;
    sh[t] = v;
    __syncthreads();
    #pragma unroll
    for (int off = 1; off < SCAN_BLK; off <<= 1) {
        int add = (t >= off) ? sh[t - off] : 0;
        __syncthreads();
        sh[t] += add;
        __syncthreads();
    }
    if (i < N_NODES) g_rowstart[i] = sh[t] - v;          // exclusive within block
    if (t == SCAN_BLK - 1) g_blocksum[blockIdx.x] = sh[t];
}

__global__ void csr_scan2() {
    if (threadIdx.x == 0 && blockIdx.x == 0) {
        int run = 0;
        for (int b = 0; b < N_SCAN_BLOCKS; b++) {
            int t = g_blocksum[b];
            g_blocksum[b] = run;
            run += t;
        }
    }
}

__global__ void csr_scan3() {
    int i = blockIdx.x * blockDim.x + threadIdx.x;
    if (i < N_NODES) {
        int rs = g_rowstart[i] + g_blocksum[i / SCAN_BLK];
        g_rowstart[i] = rs;
        g_cursor[i] = rs;
    }
    if (i == 0) g_rowstart[N_NODES] = N_EDGES;
}

__global__ void csr_scatter(const int* __restrict__ src, const int* __restrict__ dst) {
    int e = blockIdx.x * blockDim.x + threadIdx.x;
    if (e < N_EDGES) {
        int pos = atomicAdd(&g_cursor[dst[e]], 1);
        g_csrsrc[pos] = src[e];
    }
}

// ================= fused GEMM: [Yl|Yr] = X @ [W1l|W1r] + b =================
__global__ void __launch_bounds__(512) gemm_fused(const float* __restrict__ X,
                                                  const float* __restrict__ W1l,
                                                  const float* __restrict__ b1l,
                                                  const float* __restrict__ W1r,
                                                  const float* __restrict__ b1r) {
    __shared__ float Xs[128][32];
    __shared__ float Ws[32][256];

    const int tid = threadIdx.x;
    const int tx = tid & 31;
    const int ty = tid >> 5;
    const int row0 = blockIdx.x * 128;

    float acc[8][8];
    #pragma unroll
    for (int i = 0; i < 8; i++)
        #pragma unroll
        for (int j = 0; j < 8; j++) acc[i][j] = 0.f;

    for (int k0 = 0; k0 < N_FEAT; k0 += 32) {
        #pragma unroll
        for (int i = 0; i < 8; i++) {
            int lin = tid + i * 512;
            int m = lin >> 5, k = lin & 31;
            int gr = row0 + m, gk = k0 + k;
            float v = 0.f;
            if (gr < N_NODES && gk < N_FEAT) v = X[(size_t)gr * N_FEAT + gk];
            Xs[m][k] = v;
        }
        #pragma unroll
        for (int i = 0; i < 16; i++) {
            int lin = tid + i * 512;
            int k = lin >> 8, n = lin & 255;
            int gk = k0 + k;
            float v = 0.f;
            if (gk < N_FEAT)
                v = (n < 128) ? W1l[gk * HIDDEN + n] : W1r[gk * HIDDEN + (n - 128)];
            Ws[k][n] = v;
        }
        __syncthreads();

        #pragma unroll
        for (int k = 0; k < 32; k++) {
            float a[8];
            #pragma unroll
            for (int i = 0; i < 8; i++) a[i] = Xs[ty * 8 + i][k];
            float4 b0 = *(const float4*)&Ws[k][tx * 8];
            float4 b1 = *(const float4*)&Ws[k][tx * 8 + 4];
            float b[8] = {b0.x, b0.y, b0.z, b0.w, b1.x, b1.y, b1.z, b1.w};
            #pragma unroll
            for (int i = 0; i < 8; i++)
                #pragma unroll
                for (int j = 0; j < 8; j++) acc[i][j] += a[i] * b[j];
        }
        __syncthreads();
    }

    #pragma unroll
    for (int i = 0; i < 8; i++) {
        int r = row0 + ty * 8 + i;
        if (r < N_NODES) {
            #pragma unroll
            for (int j = 0; j < 8; j++) {
                int c = tx * 8 + j;
                if (c < 128) g_xl[(size_t)r * HIDDEN + c] = acc[i][j] + b1l[c];
                else         g_xr[(size_t)r * HIDDEN + (c - 128)] = acc[i][j] + b1r[c - 128];
            }
        }
    }
}

// ================= layer 1: warp-per-node attention + finalize + lin2 ======
// Warp holds xr[d] (float4/lane) and accumulates w*xl[src] in registers.
// No atomics, no g_h materialization.
__global__ void __launch_bounds__(256) layer1_csr(const float* __restrict__ att,
                                                  const float* __restrict__ bias1,
                                                  const float* __restrict__ W2l,
                                                  const float* __restrict__ b2l,
                                                  const float* __restrict__ W2r,
                                                  const float* __restrict__ b2r) {
    int d = (blockIdx.x * blockDim.x + threadIdx.x) >> 5;
    int lane = threadIdx.x & 31;
    if (d >= N_NODES) return;

    float4 xr4  = ((const float4*)(g_xr + (size_t)d * HIDDEN))[lane];
    float4 att4 = __ldg(&((const float4*)att)[lane]);

    // self loop
    float4 xls = ((const float4*)(g_xl + (size_t)d * HIDDEN))[lane];
    float p = warpSum(dot_lrelu(xls, xr4, att4));
    float w = __expf(p);
    float wsum = w;
    float4 acc = make_float4(w * xls.x, w * xls.y, w * xls.z, w * xls.w);

    int j  = g_rowstart[d];
    int re = g_rowstart[d + 1];

    // pairs: two independent gather+score chains in flight
    for (; j + 1 < re; j += 2) {
        int s0 = g_csrsrc[j];
        int s1 = g_csrsrc[j + 1];
        float4 a0 = ((const float4*)(g_xl + (size_t)s0 * HIDDEN))[lane];
        float4 a1 = ((const float4*)(g_xl + (size_t)s1 * HIDDEN))[lane];
        float p0 = dot_lrelu(a0, xr4, att4);
        float p1 = dot_lrelu(a1, xr4, att4);
        warpSum2(p0, p1);
        float w0 = __expf(p0);
        float w1 = __expf(p1);
        wsum += w0 + w1;
        acc.x += w0 * a0.x + w1 * a1.x;
        acc.y += w0 * a0.y + w1 * a1.y;
        acc.z += w0 * a0.z + w1 * a1.z;
        acc.w += w0 * a0.w + w1 * a1.w;
    }
    if (j < re) {
        int s0 = g_csrsrc[j];
        float4 a0 = ((const float4*)(g_xl + (size_t)s0 * HIDDEN))[lane];
        float w0 = __expf(warpSum(dot_lrelu(a0, xr4, att4)));
        wsum += w0;
        acc.x += w0 * a0.x; acc.y += w0 * a0.y;
        acc.z += w0 * a0.z; acc.w += w0 * a0.w;
    }

    // finalize: h = relu(acc/wsum + bias1)
    float inv = __fdividef(1.f, wsum);
    float4 b4 = __ldg(&((const float4*)bias1)[lane]);
    float h0 = acc.x * inv + b4.x;  h0 = h0 > 0.f ? h0 : 0.f;
    float h1 = acc.y * inv + b4.y;  h1 = h1 > 0.f ? h1 : 0.f;
    float h2 = acc.z * inv + b4.z;  h2 = h2 > 0.f ? h2 : 0.f;
    float h3 = acc.w * inv + b4.w;  h3 = h3 > 0.f ? h3 : 0.f;

    // lin2: W2 is [128][2] row-major; float4 pair covers 2 rows x 2 cols
    float4 wl0 = __ldg(&((const float4*)W2l)[2 * lane]);
    float4 wl1 = __ldg(&((const float4*)W2l)[2 * lane + 1]);
    float4 wr0 = __ldg(&((const float4*)W2r)[2 * lane]);
    float4 wr1 = __ldg(&((const float4*)W2r)[2 * lane + 1]);

    float s0 = h0 * wl0.x + h1 * wl0.z + h2 * wl1.x + h3 * wl1.z;
    float s1 = h0 * wl0.y + h1 * wl0.w + h2 * wl1.y + h3 * wl1.w;
    float s2 = h0 * wr0.x + h1 * wr0.z + h2 * wr1.x + h3 * wr1.z;
    float s3 = h0 * wr0.y + h1 * wr0.w + h2 * wr1.y + h3 * wr1.w;
    warpSum2(s0, s1);
    warpSum2(s2, s3);

    if (lane == 0) {
        g_hl[2 * d + 0] = s0 + __ldg(&b2l[0]);
        g_hl[2 * d + 1] = s1 + __ldg(&b2l[1]);
        g_hr[2 * d + 0] = s2 + __ldg(&b2r[0]);
        g_hr[2 * d + 1] = s3 + __ldg(&b2r[1]);
    }
}

// ================= layer 2: warp-per-node, lanes stride edges ==============
__global__ void __launch_bounds__(256) layer2_csr(const float* __restrict__ att2,
                                                  const float* __restrict__ bias2,
                                                  float* __restrict__ out) {
    int d = (blockIdx.x * blockDim.x + threadIdx.x) >> 5;
    int lane = threadIdx.x & 31;
    if (d >= N_NODES) return;

    float a20 = __ldg(&att2[0]);
    float a21 = __ldg(&att2[1]);
    float2 hr2 = *(const float2*)(g_hr + 2 * d);

    float den = 0.f, n0 = 0.f, n1 = 0.f;

    // self loop on lane 0
    if (lane == 0) {
        float2 hls = *(const float2*)(g_hl + 2 * d);
        float sc = lrelu(hls.x + hr2.x) * a20 + lrelu(hls.y + hr2.y) * a21;
        float w = __expf(sc);
        den = w; n0 = w * hls.x; n1 = w * hls.y;
    }

    int rs = g_rowstart[d];
    int re = g_rowstart[d + 1];
    for (int j = rs + lane; j < re; j += 32) {
        int s = g_csrsrc[j];
        float2 hl = *(const float2*)(g_hl + 2 * s);
        float sc = lrelu(hl.x + hr2.x) * a20 + lrelu(hl.y + hr2.y) * a21;
        float w = __expf(sc);
        den += w; n0 += w * hl.x; n1 += w * hl.y;
    }

    warpSum2(n0, n1);
    den = warpSum(den);

    if (lane == 0) {
        float inv = __fdividef(1.f, den);
        out[2 * d + 0] = n0 * inv + __ldg(&bias2[0]);
        out[2 * d + 1] = n1 * inv + __ldg(&bias2[1]);
    }
}

// ---------------- launch ----------------
extern "C" void kernel_launch(void* const* d_in, const int* in_sizes, int n_in,
                              void* d_out, int out_size) {
    const float* x    = (const float*)d_in[0];
    const int*   src  = (const int*)  d_in[1];
    const int*   dst  = (const int*)  d_in[2];
    const float* W1l  = (const float*)d_in[3];
    const float* b1l  = (const float*)d_in[4];
    const float* W1r  = (const float*)d_in[5];
    const float* b1r  = (const float*)d_in[6];
    const float* att1 = (const float*)d_in[7];
    const float* bias1= (const float*)d_in[8];
    const float* W2l  = (const float*)d_in[9];
    const float* b2l  = (const float*)d_in[10];
    const float* W2r  = (const float*)d_in[11];
    const float* b2r  = (const float*)d_in[12];
    const float* att2 = (const float*)d_in[13];
    const float* bias2= (const float*)d_in[14];
    float* out = (float*)d_out;

    const int gemmBlocks = (N_NODES + 127) / 128;             // 782
    const int edgeBlocks = (N_EDGES + 255) / 256;             // 6250
    const int nodeBlocks = (N_NODES + 255) / 256;             // 391
    const int nodeWarpBlocks = (N_NODES * 32 + 255) / 256;    // 12500

    // CSR build (dst-sorted)
    csr_zero<<<nodeBlocks, 256>>>();
    csr_hist<<<edgeBlocks, 256>>>(dst);
    csr_scan1<<<N_SCAN_BLOCKS, SCAN_BLK>>>();
    csr_scan2<<<1, 32>>>();
    csr_scan3<<<nodeBlocks, 256>>>();
    csr_scatter<<<edgeBlocks, 256>>>(src, dst);

    // network
    gemm_fused<<<gemmBlocks, 512>>>(x, W1l, b1l, W1r, b1r);
    layer1_csr<<<nodeWarpBlocks, 256>>>(att1, bias1, W2l, b2l, W2r, b2r);
    layer2_csr<<<nodeWarpBlocks, 256>>>(att2, bias2, out);
}

// round 9
// speedup vs baseline: 1.8769x; 1.0351x over previous
#include <cuda_runtime.h>
#include <cstdint>

#define N_NODES 100000
#define N_EDGES 1600000
#define N_FEAT  165
#define HIDDEN  128
#define NEG_SLOPE 0.2f
#define SCAN_BLK 512
#define N_SCAN_BLOCKS ((N_NODES + SCAN_BLK - 1) / SCAN_BLK)   // 196

// ---------------- scratch (static __device__ arrays; no allocation) -------
__device__ float g_xl[(size_t)N_NODES * HIDDEN];
__device__ float g_xr[(size_t)N_NODES * HIDDEN];
__device__ float g_hl[N_NODES * 2];
__device__ float g_hr[N_NODES * 2];
__device__ int   g_cnt[N_NODES];
__device__ int   g_rowstart[N_NODES + 1];
__device__ int   g_cursor[N_NODES];
__device__ int   g_blocksum[N_SCAN_BLOCKS];
__device__ int   g_csrsrc[N_EDGES];

// ---------------- helpers ----------------
__device__ __forceinline__ float warpSum(float v) {
    #pragma unroll
    for (int o = 16; o > 0; o >>= 1) v += __shfl_xor_sync(0xffffffffu, v, o);
    return v;
}

__device__ __forceinline__ void warpSum2(float& a, float& b) {
    #pragma unroll
    for (int o = 16; o > 0; o >>= 1) {
        a += __shfl_xor_sync(0xffffffffu, a, o);
        b += __shfl_xor_sync(0xffffffffu, b, o);
    }
}

__device__ __forceinline__ void warpSum4(float& a, float& b, float& c, float& d) {
    #pragma unroll
    for (int o = 16; o > 0; o >>= 1) {
        a += __shfl_xor_sync(0xffffffffu, a, o);
        b += __shfl_xor_sync(0xffffffffu, b, o);
        c += __shfl_xor_sync(0xffffffffu, c, o);
        d += __shfl_xor_sync(0xffffffffu, d, o);
    }
}

__device__ __forceinline__ float lrelu(float v) {
    return v > 0.f ? v : NEG_SLOPE * v;
}

__device__ __forceinline__ float dot_lrelu(float4 a, float4 b, float4 t) {
    return lrelu(a.x + b.x) * t.x + lrelu(a.y + b.y) * t.y
         + lrelu(a.z + b.z) * t.z + lrelu(a.w + b.w) * t.w;
}

// packed f32x2 ops (sm_103a; ptxas never auto-fuses — PTX-only path)
#define FMA2(d, a, b, c) \
    asm("fma.rn.f32x2 %0, %1, %2, %3;" : "=l"(d) : "l"(a), "l"(b), "l"(c))
#define PACK2(out, lo, hi) \
    asm("mov.b64 %0, {%1, %2};" : "=l"(out) : "r"(lo), "r"(hi))
#define UNPACK2(lo, hi, in) \
    asm("mov.b64 {%0, %1}, %2;" : "=r"(lo), "=r"(hi) : "l"(in))

// ================= CSR build =================
__global__ void csr_zero() {
    int i = blockIdx.x * blockDim.x + threadIdx.x;
    if (i < N_NODES) g_cnt[i] = 0;
}

__global__ void csr_hist(const int* __restrict__ dst) {
    int e = blockIdx.x * blockDim.x + threadIdx.x;
    if (e < N_EDGES) atomicAdd(&g_cnt[dst[e]], 1);
}

__global__ void __launch_bounds__(SCAN_BLK) csr_scan1() {
    __shared__ int sh[SCAN_BLK];
    int t = threadIdx.x;
    int i = blockIdx.x * SCAN_BLK + t;
    int v = (i < N_NODES) ? g_cnt[i] : 0;
    sh[t] = v;
    __syncthreads();
    #pragma unroll
    for (int off = 1; off < SCAN_BLK; off <<= 1) {
        int add = (t >= off) ? sh[t - off] : 0;
        __syncthreads();
        sh[t] += add;
        __syncthreads();
    }
    if (i < N_NODES) g_rowstart[i] = sh[t] - v;
    if (t == SCAN_BLK - 1) g_blocksum[blockIdx.x] = sh[t];
}

// parallel scan of the 196 block sums (one block)
__global__ void __launch_bounds__(256) csr_scan2() {
    __shared__ int sh[256];
    int t = threadIdx.x;
    int v = (t < N_SCAN_BLOCKS) ? g_blocksum[t] : 0;
    sh[t] = v;
    __syncthreads();
    #pragma unroll
    for (int off = 1; off < 256; off <<= 1) {
        int add = (t >= off) ? sh[t - off] : 0;
        __syncthreads();
        sh[t] += add;
        __syncthreads();
    }
    if (t < N_SCAN_BLOCKS) g_blocksum[t] = sh[t] - v;   // exclusive
}

__global__ void csr_scan3() {
    int i = blockIdx.x * blockDim.x + threadIdx.x;
    if (i < N_NODES) {
        int rs = g_rowstart[i] + g_blocksum[i / SCAN_BLK];
        g_rowstart[i] = rs;
        g_cursor[i] = rs;
    }
    if (i == 0) g_rowstart[N_NODES] = N_EDGES;
}

__global__ void csr_scatter(const int* __restrict__ src, const int* __restrict__ dst) {
    int e = blockIdx.x * blockDim.x + threadIdx.x;
    if (e < N_EDGES) {
        int pos = atomicAdd(&g_cursor[dst[e]], 1);
        g_csrsrc[pos] = src[e];
    }
}

// ================= fused GEMM (f32x2 packed FMA): [Yl|Yr] = X @ [W1l|W1r] ==
__global__ void __launch_bounds__(512) gemm_fused(const float* __restrict__ X,
                                                  const float* __restrict__ W1l,
                                                  const float* __restrict__ b1l,
                                                  const float* __restrict__ W1r,
                                                  const float* __restrict__ b1r) {
    __shared__ float Xs[128][32];
    __shared__ float Ws[32][256];

    const int tid = threadIdx.x;
    const int tx = tid & 31;
    const int ty = tid >> 5;
    const int row0 = blockIdx.x * 128;

    // 8 rows x 4 f32x2 pairs = 8x8 microtile
    unsigned long long acc[8][4];
    #pragma unroll
    for (int i = 0; i < 8; i++)
        #pragma unroll
        for (int j = 0; j < 4; j++) acc[i][j] = 0ULL;   // (0.f,0.f)

    for (int k0 = 0; k0 < N_FEAT; k0 += 32) {
        #pragma unroll
        for (int i = 0; i < 8; i++) {
            int lin = tid + i * 512;
            int m = lin >> 5, k = lin & 31;
            int gr = row0 + m, gk = k0 + k;
            float v = 0.f;
            if (gr < N_NODES && gk < N_FEAT) v = X[(size_t)gr * N_FEAT + gk];
            Xs[m][k] = v;
        }
        #pragma unroll
        for (int i = 0; i < 16; i++) {
            int lin = tid + i * 512;
            int k = lin >> 8, n = lin & 255;
            int gk = k0 + k;
            float v = 0.f;
            if (gk < N_FEAT)
                v = (n < 128) ? W1l[gk * HIDDEN + n] : W1r[gk * HIDDEN + (n - 128)];
            Ws[k][n] = v;
        }
        __syncthreads();

        #pragma unroll
        for (int k = 0; k < 32; k++) {
            // B: 4 packed pairs straight from shared (16B-aligned)
            ulonglong2 B0 = *(const ulonglong2*)&Ws[k][tx * 8];
            ulonglong2 B1 = *(const ulonglong2*)&Ws[k][tx * 8 + 4];
            unsigned long long bb[4] = {B0.x, B0.y, B1.x, B1.y};
            #pragma unroll
            for (int i = 0; i < 8; i++) {
                float a = Xs[ty * 8 + i][k];            // warp-uniform broadcast
                unsigned long long aa;
                PACK2(aa, __float_as_uint(a), __float_as_uint(a));
                #pragma unroll
                for (int j = 0; j < 4; j++)
                    FMA2(acc[i][j], aa, bb[j], acc[i][j]);
            }
        }
        __syncthreads();
    }

    #pragma unroll
    for (int i = 0; i < 8; i++) {
        int r = row0 + ty * 8 + i;
        if (r < N_NODES) {
            #pragma unroll
            for (int j = 0; j < 4; j++) {
                unsigned int lo, hi;
                UNPACK2(lo, hi, acc[i][j]);
                int c = tx * 8 + j * 2;                 // pair never crosses 128
                if (c < 128) {
                    g_xl[(size_t)r * HIDDEN + c]     = __uint_as_float(lo) + b1l[c];
                    g_xl[(size_t)r * HIDDEN + c + 1] = __uint_as_float(hi) + b1l[c + 1];
                } else {
                    g_xr[(size_t)r * HIDDEN + (c - 128)] = __uint_as_float(lo) + b1r[c - 128];
                    g_xr[(size_t)r * HIDDEN + (c - 127)] = __uint_as_float(hi) + b1r[c - 127];
                }
            }
        }
    }
}

// ================= layer 1: warp-per-node, 4-wide edge unroll ==============
__global__ void __launch_bounds__(256) layer1_csr(const float* __restrict__ att,
                                                  const float* __restrict__ bias1,
                                                  const float* __restrict__ W2l,
                                                  const float* __restrict__ b2l,
                                                  const float* __restrict__ W2r,
                                                  const float* __restrict__ b2r) {
    int d = (blockIdx.x * blockDim.x + threadIdx.x) >> 5;
    int lane = threadIdx.x & 31;
    if (d >= N_NODES) return;

    float4 xr4  = ((const float4*)(g_xr + (size_t)d * HIDDEN))[lane];
    float4 att4 = __ldg(&((const float4*)att)[lane]);

    // self loop
    float4 xls = ((const float4*)(g_xl + (size_t)d * HIDDEN))[lane];
    float p = warpSum(dot_lrelu(xls, xr4, att4));
    float w = __expf(p);
    float wsum = w;
    float4 acc = make_float4(w * xls.x, w * xls.y, w * xls.z, w * xls.w);

    int j  = g_rowstart[d];
    int re = g_rowstart[d + 1];

    // 4 independent gather+score chains
    for (; j + 3 < re; j += 4) {
        int s0 = g_csrsrc[j],     s1 = g_csrsrc[j + 1];
        int s2 = g_csrsrc[j + 2], s3 = g_csrsrc[j + 3];
        float4 a0 = ((const float4*)(g_xl + (size_t)s0 * HIDDEN))[lane];
        float4 a1 = ((const float4*)(g_xl + (size_t)s1 * HIDDEN))[lane];
        float4 a2 = ((const float4*)(g_xl + (size_t)s2 * HIDDEN))[lane];
        float4 a3 = ((const float4*)(g_xl + (size_t)s3 * HIDDEN))[lane];
        float p0 = dot_lrelu(a0, xr4, att4);
        float p1 = dot_lrelu(a1, xr4, att4);
        float p2 = dot_lrelu(a2, xr4, att4);
        float p3 = dot_lrelu(a3, xr4, att4);
        warpSum4(p0, p1, p2, p3);
        float w0 = __expf(p0), w1 = __expf(p1);
        float w2 = __expf(p2), w3 = __expf(p3);
        wsum += (w0 + w1) + (w2 + w3);
        acc.x += w0 * a0.x + w1 * a1.x + w2 * a2.x + w3 * a3.x;
        acc.y += w0 * a0.y + w1 * a1.y + w2 * a2.y + w3 * a3.y;
        acc.z += w0 * a0.z + w1 * a1.z + w2 * a2.z + w3 * a3.z;
        acc.w += w0 * a0.w + w1 * a1.w + w2 * a2.w + w3 * a3.w;
    }
    for (; j + 1 < re; j += 2) {
        int s0 = g_csrsrc[j], s1 = g_csrsrc[j + 1];
        float4 a0 = ((const float4*)(g_xl + (size_t)s0 * HIDDEN))[lane];
        float4 a1 = ((const float4*)(g_xl + (size_t)s1 * HIDDEN))[lane];
        float p0 = dot_lrelu(a0, xr4, att4);
        float p1 = dot_lrelu(a1, xr4, att4);
        warpSum2(p0, p1);
        float w0 = __expf(p0), w1 = __expf(p1);
        wsum += w0 + w1;
        acc.x += w0 * a0.x + w1 * a1.x;
        acc.y += w0 * a0.y + w1 * a1.y;
        acc.z += w0 * a0.z + w1 * a1.z;
        acc.w += w0 * a0.w + w1 * a1.w;
    }
    if (j < re) {
        int s0 = g_csrsrc[j];
        float4 a0 = ((const float4*)(g_xl + (size_t)s0 * HIDDEN))[lane];
        float w0 = __expf(warpSum(dot_lrelu(a0, xr4, att4)));
        wsum += w0;
        acc.x += w0 * a0.x; acc.y += w0 * a0.y;
        acc.z += w0 * a0.z; acc.w += w0 * a0.w;
    }

    // finalize: h = relu(acc/wsum + bias1), then lin2
    float inv = __fdividef(1.f, wsum);
    float4 b4 = __ldg(&((const float4*)bias1)[lane]);
    float h0 = acc.x * inv + b4.x;  h0 = h0 > 0.f ? h0 : 0.f;
    float h1 = acc.y * inv + b4.y;  h1 = h1 > 0.f ? h1 : 0.f;
    float h2 = acc.z * inv + b4.z;  h2 = h2 > 0.f ? h2 : 0.f;
    float h3 = acc.w * inv + b4.w;  h3 = h3 > 0.f ? h3 : 0.f;

    float4 wl0 = __ldg(&((const float4*)W2l)[2 * lane]);
    float4 wl1 = __ldg(&((const float4*)W2l)[2 * lane + 1]);
    float4 wr0 = __ldg(&((const float4*)W2r)[2 * lane]);
    float4 wr1 = __ldg(&((const float4*)W2r)[2 * lane + 1]);

    float s0 = h0 * wl0.x + h1 * wl0.z + h2 * wl1.x + h3 * wl1.z;
    float s1 = h0 * wl0.y + h1 * wl0.w + h2 * wl1.y + h3 * wl1.w;
    float s2 = h0 * wr0.x + h1 * wr0.z + h2 * wr1.x + h3 * wr1.z;
    float s3 = h0 * wr0.y + h1 * wr0.w + h2 * wr1.y + h3 * wr1.w;
    warpSum4(s0, s1, s2, s3);

    if (lane == 0) {
        g_hl[2 * d + 0] = s0 + __ldg(&b2l[0]);
        g_hl[2 * d + 1] = s1 + __ldg(&b2l[1]);
        g_hr[2 * d + 0] = s2 + __ldg(&b2r[0]);
        g_hr[2 * d + 1] = s3 + __ldg(&b2r[1]);
    }
}

// ================= layer 2: warp-per-node, lanes stride edges ==============
__global__ void __launch_bounds__(256) layer2_csr(const float* __restrict__ att2,
                                                  const float* __restrict__ bias2,
                                                  float* __restrict__ out) {
    int d = (blockIdx.x * blockDim.x + threadIdx.x) >> 5;
    int lane = threadIdx.x & 31;
    if (d >= N_NODES) return;

    float a20 = __ldg(&att2[0]);
    float a21 = __ldg(&att2[1]);
    float2 hr2 = *(const float2*)(g_hr + 2 * d);

    float den = 0.f, n0 = 0.f, n1 = 0.f;

    if (lane == 0) {
        float2 hls = *(const float2*)(g_hl + 2 * d);
        float sc = lrelu(hls.x + hr2.x) * a20 + lrelu(hls.y + hr2.y) * a21;
        float w = __expf(sc);
        den = w; n0 = w * hls.x; n1 = w * hls.y;
    }

    int rs = g_rowstart[d];
    int re = g_rowstart[d + 1];
    for (int j = rs + lane; j < re; j += 32) {
        int s = g_csrsrc[j];
        float2 hl = *(const float2*)(g_hl + 2 * s);
        float sc = lrelu(hl.x + hr2.x) * a20 + lrelu(hl.y + hr2.y) * a21;
        float w = __expf(sc);
        den += w; n0 += w * hl.x; n1 += w * hl.y;
    }

    warpSum2(n0, n1);
    den = warpSum(den);

    if (lane == 0) {
        float inv = __fdividef(1.f, den);
        out[2 * d + 0] = n0 * inv + __ldg(&bias2[0]);
        out[2 * d + 1] = n1 * inv + __ldg(&bias2[1]);
    }
}

// ---------------- launch ----------------
extern "C" void kernel_launch(void* const* d_in, const int* in_sizes, int n_in,
                              void* d_out, int out_size) {
    const float* x    = (const float*)d_in[0];
    const int*   src  = (const int*)  d_in[1];
    const int*   dst  = (const int*)  d_in[2];
    const float* W1l  = (const float*)d_in[3];
    const float* b1l  = (const float*)d_in[4];
    const float* W1r  = (const float*)d_in[5];
    const float* b1r  = (const float*)d_in[6];
    const float* att1 = (const float*)d_in[7];
    const float* bias1= (const float*)d_in[8];
    const float* W2l  = (const float*)d_in[9];
    const float* b2l  = (const float*)d_in[10];
    const float* W2r  = (const float*)d_in[11];
    const float* b2r  = (const float*)d_in[12];
    const float* att2 = (const float*)d_in[13];
    const float* bias2= (const float*)d_in[14];
    float* out = (float*)d_out;

    const int gemmBlocks = (N_NODES + 127) / 128;             // 782
    const int edgeBlocks = (N_EDGES + 255) / 256;             // 6250
    const int nodeBlocks = (N_NODES + 255) / 256;             // 391
    const int nodeWarpBlocks = (N_NODES * 32 + 255) / 256;    // 12500

    // CSR build interleaved with GEMM; gemm_fused placed 4th so ncu (-s 5 -c 1)
    // profiles it next round. gemm is independent of the CSR chain.
    csr_zero<<<nodeBlocks, 256>>>();
    csr_hist<<<edgeBlocks, 256>>>(dst);
    csr_scan1<<<N_SCAN_BLOCKS, SCAN_BLK>>>();
    gemm_fused<<<gemmBlocks, 512>>>(x, W1l, b1l, W1r, b1r);
    csr_scan2<<<1, 256>>>();
    csr_scan3<<<nodeBlocks, 256>>>();
    csr_scatter<<<edgeBlocks, 256>>>(src, dst);
    layer1_csr<<<nodeWarpBlocks, 256>>>(att1, bias1, W2l, b2l, W2r, b2r);
    layer2_csr<<<nodeWarpBlocks, 256>>>(att2, bias2, out);
}

// round 10
// speedup vs baseline: 2.4917x; 1.3276x over previous
#include <cuda_runtime.h>
#include <cstdint>

#define N_NODES 100000
#define N_EDGES 1600000
#define N_FEAT  165
#define HIDDEN  128
#define NEG_SLOPE 0.2f
#define SCAN_BLK 512
#define N_SCAN_BLOCKS ((N_NODES + SCAN_BLK - 1) / SCAN_BLK)   // 196

// ---------------- scratch (static __device__ arrays; no allocation) -------
__device__ float g_xl[(size_t)N_NODES * HIDDEN];
__device__ float g_xr[(size_t)N_NODES * HIDDEN];
__device__ float g_hl[N_NODES * 2];
__device__ float g_hr[N_NODES * 2];
__device__ int   g_cnt[N_NODES];
__device__ int   g_rowstart[N_NODES + 1];
__device__ int   g_cursor[N_NODES];
__device__ int   g_blocksum[N_SCAN_BLOCKS];
__device__ int   g_csrsrc[N_EDGES];

// ---------------- helpers ----------------
__device__ __forceinline__ float warpSum(float v) {
    #pragma unroll
    for (int o = 16; o > 0; o >>= 1) v += __shfl_xor_sync(0xffffffffu, v, o);
    return v;
}

__device__ __forceinline__ void warpSum2(float& a, float& b) {
    #pragma unroll
    for (int o = 16; o > 0; o >>= 1) {
        a += __shfl_xor_sync(0xffffffffu, a, o);
        b += __shfl_xor_sync(0xffffffffu, b, o);
    }
}

__device__ __forceinline__ void warpSum4(float& a, float& b, float& c, float& d) {
    #pragma unroll
    for (int o = 16; o > 0; o >>= 1) {
        a += __shfl_xor_sync(0xffffffffu, a, o);
        b += __shfl_xor_sync(0xffffffffu, b, o);
        c += __shfl_xor_sync(0xffffffffu, c, o);
        d += __shfl_xor_sync(0xffffffffu, d, o);
    }
}

__device__ __forceinline__ float lrelu(float v) {
    return v > 0.f ? v : NEG_SLOPE * v;
}

__device__ __forceinline__ float dot_lrelu(float4 a, float4 b, float4 t) {
    return lrelu(a.x + b.x) * t.x + lrelu(a.y + b.y) * t.y
         + lrelu(a.z + b.z) * t.z + lrelu(a.w + b.w) * t.w;
}

// cp.async primitives
__device__ __forceinline__ uint32_t s2u(const void* p) {
    return (uint32_t)__cvta_generic_to_shared(p);
}
#define CPA4(d, s)  asm volatile("cp.async.ca.shared.global [%0], [%1], 4;"  :: "r"(d), "l"(s))
#define CPA16(d, s) asm volatile("cp.async.cg.shared.global [%0], [%1], 16;" :: "r"(d), "l"(s))
#define CP_COMMIT() asm volatile("cp.async.commit_group;" ::: "memory")
#define CP_WAIT1()  asm volatile("cp.async.wait_group 1;" ::: "memory")

// ================= CSR build =================
__global__ void csr_zero() {
    int i = blockIdx.x * blockDim.x + threadIdx.x;
    if (i < N_NODES) g_cnt[i] = 0;
}

__global__ void csr_hist(const int* __restrict__ dst) {
    int e = blockIdx.x * blockDim.x + threadIdx.x;
    if (e < N_EDGES) atomicAdd(&g_cnt[dst[e]], 1);
}

__global__ void __launch_bounds__(SCAN_BLK) csr_scan1() {
    __shared__ int sh[SCAN_BLK];
    int t = threadIdx.x;
    int i = blockIdx.x * SCAN_BLK + t;
    int v = (i < N_NODES) ? g_cnt[i] : 0;
    sh[t] = v;
    __syncthreads();
    #pragma unroll
    for (int off = 1; off < SCAN_BLK; off <<= 1) {
        int add = (t >= off) ? sh[t - off] : 0;
        __syncthreads();
        sh[t] += add;
        __syncthreads();
    }
    if (i < N_NODES) g_rowstart[i] = sh[t] - v;
    if (t == SCAN_BLK - 1) g_blocksum[blockIdx.x] = sh[t];
}

__global__ void __launch_bounds__(256) csr_scan2() {
    __shared__ int sh[256];
    int t = threadIdx.x;
    int v = (t < N_SCAN_BLOCKS) ? g_blocksum[t] : 0;
    sh[t] = v;
    __syncthreads();
    #pragma unroll
    for (int off = 1; off < 256; off <<= 1) {
        int add = (t >= off) ? sh[t - off] : 0;
        __syncthreads();
        sh[t] += add;
        __syncthreads();
    }
    if (t < N_SCAN_BLOCKS) g_blocksum[t] = sh[t] - v;   // exclusive
}

__global__ void csr_scan3() {
    int i = blockIdx.x * blockDim.x + threadIdx.x;
    if (i < N_NODES) {
        int rs = g_rowstart[i] + g_blocksum[i / SCAN_BLK];
        g_rowstart[i] = rs;
        g_cursor[i] = rs;
    }
    if (i == 0) g_rowstart[N_NODES] = N_EDGES;
}

__global__ void csr_scatter(const int* __restrict__ src, const int* __restrict__ dst) {
    int e = blockIdx.x * blockDim.x + threadIdx.x;
    if (e < N_EDGES) {
        int pos = atomicAdd(&g_cursor[dst[e]], 1);
        g_csrsrc[pos] = src[e];
    }
}

// ================= fused GEMM: [Yl|Yr] = X @ [W1l|W1r] + b ================
// 64x256 tile, 256 threads, 8x8 microtile, 2 CTAs/SM, cp.async 2-stage.
// Dynamic smem: Xs 2*64*32 + Ws 2*32*256 floats = 80KB.
#define GEMM_TM 64
#define N_CHUNKS 6   // 5 full 32-chunks + 5-col tail

__global__ void __launch_bounds__(256, 2) gemm_fused(const float* __restrict__ X,
                                                     const float* __restrict__ W1l,
                                                     const float* __restrict__ b1l,
                                                     const float* __restrict__ W1r,
                                                     const float* __restrict__ b1r) {
    extern __shared__ float dsm[];
    float* Xs = dsm;            // [2][64][32]
    float* Ws = dsm + 4096;     // [2][32][256]

    const int tid = threadIdx.x;
    const int tx = tid & 31;    // 0..31 -> 8 cols each
    const int ty = tid >> 5;    // 0..7  -> 8 rows each
    const int row0 = blockIdx.x * GEMM_TM;

    // async load of chunk c (c < 5) into stage stg
    auto load_async = [&](int c, int stg) {
        int k0 = c * 32;
        // X tile: 64 rows x 32 k, 4B ops (X rows not 16B aligned)
        float* xbase = Xs + stg * 2048;
        #pragma unroll
        for (int i = 0; i < 8; i++) {
            int lin = tid + i * 256;          // 0..2047
            int m = lin >> 5, k = lin & 31;
            int gr = row0 + m;
            if (gr < N_NODES)
                CPA4(s2u(xbase + m * 32 + k), X + (size_t)gr * N_FEAT + k0 + k);
        }
        // W tile: 32 k x 256 n, 16B ops (gk <= 159 < 165 always here)
        float* wbase = Ws + stg * 8192;
        #pragma unroll
        for (int i = 0; i < 8; i++) {
            int lin = tid + i * 256;          // 0..2047 lines of 4 floats
            int k = lin >> 6;                 // 0..31
            int n0 = (lin & 63) * 4;          // 0..252
            int gk = k0 + k;
            const float* src = (n0 < 128) ? (W1l + gk * HIDDEN + n0)
                                          : (W1r + gk * HIDDEN + (n0 - 128));
            CPA16(s2u(wbase + k * 256 + n0), src);
        }
    };

    // synchronous guarded load of the 5-col tail chunk into stage 1
    auto load_tail = [&]() {
        float* xbase = Xs + 1 * 2048;
        for (int lin = tid; lin < GEMM_TM * 5; lin += 256) {
            int m = lin / 5, k = lin % 5;
            int gr = row0 + m;
            xbase[m * 32 + k] = (gr < N_NODES) ? X[(size_t)gr * N_FEAT + 160 + k] : 0.f;
        }
        float* wbase = Ws + 1 * 8192;
        for (int lin = tid; lin < 5 * 256; lin += 256) {
            int k = lin >> 8, n = lin & 255;
            int gk = 160 + k;
            wbase[k * 256 + n] = (n < 128) ? W1l[gk * HIDDEN + n]
                                           : W1r[gk * HIDDEN + (n - 128)];
        }
    };

    float acc[8][8];
    #pragma unroll
    for (int i = 0; i < 8; i++)
        #pragma unroll
        for (int j = 0; j < 8; j++) acc[i][j] = 0.f;

    load_async(0, 0);
    CP_COMMIT();

    for (int c = 0; c < N_CHUNKS; c++) {
        int stg = c & 1;
        // prefetch next chunk
        if (c + 1 < N_CHUNKS) {
            if (c + 1 < 5) load_async(c + 1, (c + 1) & 1);
            else           load_tail();
            CP_COMMIT();                      // empty group ok for tail
        }
        CP_WAIT1();                           // chunk c resident
        __syncthreads();

        const float* xb = Xs + stg * 2048 + ty * 8 * 32;
        const float* wb = Ws + stg * 8192;
        int klim = (c == 5) ? 5 : 32;
        if (c < 5) {
            #pragma unroll
            for (int k = 0; k < 32; k++) {
                float a[8];
                #pragma unroll
                for (int i = 0; i < 8; i++) a[i] = xb[i * 32 + k];   // broadcast
                float4 b0 = *(const float4*)(wb + k * 256 + tx * 8);
                float4 b1 = *(const float4*)(wb + k * 256 + tx * 8 + 4);
                float b[8] = {b0.x, b0.y, b0.z, b0.w, b1.x, b1.y, b1.z, b1.w};
                #pragma unroll
                for (int i = 0; i < 8; i++)
                    #pragma unroll
                    for (int j = 0; j < 8; j++) acc[i][j] += a[i] * b[j];
            }
        } else {
            #pragma unroll
            for (int k = 0; k < 5; k++) {
                float a[8];
                #pragma unroll
                for (int i = 0; i < 8; i++) a[i] = xb[i * 32 + k];
                float4 b0 = *(const float4*)(wb + k * 256 + tx * 8);
                float4 b1 = *(const float4*)(wb + k * 256 + tx * 8 + 4);
                float b[8] = {b0.x, b0.y, b0.z, b0.w, b1.x, b1.y, b1.z, b1.w};
                #pragma unroll
                for (int i = 0; i < 8; i++)
                    #pragma unroll
                    for (int j = 0; j < 8; j++) acc[i][j] += a[i] * b[j];
            }
        }
        (void)klim;
        __syncthreads();
    }

    #pragma unroll
    for (int i = 0; i < 8; i++) {
        int r = row0 + ty * 8 + i;
        if (r < N_NODES) {
            #pragma unroll
            for (int j = 0; j < 8; j++) {
                int c = tx * 8 + j;
                if (c < 128) g_xl[(size_t)r * HIDDEN + c] = acc[i][j] + b1l[c];
                else         g_xr[(size_t)r * HIDDEN + (c - 128)] = acc[i][j] + b1r[c - 128];
            }
        }
    }
}

// ================= layer 1: warp-per-node, 4-wide edge unroll ==============
__global__ void __launch_bounds__(256) layer1_csr(const float* __restrict__ att,
                                                  const float* __restrict__ bias1,
                                                  const float* __restrict__ W2l,
                                                  const float* __restrict__ b2l,
                                                  const float* __restrict__ W2r,
                                                  const float* __restrict__ b2r) {
    int d = (blockIdx.x * blockDim.x + threadIdx.x) >> 5;
    int lane = threadIdx.x & 31;
    if (d >= N_NODES) return;

    float4 xr4  = ((const float4*)(g_xr + (size_t)d * HIDDEN))[lane];
    float4 att4 = __ldg(&((const float4*)att)[lane]);

    float4 xls = ((const float4*)(g_xl + (size_t)d * HIDDEN))[lane];
    float p = warpSum(dot_lrelu(xls, xr4, att4));
    float w = __expf(p);
    float wsum = w;
    float4 acc = make_float4(w * xls.x, w * xls.y, w * xls.z, w * xls.w);

    int j  = g_rowstart[d];
    int re = g_rowstart[d + 1];

    for (; j + 3 < re; j += 4) {
        int s0 = g_csrsrc[j],     s1 = g_csrsrc[j + 1];
        int s2 = g_csrsrc[j + 2], s3 = g_csrsrc[j + 3];
        float4 a0 = ((const float4*)(g_xl + (size_t)s0 * HIDDEN))[lane];
        float4 a1 = ((const float4*)(g_xl + (size_t)s1 * HIDDEN))[lane];
        float4 a2 = ((const float4*)(g_xl + (size_t)s2 * HIDDEN))[lane];
        float4 a3 = ((const float4*)(g_xl + (size_t)s3 * HIDDEN))[lane];
        float p0 = dot_lrelu(a0, xr4, att4);
        float p1 = dot_lrelu(a1, xr4, att4);
        float p2 = dot_lrelu(a2, xr4, att4);
        float p3 = dot_lrelu(a3, xr4, att4);
        warpSum4(p0, p1, p2, p3);
        float w0 = __expf(p0), w1 = __expf(p1);
        float w2 = __expf(p2), w3 = __expf(p3);
        wsum += (w0 + w1) + (w2 + w3);
        acc.x += w0 * a0.x + w1 * a1.x + w2 * a2.x + w3 * a3.x;
        acc.y += w0 * a0.y + w1 * a1.y + w2 * a2.y + w3 * a3.y;
        acc.z += w0 * a0.z + w1 * a1.z + w2 * a2.z + w3 * a3.z;
        acc.w += w0 * a0.w + w1 * a1.w + w2 * a2.w + w3 * a3.w;
    }
    for (; j + 1 < re; j += 2) {
        int s0 = g_csrsrc[j], s1 = g_csrsrc[j + 1];
        float4 a0 = ((const float4*)(g_xl + (size_t)s0 * HIDDEN))[lane];
        float4 a1 = ((const float4*)(g_xl + (size_t)s1 * HIDDEN))[lane];
        float p0 = dot_lrelu(a0, xr4, att4);
        float p1 = dot_lrelu(a1, xr4, att4);
        warpSum2(p0, p1);
        float w0 = __expf(p0), w1 = __expf(p1);
        wsum += w0 + w1;
        acc.x += w0 * a0.x + w1 * a1.x;
        acc.y += w0 * a0.y + w1 * a1.y;
        acc.z += w0 * a0.z + w1 * a1.z;
        acc.w += w0 * a0.w + w1 * a1.w;
    }
    if (j < re) {
        int s0 = g_csrsrc[j];
        float4 a0 = ((const float4*)(g_xl + (size_t)s0 * HIDDEN))[lane];
        float w0 = __expf(warpSum(dot_lrelu(a0, xr4, att4)));
        wsum += w0;
        acc.x += w0 * a0.x; acc.y += w0 * a0.y;
        acc.z += w0 * a0.z; acc.w += w0 * a0.w;
    }

    float inv = __fdividef(1.f, wsum);
    float4 b4 = __ldg(&((const float4*)bias1)[lane]);
    float h0 = acc.x * inv + b4.x;  h0 = h0 > 0.f ? h0 : 0.f;
    float h1 = acc.y * inv + b4.y;  h1 = h1 > 0.f ? h1 : 0.f;
    float h2 = acc.z * inv + b4.z;  h2 = h2 > 0.f ? h2 : 0.f;
    float h3 = acc.w * inv + b4.w;  h3 = h3 > 0.f ? h3 : 0.f;

    float4 wl0 = __ldg(&((const float4*)W2l)[2 * lane]);
    float4 wl1 = __ldg(&((const float4*)W2l)[2 * lane + 1]);
    float4 wr0 = __ldg(&((const float4*)W2r)[2 * lane]);
    float4 wr1 = __ldg(&((const float4*)W2r)[2 * lane + 1]);

    float s0 = h0 * wl0.x + h1 * wl0.z + h2 * wl1.x + h3 * wl1.z;
    float s1 = h0 * wl0.y + h1 * wl0.w + h2 * wl1.y + h3 * wl1.w;
    float s2 = h0 * wr0.x + h1 * wr0.z + h2 * wr1.x + h3 * wr1.z;
    float s3 = h0 * wr0.y + h1 * wr0.w + h2 * wr1.y + h3 * wr1.w;
    warpSum4(s0, s1, s2, s3);

    if (lane == 0) {
        g_hl[2 * d + 0] = s0 + __ldg(&b2l[0]);
        g_hl[2 * d + 1] = s1 + __ldg(&b2l[1]);
        g_hr[2 * d + 0] = s2 + __ldg(&b2r[0]);
        g_hr[2 * d + 1] = s3 + __ldg(&b2r[1]);
    }
}

// ================= layer 2: warp-per-node, lanes stride edges ==============
__global__ void __launch_bounds__(256) layer2_csr(const float* __restrict__ att2,
                                                  const float* __restrict__ bias2,
                                                  float* __restrict__ out) {
    int d = (blockIdx.x * blockDim.x + threadIdx.x) >> 5;
    int lane = threadIdx.x & 31;
    if (d >= N_NODES) return;

    float a20 = __ldg(&att2[0]);
    float a21 = __ldg(&att2[1]);
    float2 hr2 = *(const float2*)(g_hr + 2 * d);

    float den = 0.f, n0 = 0.f, n1 = 0.f;

    if (lane == 0) {
        float2 hls = *(const float2*)(g_hl + 2 * d);
        float sc = lrelu(hls.x + hr2.x) * a20 + lrelu(hls.y + hr2.y) * a21;
        float w = __expf(sc);
        den = w; n0 = w * hls.x; n1 = w * hls.y;
    }

    int rs = g_rowstart[d];
    int re = g_rowstart[d + 1];
    for (int j = rs + lane; j < re; j += 32) {
        int s = g_csrsrc[j];
        float2 hl = *(const float2*)(g_hl + 2 * s);
        float sc = lrelu(hl.x + hr2.x) * a20 + lrelu(hl.y + hr2.y) * a21;
        float w = __expf(sc);
        den += w; n0 += w * hl.x; n1 += w * hl.y;
    }

    warpSum2(n0, n1);
    den = warpSum(den);

    if (lane == 0) {
        float inv = __fdividef(1.f, den);
        out[2 * d + 0] = n0 * inv + __ldg(&bias2[0]);
        out[2 * d + 1] = n1 * inv + __ldg(&bias2[1]);
    }
}

// ---------------- launch ----------------
extern "C" void kernel_launch(void* const* d_in, const int* in_sizes, int n_in,
                              void* d_out, int out_size) {
    const float* x    = (const float*)d_in[0];
    const int*   src  = (const int*)  d_in[1];
    const int*   dst  = (const int*)  d_in[2];
    const float* W1l  = (const float*)d_in[3];
    const float* b1l  = (const float*)d_in[4];
    const float* W1r  = (const float*)d_in[5];
    const float* b1r  = (const float*)d_in[6];
    const float* att1 = (const float*)d_in[7];
    const float* bias1= (const float*)d_in[8];
    const float* W2l  = (const float*)d_in[9];
    const float* b2l  = (const float*)d_in[10];
    const float* W2r  = (const float*)d_in[11];
    const float* b2r  = (const float*)d_in[12];
    const float* att2 = (const float*)d_in[13];
    const float* bias2= (const float*)d_in[14];
    float* out = (float*)d_out;

    const int gemmBlocks = (N_NODES + GEMM_TM - 1) / GEMM_TM; // 1563
    const int edgeBlocks = (N_EDGES + 255) / 256;             // 6250
    const int nodeBlocks = (N_NODES + 255) / 256;             // 391
    const int nodeWarpBlocks = (N_NODES * 32 + 255) / 256;    // 12500
    const int GEMM_SMEM = (4096 + 16384) * 4;                 // 80KB

    cudaFuncSetAttribute((const void*)gemm_fused,
                         cudaFuncAttributeMaxDynamicSharedMemorySize, GEMM_SMEM);

    // gemm_fused kept as 4th launch so ncu (-s 5 -c 1) profiles it.
    csr_zero<<<nodeBlocks, 256>>>();
    csr_hist<<<edgeBlocks, 256>>>(dst);
    csr_scan1<<<N_SCAN_BLOCKS, SCAN_BLK>>>();
    gemm_fused<<<gemmBlocks, 256, GEMM_SMEM>>>(x, W1l, b1l, W1r, b1r);
    csr_scan2<<<1, 256>>>();
    csr_scan3<<<nodeBlocks, 256>>>();
    csr_scatter<<<edgeBlocks, 256>>>(src, dst);
    layer1_csr<<<nodeWarpBlocks, 256>>>(att1, bias1, W2l, b2l, W2r, b2r);
    layer2_csr<<<nodeWarpBlocks, 256>>>(att2, bias2, out);
}

// round 11
// speedup vs baseline: 2.7619x; 1.1084x over previous
#include <cuda_runtime.h>
#include <cstdint>

#define N_NODES 100000
#define N_EDGES 1600000
#define N_FEAT  165
#define HIDDEN  128
#define NEG_SLOPE 0.2f
#define SCAN_BLK 512
#define N_SCAN_BLOCKS ((N_NODES + SCAN_BLK - 1) / SCAN_BLK)   // 196
#define KPAD 176          // N_FEAT padded to 11 chunks of 16
#define KCHUNK 16
#define NCHUNKS 11

// ---------------- scratch (static __device__ arrays; no allocation) -------
__device__ float g_xl[(size_t)N_NODES * HIDDEN];
__device__ float g_xr[(size_t)N_NODES * HIDDEN];
__device__ float g_hl[N_NODES * 2];
__device__ float g_hr[N_NODES * 2];
__device__ int   g_cnt[N_NODES];
__device__ int   g_rowstart[N_NODES + 1];
__device__ int   g_cursor[N_NODES];
__device__ int   g_blocksum[N_SCAN_BLOCKS];
__device__ int   g_csrsrc[N_EDGES];
// tf32 split planes
__device__ float g_xhi[(size_t)N_NODES * KPAD];
__device__ float g_xlo[(size_t)N_NODES * KPAD];
__device__ float g_whi[KPAD * 256];
__device__ float g_wlo[KPAD * 256];

// ---------------- helpers ----------------
__device__ __forceinline__ float warpSum(float v) {
    #pragma unroll
    for (int o = 16; o > 0; o >>= 1) v += __shfl_xor_sync(0xffffffffu, v, o);
    return v;
}

__device__ __forceinline__ void warpSum2(float& a, float& b) {
    #pragma unroll
    for (int o = 16; o > 0; o >>= 1) {
        a += __shfl_xor_sync(0xffffffffu, a, o);
        b += __shfl_xor_sync(0xffffffffu, b, o);
    }
}

__device__ __forceinline__ void warpSum4(float& a, float& b, float& c, float& d) {
    #pragma unroll
    for (int o = 16; o > 0; o >>= 1) {
        a += __shfl_xor_sync(0xffffffffu, a, o);
        b += __shfl_xor_sync(0xffffffffu, b, o);
        c += __shfl_xor_sync(0xffffffffu, c, o);
        d += __shfl_xor_sync(0xffffffffu, d, o);
    }
}

__device__ __forceinline__ float lrelu(float v) {
    return v > 0.f ? v : NEG_SLOPE * v;
}

__device__ __forceinline__ float dot_lrelu(float4 a, float4 b, float4 t) {
    return lrelu(a.x + b.x) * t.x + lrelu(a.y + b.y) * t.y
         + lrelu(a.z + b.z) * t.z + lrelu(a.w + b.w) * t.w;
}

__device__ __forceinline__ uint32_t s2u(const void* p) {
    return (uint32_t)__cvta_generic_to_shared(p);
}
#define CPA16(d, s) asm volatile("cp.async.cg.shared.global [%0], [%1], 16;" :: "r"(d), "l"(s))
#define CP_COMMIT() asm volatile("cp.async.commit_group;" ::: "memory")
#define CP_WAIT1()  asm volatile("cp.async.wait_group 1;" ::: "memory")
#define CP_WAIT0()  asm volatile("cp.async.wait_group 0;" ::: "memory")

#define CVT_TF32(u, f) asm("cvt.rna.tf32.f32 %0, %1;" : "=r"(u) : "f"(f))

// D += A(tf32) * B(tf32);  D,A 4 regs, B 2 regs  (m16n8k8)
#define MMA_TF32(D, A, b0, b1) \
    asm volatile("mma.sync.aligned.m16n8k8.row.col.f32.tf32.tf32.f32 " \
        "{%0,%1,%2,%3}, {%4,%5,%6,%7}, {%8,%9}, {%0,%1,%2,%3};" \
        : "+f"((D)[0]), "+f"((D)[1]), "+f"((D)[2]), "+f"((D)[3]) \
        : "r"((A)[0]), "r"((A)[1]), "r"((A)[2]), "r"((A)[3]), "r"(b0), "r"(b1))

// ================= tf32 hi/lo split =================
__global__ void split_w(const float* __restrict__ W1l, const float* __restrict__ W1r) {
    int i = blockIdx.x * blockDim.x + threadIdx.x;
    if (i >= KPAD * 256) return;
    int k = i >> 8, n = i & 255;
    float v = 0.f;
    if (k < N_FEAT) v = (n < 128) ? W1l[k * HIDDEN + n] : W1r[k * HIDDEN + (n - 128)];
    uint32_t hi; CVT_TF32(hi, v);
    float lof = v - __uint_as_float(hi);
    uint32_t lo; CVT_TF32(lo, lof);
    g_whi[i] = __uint_as_float(hi);
    g_wlo[i] = __uint_as_float(lo);
}

__global__ void __launch_bounds__(192) split_x(const float* __restrict__ X) {
    int r = blockIdx.x;
    int k = threadIdx.x;
    if (k >= KPAD) return;
    float v = (k < N_FEAT) ? X[(size_t)r * N_FEAT + k] : 0.f;
    uint32_t hi; CVT_TF32(hi, v);
    float lof = v - __uint_as_float(hi);
    uint32_t lo; CVT_TF32(lo, lof);
    g_xhi[(size_t)r * KPAD + k] = __uint_as_float(hi);
    g_xlo[(size_t)r * KPAD + k] = __uint_as_float(lo);
}

// ================= CSR build =================
__global__ void csr_zero() {
    int i = blockIdx.x * blockDim.x + threadIdx.x;
    if (i < N_NODES) g_cnt[i] = 0;
}

__global__ void csr_hist(const int* __restrict__ dst) {
    int e = blockIdx.x * blockDim.x + threadIdx.x;
    if (e < N_EDGES) atomicAdd(&g_cnt[dst[e]], 1);
}

__global__ void __launch_bounds__(SCAN_BLK) csr_scan1() {
    __shared__ int sh[SCAN_BLK];
    int t = threadIdx.x;
    int i = blockIdx.x * SCAN_BLK + t;
    int v = (i < N_NODES) ? g_cnt[i] : 0;
    sh[t] = v;
    __syncthreads();
    #pragma unroll
    for (int off = 1; off < SCAN_BLK; off <<= 1) {
        int add = (t >= off) ? sh[t - off] : 0;
        __syncthreads();
        sh[t] += add;
        __syncthreads();
    }
    if (i < N_NODES) g_rowstart[i] = sh[t] - v;
    if (t == SCAN_BLK - 1) g_blocksum[blockIdx.x] = sh[t];
}

__global__ void __launch_bounds__(256) csr_scan2() {
    __shared__ int sh[256];
    int t = threadIdx.x;
    int v = (t < N_SCAN_BLOCKS) ? g_blocksum[t] : 0;
    sh[t] = v;
    __syncthreads();
    #pragma unroll
    for (int off = 1; off < 256; off <<= 1) {
        int add = (t >= off) ? sh[t - off] : 0;
        __syncthreads();
        sh[t] += add;
        __syncthreads();
    }
    if (t < N_SCAN_BLOCKS) g_blocksum[t] = sh[t] - v;
}

__global__ void csr_scan3() {
    int i = blockIdx.x * blockDim.x + threadIdx.x;
    if (i < N_NODES) {
        int rs = g_rowstart[i] + g_blocksum[i / SCAN_BLK];
        g_rowstart[i] = rs;
        g_cursor[i] = rs;
    }
    if (i == 0) g_rowstart[N_NODES] = N_EDGES;
}

__global__ void csr_scatter(const int* __restrict__ src, const int* __restrict__ dst) {
    int e = blockIdx.x * blockDim.x + threadIdx.x;
    if (e < N_EDGES) {
        int pos = atomicAdd(&g_cursor[dst[e]], 1);
        g_csrsrc[pos] = src[e];
    }
}

// ================= 3xTF32 tensor GEMM: [Yl|Yr] = X @ [W1l|W1r] + b =========
// Block 64x256, 256 thr, warp grid 2x4 (warp tile 32x64), cp.async 2-stage.
// Smem strides: X rows 20 floats, W rows 264 floats (conflict-free frags).
// Smem: X 2stg*2pl*64*20 + W 2*2*16*264 = 5120 + 16896 floats = 88064 B.
__global__ void __launch_bounds__(256, 2) gemm_mma(const float* __restrict__ b1l,
                                                   const float* __restrict__ b1r) {
    extern __shared__ float dsm[];
    float* XS = dsm;            // [stg][pl][64][20]
    float* WS = dsm + 5120;     // [stg][pl][16][264]

    const int tid = threadIdx.x;
    const int wid = tid >> 5;
    const int lane = tid & 31;
    const int g   = lane >> 2;   // 0..7
    const int tig = lane & 3;    // 0..3
    const int wm = wid >> 2;     // 0..1
    const int wn = wid & 3;      // 0..3
    const int row0 = blockIdx.x * 64;

    auto xs_pl = [&](int stg, int pl) { return XS + (stg * 2 + pl) * 1280; };
    auto ws_pl = [&](int stg, int pl) { return WS + (stg * 2 + pl) * 4224; };

    auto load_chunk = [&](int c, int stg) {
        int k0 = c * KCHUNK;
        // X: thread t -> row m=t>>2, 4-float group kq=(t&3)*4; rows 16B-aligned (KPAD*4=704)
        int m = tid >> 2, kq = (tid & 3) * 4;
        int gr = row0 + m;
        if (gr < N_NODES) {
            CPA16(s2u(xs_pl(stg, 0) + m * 20 + kq), g_xhi + (size_t)gr * KPAD + k0 + kq);
            CPA16(s2u(xs_pl(stg, 1) + m * 20 + kq), g_xlo + (size_t)gr * KPAD + k0 + kq);
        }
        // W: 16 rows x 256 cols per plane = 1024 16B-lines; 4 iters
        #pragma unroll
        for (int i = 0; i < 4; i++) {
            int L = tid + i * 256;
            int k = L >> 6;              // 0..15
            int nq = (L & 63) * 4;       // 0..252
            CPA16(s2u(ws_pl(stg, 0) + k * 264 + nq), g_whi + (k0 + k) * 256 + nq);
            CPA16(s2u(ws_pl(stg, 1) + k * 264 + nq), g_wlo + (k0 + k) * 256 + nq);
        }
    };

    float d[2][8][4];
    #pragma unroll
    for (int i = 0; i < 2; i++)
        #pragma unroll
        for (int j = 0; j < 8; j++)
            #pragma unroll
            for (int q = 0; q < 4; q++) d[i][j][q] = 0.f;

    load_chunk(0, 0);
    CP_COMMIT();

    for (int c = 0; c < NCHUNKS; c++) {
        int stg = c & 1;
        if (c + 1 < NCHUNKS) {
            load_chunk(c + 1, (c + 1) & 1);
            CP_COMMIT();
            CP_WAIT1();
        } else {
            CP_WAIT0();
        }
        __syncthreads();

        const float* xhi = xs_pl(stg, 0);
        const float* xlo = xs_pl(stg, 1);
        const float* whi = ws_pl(stg, 0);
        const float* wlo = ws_pl(stg, 1);

        #pragma unroll
        for (int k8 = 0; k8 < 2; k8++) {
            int kb = k8 * 8;
            uint32_t ahi[2][4], alo[2][4];
            #pragma unroll
            for (int i = 0; i < 2; i++) {
                int rb = wm * 32 + i * 16;
                ahi[i][0] = __float_as_uint(xhi[(rb + g)     * 20 + kb + tig]);
                ahi[i][1] = __float_as_uint(xhi[(rb + g + 8) * 20 + kb + tig]);
                ahi[i][2] = __float_as_uint(xhi[(rb + g)     * 20 + kb + tig + 4]);
                ahi[i][3] = __float_as_uint(xhi[(rb + g + 8) * 20 + kb + tig + 4]);
                alo[i][0] = __float_as_uint(xlo[(rb + g)     * 20 + kb + tig]);
                alo[i][1] = __float_as_uint(xlo[(rb + g + 8) * 20 + kb + tig]);
                alo[i][2] = __float_as_uint(xlo[(rb + g)     * 20 + kb + tig + 4]);
                alo[i][3] = __float_as_uint(xlo[(rb + g + 8) * 20 + kb + tig + 4]);
            }
            #pragma unroll
            for (int j = 0; j < 8; j++) {
                int nb = wn * 64 + j * 8;
                uint32_t bh0 = __float_as_uint(whi[(kb + tig)     * 264 + nb + g]);
                uint32_t bh1 = __float_as_uint(whi[(kb + tig + 4) * 264 + nb + g]);
                uint32_t bl0 = __float_as_uint(wlo[(kb + tig)     * 264 + nb + g]);
                uint32_t bl1 = __float_as_uint(wlo[(kb + tig + 4) * 264 + nb + g]);
                #pragma unroll
                for (int i = 0; i < 2; i++) {
                    MMA_TF32(d[i][j], ahi[i], bh0, bh1);   // hi*hi
                    MMA_TF32(d[i][j], ahi[i], bl0, bl1);   // hi*lo
                    MMA_TF32(d[i][j], alo[i], bh0, bh1);   // lo*hi
                }
            }
        }
        __syncthreads();
    }

    // epilogue: D + bias -> g_xl / g_xr
    #pragma unroll
    for (int i = 0; i < 2; i++) {
        int r0 = row0 + wm * 32 + i * 16 + g;
        int r1 = r0 + 8;
        #pragma unroll
        for (int j = 0; j < 8; j++) {
            int col = wn * 64 + j * 8 + tig * 2;
            if (col < 128) {
                float bb0 = __ldg(&b1l[col]), bb1 = __ldg(&b1l[col + 1]);
                if (r0 < N_NODES) {
                    float2 v = make_float2(d[i][j][0] + bb0, d[i][j][1] + bb1);
                    *(float2*)(g_xl + (size_t)r0 * HIDDEN + col) = v;
                }
                if (r1 < N_NODES) {
                    float2 v = make_float2(d[i][j][2] + bb0, d[i][j][3] + bb1);
                    *(float2*)(g_xl + (size_t)r1 * HIDDEN + col) = v;
                }
            } else {
                int c2 = col - 128;
                float bb0 = __ldg(&b1r[c2]), bb1 = __ldg(&b1r[c2 + 1]);
                if (r0 < N_NODES) {
                    float2 v = make_float2(d[i][j][0] + bb0, d[i][j][1] + bb1);
                    *(float2*)(g_xr + (size_t)r0 * HIDDEN + c2) = v;
                }
                if (r1 < N_NODES) {
                    float2 v = make_float2(d[i][j][2] + bb0, d[i][j][3] + bb1);
                    *(float2*)(g_xr + (size_t)r1 * HIDDEN + c2) = v;
                }
            }
        }
    }
}

// ================= layer 1: warp-per-node, 4-wide edge unroll ==============
__global__ void __launch_bounds__(256) layer1_csr(const float* __restrict__ att,
                                                  const float* __restrict__ bias1,
                                                  const float* __restrict__ W2l,
                                                  const float* __restrict__ b2l,
                                                  const float* __restrict__ W2r,
                                                  const float* __restrict__ b2r) {
    int d = (blockIdx.x * blockDim.x + threadIdx.x) >> 5;
    int lane = threadIdx.x & 31;
    if (d >= N_NODES) return;

    float4 xr4  = ((const float4*)(g_xr + (size_t)d * HIDDEN))[lane];
    float4 att4 = __ldg(&((const float4*)att)[lane]);

    float4 xls = ((const float4*)(g_xl + (size_t)d * HIDDEN))[lane];
    float p = warpSum(dot_lrelu(xls, xr4, att4));
    float w = __expf(p);
    float wsum = w;
    float4 acc = make_float4(w * xls.x, w * xls.y, w * xls.z, w * xls.w);

    int j  = g_rowstart[d];
    int re = g_rowstart[d + 1];

    for (; j + 3 < re; j += 4) {
        int s0 = g_csrsrc[j],     s1 = g_csrsrc[j + 1];
        int s2 = g_csrsrc[j + 2], s3 = g_csrsrc[j + 3];
        float4 a0 = ((const float4*)(g_xl + (size_t)s0 * HIDDEN))[lane];
        float4 a1 = ((const float4*)(g_xl + (size_t)s1 * HIDDEN))[lane];
        float4 a2 = ((const float4*)(g_xl + (size_t)s2 * HIDDEN))[lane];
        float4 a3 = ((const float4*)(g_xl + (size_t)s3 * HIDDEN))[lane];
        float p0 = dot_lrelu(a0, xr4, att4);
        float p1 = dot_lrelu(a1, xr4, att4);
        float p2 = dot_lrelu(a2, xr4, att4);
        float p3 = dot_lrelu(a3, xr4, att4);
        warpSum4(p0, p1, p2, p3);
        float w0 = __expf(p0), w1 = __expf(p1);
        float w2 = __expf(p2), w3 = __expf(p3);
        wsum += (w0 + w1) + (w2 + w3);
        acc.x += w0 * a0.x + w1 * a1.x + w2 * a2.x + w3 * a3.x;
        acc.y += w0 * a0.y + w1 * a1.y + w2 * a2.y + w3 * a3.y;
        acc.z += w0 * a0.z + w1 * a1.z + w2 * a2.z + w3 * a3.z;
        acc.w += w0 * a0.w + w1 * a1.w + w2 * a2.w + w3 * a3.w;
    }
    for (; j + 1 < re; j += 2) {
        int s0 = g_csrsrc[j], s1 = g_csrsrc[j + 1];
        float4 a0 = ((const float4*)(g_xl + (size_t)s0 * HIDDEN))[lane];
        float4 a1 = ((const float4*)(g_xl + (size_t)s1 * HIDDEN))[lane];
        float p0 = dot_lrelu(a0, xr4, att4);
        float p1 = dot_lrelu(a1, xr4, att4);
        warpSum2(p0, p1);
        float w0 = __expf(p0), w1 = __expf(p1);
        wsum += w0 + w1;
        acc.x += w0 * a0.x + w1 * a1.x;
        acc.y += w0 * a0.y + w1 * a1.y;
        acc.z += w0 * a0.z + w1 * a1.z;
        acc.w += w0 * a0.w + w1 * a1.w;
    }
    if (j < re) {
        int s0 = g_csrsrc[j];
        float4 a0 = ((const float4*)(g_xl + (size_t)s0 * HIDDEN))[lane];
        float w0 = __expf(warpSum(dot_lrelu(a0, xr4, att4)));
        wsum += w0;
        acc.x += w0 * a0.x; acc.y += w0 * a0.y;
        acc.z += w0 * a0.z; acc.w += w0 * a0.w;
    }

    float inv = __fdividef(1.f, wsum);
    float4 b4 = __ldg(&((const float4*)bias1)[lane]);
    float h0 = acc.x * inv + b4.x;  h0 = h0 > 0.f ? h0 : 0.f;
    float h1 = acc.y * inv + b4.y;  h1 = h1 > 0.f ? h1 : 0.f;
    float h2 = acc.z * inv + b4.z;  h2 = h2 > 0.f ? h2 : 0.f;
    float h3 = acc.w * inv + b4.w;  h3 = h3 > 0.f ? h3 : 0.f;

    float4 wl0 = __ldg(&((const float4*)W2l)[2 * lane]);
    float4 wl1 = __ldg(&((const float4*)W2l)[2 * lane + 1]);
    float4 wr0 = __ldg(&((const float4*)W2r)[2 * lane]);
    float4 wr1 = __ldg(&((const float4*)W2r)[2 * lane + 1]);

    float s0 = h0 * wl0.x + h1 * wl0.z + h2 * wl1.x + h3 * wl1.z;
    float s1 = h0 * wl0.y + h1 * wl0.w + h2 * wl1.y + h3 * wl1.w;
    float s2 = h0 * wr0.x + h1 * wr0.z + h2 * wr1.x + h3 * wr1.z;
    float s3 = h0 * wr0.y + h1 * wr0.w + h2 * wr1.y + h3 * wr1.w;
    warpSum4(s0, s1, s2, s3);

    if (lane == 0) {
        g_hl[2 * d + 0] = s0 + __ldg(&b2l[0]);
        g_hl[2 * d + 1] = s1 + __ldg(&b2l[1]);
        g_hr[2 * d + 0] = s2 + __ldg(&b2r[0]);
        g_hr[2 * d + 1] = s3 + __ldg(&b2r[1]);
    }
}

// ================= layer 2: warp-per-node, lanes stride edges ==============
__global__ void __launch_bounds__(256) layer2_csr(const float* __restrict__ att2,
                                                  const float* __restrict__ bias2,
                                                  float* __restrict__ out) {
    int d = (blockIdx.x * blockDim.x + threadIdx.x) >> 5;
    int lane = threadIdx.x & 31;
    if (d >= N_NODES) return;

    float a20 = __ldg(&att2[0]);
    float a21 = __ldg(&att2[1]);
    float2 hr2 = *(const float2*)(g_hr + 2 * d);

    float den = 0.f, n0 = 0.f, n1 = 0.f;

    if (lane == 0) {
        float2 hls = *(const float2*)(g_hl + 2 * d);
        float sc = lrelu(hls.x + hr2.x) * a20 + lrelu(hls.y + hr2.y) * a21;
        float w = __expf(sc);
        den = w; n0 = w * hls.x; n1 = w * hls.y;
    }

    int rs = g_rowstart[d];
    int re = g_rowstart[d + 1];
    for (int j = rs + lane; j < re; j += 32) {
        int s = g_csrsrc[j];
        float2 hl = *(const float2*)(g_hl + 2 * s);
        float sc = lrelu(hl.x + hr2.x) * a20 + lrelu(hl.y + hr2.y) * a21;
        float w = __expf(sc);
        den += w; n0 += w * hl.x; n1 += w * hl.y;
    }

    warpSum2(n0, n1);
    den = warpSum(den);

    if (lane == 0) {
        float inv = __fdividef(1.f, den);
        out[2 * d + 0] = n0 * inv + __ldg(&bias2[0]);
        out[2 * d + 1] = n1 * inv + __ldg(&bias2[1]);
    }
}

// ---------------- launch ----------------
extern "C" void kernel_launch(void* const* d_in, const int* in_sizes, int n_in,
                              void* d_out, int out_size) {
    const float* x    = (const float*)d_in[0];
    const int*   src  = (const int*)  d_in[1];
    const int*   dst  = (const int*)  d_in[2];
    const float* W1l  = (const float*)d_in[3];
    const float* b1l  = (const float*)d_in[4];
    const float* W1r  = (const float*)d_in[5];
    const float* b1r  = (const float*)d_in[6];
    const float* att1 = (const float*)d_in[7];
    const float* bias1= (const float*)d_in[8];
    const float* W2l  = (const float*)d_in[9];
    const float* b2l  = (const float*)d_in[10];
    const float* W2r  = (const float*)d_in[11];
    const float* b2r  = (const float*)d_in[12];
    const float* att2 = (const float*)d_in[13];
    const float* bias2= (const float*)d_in[14];
    float* out = (float*)d_out;

    const int gemmBlocks = (N_NODES + 63) / 64;               // 1563
    const int edgeBlocks = (N_EDGES + 255) / 256;             // 6250
    const int nodeBlocks = (N_NODES + 255) / 256;             // 391
    const int nodeWarpBlocks = (N_NODES * 32 + 255) / 256;    // 12500
    const int GEMM_SMEM = (5120 + 16896) * 4;                 // 88064 B

    cudaFuncSetAttribute((const void*)gemm_mma,
                         cudaFuncAttributeMaxDynamicSharedMemorySize, GEMM_SMEM);

    // gemm_mma kept as 4th launch so ncu (-s 5 -c 1) profiles it.
    split_w<<<(KPAD * 256 + 255) / 256, 256>>>(W1l, W1r);
    split_x<<<N_NODES, 192>>>(x);
    csr_zero<<<nodeBlocks, 256>>>();
    gemm_mma<<<gemmBlocks, 256, GEMM_SMEM>>>(b1l, b1r);
    csr_hist<<<edgeBlocks, 256>>>(dst);
    csr_scan1<<<N_SCAN_BLOCKS, SCAN_BLK>>>();
    csr_scan2<<<1, 256>>>();
    csr_scan3<<<nodeBlocks, 256>>>();
    csr_scatter<<<edgeBlocks, 256>>>(src, dst);
    layer1_csr<<<nodeWarpBlocks, 256>>>(att1, bias1, W2l, b2l, W2r, b2r);
    layer2_csr<<<nodeWarpBlocks, 256>>>(att2, bias2, out);
}

// round 12
// speedup vs baseline: 3.2328x; 1.1705x over previous
#include <cuda_runtime.h>
#include <cstdint>

#define N_NODES 100000
#define N_EDGES 1600000
#define N_FEAT  165
#define HIDDEN  128
#define NEG_SLOPE 0.2f
#define SCAN_BLK 512
#define N_SCAN_BLOCKS ((N_NODES + SCAN_BLK - 1) / SCAN_BLK)   // 196
#define KPAD 176          // K padded to 11 chunks of 16 (W planes only)
#define KCHUNK 16
#define NCHUNKS 11

// ---------------- scratch (static __device__ arrays; no allocation) -------
__device__ float g_xl[(size_t)N_NODES * HIDDEN];
__device__ float g_xr[(size_t)N_NODES * HIDDEN];
__device__ float g_hl[N_NODES * 2];
__device__ float g_hr[N_NODES * 2];
__device__ int   g_cnt[N_NODES];
__device__ int   g_rowstart[N_NODES + 1];
__device__ int   g_cursor[N_NODES];
__device__ int   g_blocksum[N_SCAN_BLOCKS];
__device__ int   g_csrsrc[N_EDGES];
// tf32 split planes for W only (X split happens in-register in the GEMM)
__device__ float g_whi[KPAD * 256];
__device__ float g_wlo[KPAD * 256];

// ---------------- helpers ----------------
__device__ __forceinline__ float warpSum(float v) {
    #pragma unroll
    for (int o = 16; o > 0; o >>= 1) v += __shfl_xor_sync(0xffffffffu, v, o);
    return v;
}

__device__ __forceinline__ void warpSum2(float& a, float& b) {
    #pragma unroll
    for (int o = 16; o > 0; o >>= 1) {
        a += __shfl_xor_sync(0xffffffffu, a, o);
        b += __shfl_xor_sync(0xffffffffu, b, o);
    }
}

__device__ __forceinline__ void warpSum4(float& a, float& b, float& c, float& d) {
    #pragma unroll
    for (int o = 16; o > 0; o >>= 1) {
        a += __shfl_xor_sync(0xffffffffu, a, o);
        b += __shfl_xor_sync(0xffffffffu, b, o);
        c += __shfl_xor_sync(0xffffffffu, c, o);
        d += __shfl_xor_sync(0xffffffffu, d, o);
    }
}

__device__ __forceinline__ float lrelu(float v) {
    return v > 0.f ? v : NEG_SLOPE * v;
}

__device__ __forceinline__ float dot_lrelu(float4 a, float4 b, float4 t) {
    return lrelu(a.x + b.x) * t.x + lrelu(a.y + b.y) * t.y
         + lrelu(a.z + b.z) * t.z + lrelu(a.w + b.w) * t.w;
}

__device__ __forceinline__ uint32_t s2u(const void* p) {
    return (uint32_t)__cvta_generic_to_shared(p);
}
#define CPA4(d, s)  asm volatile("cp.async.ca.shared.global [%0], [%1], 4;"  :: "r"(d), "l"(s))
#define CPA16(d, s) asm volatile("cp.async.cg.shared.global [%0], [%1], 16;" :: "r"(d), "l"(s))
#define CP_COMMIT() asm volatile("cp.async.commit_group;" ::: "memory")
#define CP_WAIT1()  asm volatile("cp.async.wait_group 1;" ::: "memory")
#define CP_WAIT0()  asm volatile("cp.async.wait_group 0;" ::: "memory")

#define CVT_TF32(u, f) asm("cvt.rna.tf32.f32 %0, %1;" : "=r"(u) : "f"(f))

// D += A(tf32) * B(tf32);  D,A 4 regs, B 2 regs  (m16n8k8)
#define MMA_TF32(D, A, b0, b1) \
    asm volatile("mma.sync.aligned.m16n8k8.row.col.f32.tf32.tf32.f32 " \
        "{%0,%1,%2,%3}, {%4,%5,%6,%7}, {%8,%9}, {%0,%1,%2,%3};" \
        : "+f"((D)[0]), "+f"((D)[1]), "+f"((D)[2]), "+f"((D)[3]) \
        : "r"((A)[0]), "r"((A)[1]), "r"((A)[2]), "r"((A)[3]), "r"(b0), "r"(b1))

// ================= tf32 hi/lo split for W =================
__global__ void split_w(const float* __restrict__ W1l, const float* __restrict__ W1r) {
    int i = blockIdx.x * blockDim.x + threadIdx.x;
    if (i >= KPAD * 256) return;
    int k = i >> 8, n = i & 255;
    float v = 0.f;
    if (k < N_FEAT) v = (n < 128) ? W1l[k * HIDDEN + n] : W1r[k * HIDDEN + (n - 128)];
    uint32_t hi; CVT_TF32(hi, v);
    float lof = v - __uint_as_float(hi);
    uint32_t lo; CVT_TF32(lo, lof);
    g_whi[i] = __uint_as_float(hi);
    g_wlo[i] = __uint_as_float(lo);
}

// ================= CSR build =================
__global__ void csr_zero() {
    int i = blockIdx.x * blockDim.x + threadIdx.x;
    if (i < N_NODES) g_cnt[i] = 0;
}

__global__ void csr_hist(const int* __restrict__ dst) {
    int e = blockIdx.x * blockDim.x + threadIdx.x;
    if (e < N_EDGES) atomicAdd(&g_cnt[dst[e]], 1);
}

__global__ void __launch_bounds__(SCAN_BLK) csr_scan1() {
    __shared__ int sh[SCAN_BLK];
    int t = threadIdx.x;
    int i = blockIdx.x * SCAN_BLK + t;
    int v = (i < N_NODES) ? g_cnt[i] : 0;
    sh[t] = v;
    __syncthreads();
    #pragma unroll
    for (int off = 1; off < SCAN_BLK; off <<= 1) {
        int add = (t >= off) ? sh[t - off] : 0;
        __syncthreads();
        sh[t] += add;
        __syncthreads();
    }
    if (i < N_NODES) g_rowstart[i] = sh[t] - v;
    if (t == SCAN_BLK - 1) g_blocksum[blockIdx.x] = sh[t];
}

__global__ void __launch_bounds__(256) csr_scan2() {
    __shared__ int sh[256];
    int t = threadIdx.x;
    int v = (t < N_SCAN_BLOCKS) ? g_blocksum[t] : 0;
    sh[t] = v;
    __syncthreads();
    #pragma unroll
    for (int off = 1; off < 256; off <<= 1) {
        int add = (t >= off) ? sh[t - off] : 0;
        __syncthreads();
        sh[t] += add;
        __syncthreads();
    }
    if (t < N_SCAN_BLOCKS) g_blocksum[t] = sh[t] - v;
}

__global__ void csr_scan3() {
    int i = blockIdx.x * blockDim.x + threadIdx.x;
    if (i < N_NODES) {
        int rs = g_rowstart[i] + g_blocksum[i / SCAN_BLK];
        g_rowstart[i] = rs;
        g_cursor[i] = rs;
    }
    if (i == 0) g_rowstart[N_NODES] = N_EDGES;
}

__global__ void csr_scatter(const int* __restrict__ src, const int* __restrict__ dst) {
    int e = blockIdx.x * blockDim.x + threadIdx.x;
    if (e < N_EDGES) {
        int pos = atomicAdd(&g_cursor[dst[e]], 1);
        g_csrsrc[pos] = src[e];
    }
}

// ================= 3xTF32 tensor GEMM: [Yl|Yr] = X @ [W1l|W1r] + b =========
// Block 64x256, 256 thr, warp grid 2x4, cp.async 2-stage.
// X kept fp32 in smem (single plane, stride 20); hi/lo split in registers.
// Smem: X 2*64*20 + W 2pl*2stg*16*264 = 2560 + 16896 floats = 77824 B.
__global__ void __launch_bounds__(256, 2) gemm_mma(const float* __restrict__ Xp,
                                                   const float* __restrict__ b1l,
                                                   const float* __restrict__ b1r) {
    extern __shared__ float dsm[];
    float* XS = dsm;            // [stg][64][20]
    float* WS = dsm + 2560;     // [stg][pl][16][264]

    const int tid = threadIdx.x;
    const int wid = tid >> 5;
    const int lane = tid & 31;
    const int g   = lane >> 2;   // 0..7
    const int tig = lane & 3;    // 0..3
    const int wm = wid >> 2;     // 0..1
    const int wn = wid & 3;      // 0..3
    const int row0 = blockIdx.x * 64;

    auto xs_s  = [&](int stg) { return XS + stg * 1280; };
    auto ws_pl = [&](int stg, int pl) { return WS + (stg * 2 + pl) * 4224; };

    auto load_chunk = [&](int c, int stg) {
        int k0 = c * KCHUNK;
        // X fp32: 64 rows x 16 k = 1024 elements, 4B cp.async each
        float* xbase = xs_s(stg);
        #pragma unroll
        for (int i = 0; i < 4; i++) {
            int lin = tid + i * 256;
            int m = lin >> 4, k = lin & 15;
            int gr = row0 + m, gk = k0 + k;
            float* dstp = xbase + m * 20 + k;
            if (gr < N_NODES && gk < N_FEAT)
                CPA4(s2u(dstp), Xp + (size_t)gr * N_FEAT + gk);
            else
                *dstp = 0.f;     // STS; disjoint from cp.async targets
        }
        // W planes: 16 rows x 256 cols each, 16B lines (zero-padded to KPAD)
        #pragma unroll
        for (int i = 0; i < 4; i++) {
            int L = tid + i * 256;
            int k = L >> 6;              // 0..15
            int nq = (L & 63) * 4;       // 0..252
            CPA16(s2u(ws_pl(stg, 0) + k * 264 + nq), g_whi + (k0 + k) * 256 + nq);
            CPA16(s2u(ws_pl(stg, 1) + k * 264 + nq), g_wlo + (k0 + k) * 256 + nq);
        }
    };

    float d[2][8][4];
    #pragma unroll
    for (int i = 0; i < 2; i++)
        #pragma unroll
        for (int j = 0; j < 8; j++)
            #pragma unroll
            for (int q = 0; q < 4; q++) d[i][j][q] = 0.f;

    load_chunk(0, 0);
    CP_COMMIT();

    for (int c = 0; c < NCHUNKS; c++) {
        int stg = c & 1;
        if (c + 1 < NCHUNKS) {
            load_chunk(c + 1, (c + 1) & 1);
            CP_COMMIT();
            CP_WAIT1();
        } else {
            CP_WAIT0();
        }
        __syncthreads();

        const float* xs  = xs_s(stg);
        const float* whi = ws_pl(stg, 0);
        const float* wlo = ws_pl(stg, 1);

        #pragma unroll
        for (int k8 = 0; k8 < 2; k8++) {
            int kb = k8 * 8;
            uint32_t ahi[2][4], alo[2][4];
            #pragma unroll
            for (int i = 0; i < 2; i++) {
                int rb = wm * 32 + i * 16;
                float xv[4];
                xv[0] = xs[(rb + g)     * 20 + kb + tig];
                xv[1] = xs[(rb + g + 8) * 20 + kb + tig];
                xv[2] = xs[(rb + g)     * 20 + kb + tig + 4];
                xv[3] = xs[(rb + g + 8) * 20 + kb + tig + 4];
                #pragma unroll
                for (int q = 0; q < 4; q++) {
                    CVT_TF32(ahi[i][q], xv[q]);
                    float lof = xv[q] - __uint_as_float(ahi[i][q]);
                    CVT_TF32(alo[i][q], lof);
                }
            }
            #pragma unroll
            for (int j = 0; j < 8; j++) {
                int nb = wn * 64 + j * 8;
                uint32_t bh0 = __float_as_uint(whi[(kb + tig)     * 264 + nb + g]);
                uint32_t bh1 = __float_as_uint(whi[(kb + tig + 4) * 264 + nb + g]);
                uint32_t bl0 = __float_as_uint(wlo[(kb + tig)     * 264 + nb + g]);
                uint32_t bl1 = __float_as_uint(wlo[(kb + tig + 4) * 264 + nb + g]);
                #pragma unroll
                for (int i = 0; i < 2; i++) {
                    MMA_TF32(d[i][j], ahi[i], bh0, bh1);   // hi*hi
                    MMA_TF32(d[i][j], ahi[i], bl0, bl1);   // hi*lo
                    MMA_TF32(d[i][j], alo[i], bh0, bh1);   // lo*hi
                }
            }
        }
        __syncthreads();
    }

    // epilogue: D + bias -> g_xl / g_xr
    #pragma unroll
    for (int i = 0; i < 2; i++) {
        int r0 = row0 + wm * 32 + i * 16 + g;
        int r1 = r0 + 8;
        #pragma unroll
        for (int j = 0; j < 8; j++) {
            int col = wn * 64 + j * 8 + tig * 2;
            if (col < 128) {
                float bb0 = __ldg(&b1l[col]), bb1 = __ldg(&b1l[col + 1]);
                if (r0 < N_NODES) {
                    float2 v = make_float2(d[i][j][0] + bb0, d[i][j][1] + bb1);
                    *(float2*)(g_xl + (size_t)r0 * HIDDEN + col) = v;
                }
                if (r1 < N_NODES) {
                    float2 v = make_float2(d[i][j][2] + bb0, d[i][j][3] + bb1);
                    *(float2*)(g_xl + (size_t)r1 * HIDDEN + col) = v;
                }
            } else {
                int c2 = col - 128;
                float bb0 = __ldg(&b1r[c2]), bb1 = __ldg(&b1r[c2 + 1]);
                if (r0 < N_NODES) {
                    float2 v = make_float2(d[i][j][0] + bb0, d[i][j][1] + bb1);
                    *(float2*)(g_xr + (size_t)r0 * HIDDEN + c2) = v;
                }
                if (r1 < N_NODES) {
                    float2 v = make_float2(d[i][j][2] + bb0, d[i][j][3] + bb1);
                    *(float2*)(g_xr + (size_t)r1 * HIDDEN + c2) = v;
                }
            }
        }
    }
}

// ================= layer 1: warp-per-node, 4-wide edge unroll ==============
__global__ void __launch_bounds__(256) layer1_csr(const float* __restrict__ att,
                                                  const float* __restrict__ bias1,
                                                  const float* __restrict__ W2l,
                                                  const float* __restrict__ b2l,
                                                  const float* __restrict__ W2r,
                                                  const float* __restrict__ b2r) {
    int d = (blockIdx.x * blockDim.x + threadIdx.x) >> 5;
    int lane = threadIdx.x & 31;
    if (d >= N_NODES) return;

    float4 xr4  = ((const float4*)(g_xr + (size_t)d * HIDDEN))[lane];
    float4 att4 = __ldg(&((const float4*)att)[lane]);

    float4 xls = ((const float4*)(g_xl + (size_t)d * HIDDEN))[lane];
    float p = warpSum(dot_lrelu(xls, xr4, att4));
    float w = __expf(p);
    float wsum = w;
    float4 acc = make_float4(w * xls.x, w * xls.y, w * xls.z, w * xls.w);

    int j  = g_rowstart[d];
    int re = g_rowstart[d + 1];

    for (; j + 3 < re; j += 4) {
        int s0 = g_csrsrc[j],     s1 = g_csrsrc[j + 1];
        int s2 = g_csrsrc[j + 2], s3 = g_csrsrc[j + 3];
        float4 a0 = ((const float4*)(g_xl + (size_t)s0 * HIDDEN))[lane];
        float4 a1 = ((const float4*)(g_xl + (size_t)s1 * HIDDEN))[lane];
        float4 a2 = ((const float4*)(g_xl + (size_t)s2 * HIDDEN))[lane];
        float4 a3 = ((const float4*)(g_xl + (size_t)s3 * HIDDEN))[lane];
        float p0 = dot_lrelu(a0, xr4, att4);
        float p1 = dot_lrelu(a1, xr4, att4);
        float p2 = dot_lrelu(a2, xr4, att4);
        float p3 = dot_lrelu(a3, xr4, att4);
        warpSum4(p0, p1, p2, p3);
        float w0 = __expf(p0), w1 = __expf(p1);
        float w2 = __expf(p2), w3 = __expf(p3);
        wsum += (w0 + w1) + (w2 + w3);
        acc.x += w0 * a0.x + w1 * a1.x + w2 * a2.x + w3 * a3.x;
        acc.y += w0 * a0.y + w1 * a1.y + w2 * a2.y + w3 * a3.y;
        acc.z += w0 * a0.z + w1 * a1.z + w2 * a2.z + w3 * a3.z;
        acc.w += w0 * a0.w + w1 * a1.w + w2 * a2.w + w3 * a3.w;
    }
    for (; j + 1 < re; j += 2) {
        int s0 = g_csrsrc[j], s1 = g_csrsrc[j + 1];
        float4 a0 = ((const float4*)(g_xl + (size_t)s0 * HIDDEN))[lane];
        float4 a1 = ((const float4*)(g_xl + (size_t)s1 * HIDDEN))[lane];
        float p0 = dot_lrelu(a0, xr4, att4);
        float p1 = dot_lrelu(a1, xr4, att4);
        warpSum2(p0, p1);
        float w0 = __expf(p0), w1 = __expf(p1);
        wsum += w0 + w1;
        acc.x += w0 * a0.x + w1 * a1.x;
        acc.y += w0 * a0.y + w1 * a1.y;
        acc.z += w0 * a0.z + w1 * a1.z;
        acc.w += w0 * a0.w + w1 * a1.w;
    }
    if (j < re) {
        int s0 = g_csrsrc[j];
        float4 a0 = ((const float4*)(g_xl + (size_t)s0 * HIDDEN))[lane];
        float w0 = __expf(warpSum(dot_lrelu(a0, xr4, att4)));
        wsum += w0;
        acc.x += w0 * a0.x; acc.y += w0 * a0.y;
        acc.z += w0 * a0.z; acc.w += w0 * a0.w;
    }

    float inv = __fdividef(1.f, wsum);
    float4 b4 = __ldg(&((const float4*)bias1)[lane]);
    float h0 = acc.x * inv + b4.x;  h0 = h0 > 0.f ? h0 : 0.f;
    float h1 = acc.y * inv + b4.y;  h1 = h1 > 0.f ? h1 : 0.f;
    float h2 = acc.z * inv + b4.z;  h2 = h2 > 0.f ? h2 : 0.f;
    float h3 = acc.w * inv + b4.w;  h3 = h3 > 0.f ? h3 : 0.f;

    float4 wl0 = __ldg(&((const float4*)W2l)[2 * lane]);
    float4 wl1 = __ldg(&((const float4*)W2l)[2 * lane + 1]);
    float4 wr0 = __ldg(&((const float4*)W2r)[2 * lane]);
    float4 wr1 = __ldg(&((const float4*)W2r)[2 * lane + 1]);

    float s0 = h0 * wl0.x + h1 * wl0.z + h2 * wl1.x + h3 * wl1.z;
    float s1 = h0 * wl0.y + h1 * wl0.w + h2 * wl1.y + h3 * wl1.w;
    float s2 = h0 * wr0.x + h1 * wr0.z + h2 * wr1.x + h3 * wr1.z;
    float s3 = h0 * wr0.y + h1 * wr0.w + h2 * wr1.y + h3 * wr1.w;
    warpSum4(s0, s1, s2, s3);

    if (lane == 0) {
        g_hl[2 * d + 0] = s0 + __ldg(&b2l[0]);
        g_hl[2 * d + 1] = s1 + __ldg(&b2l[1]);
        g_hr[2 * d + 0] = s2 + __ldg(&b2r[0]);
        g_hr[2 * d + 1] = s3 + __ldg(&b2r[1]);
    }
}

// ================= layer 2: warp-per-node, lanes stride edges ==============
__global__ void __launch_bounds__(256) layer2_csr(const float* __restrict__ att2,
                                                  const float* __restrict__ bias2,
                                                  float* __restrict__ out) {
    int d = (blockIdx.x * blockDim.x + threadIdx.x) >> 5;
    int lane = threadIdx.x & 31;
    if (d >= N_NODES) return;

    float a20 = __ldg(&att2[0]);
    float a21 = __ldg(&att2[1]);
    float2 hr2 = *(const float2*)(g_hr + 2 * d);

    float den = 0.f, n0 = 0.f, n1 = 0.f;

    if (lane == 0) {
        float2 hls = *(const float2*)(g_hl + 2 * d);
        float sc = lrelu(hls.x + hr2.x) * a20 + lrelu(hls.y + hr2.y) * a21;
        float w = __expf(sc);
        den = w; n0 = w * hls.x; n1 = w * hls.y;
    }

    int rs = g_rowstart[d];
    int re = g_rowstart[d + 1];
    for (int j = rs + lane; j < re; j += 32) {
        int s = g_csrsrc[j];
        float2 hl = *(const float2*)(g_hl + 2 * s);
        float sc = lrelu(hl.x + hr2.x) * a20 + lrelu(hl.y + hr2.y) * a21;
        float w = __expf(sc);
        den += w; n0 += w * hl.x; n1 += w * hl.y;
    }

    warpSum2(n0, n1);
    den = warpSum(den);

    if (lane == 0) {
        float inv = __fdividef(1.f, den);
        out[2 * d + 0] = n0 * inv + __ldg(&bias2[0]);
        out[2 * d + 1] = n1 * inv + __ldg(&bias2[1]);
    }
}

// ---------------- launch ----------------
extern "C" void kernel_launch(void* const* d_in, const int* in_sizes, int n_in,
                              void* d_out, int out_size) {
    const float* x    = (const float*)d_in[0];
    const int*   src  = (const int*)  d_in[1];
    const int*   dst  = (const int*)  d_in[2];
    const float* W1l  = (const float*)d_in[3];
    const float* b1l  = (const float*)d_in[4];
    const float* W1r  = (const float*)d_in[5];
    const float* b1r  = (const float*)d_in[6];
    const float* att1 = (const float*)d_in[7];
    const float* bias1= (const float*)d_in[8];
    const float* W2l  = (const float*)d_in[9];
    const float* b2l  = (const float*)d_in[10];
    const float* W2r  = (const float*)d_in[11];
    const float* b2r  = (const float*)d_in[12];
    const float* att2 = (const float*)d_in[13];
    const float* bias2= (const float*)d_in[14];
    float* out = (float*)d_out;

    const int gemmBlocks = (N_NODES + 63) / 64;               // 1563
    const int edgeBlocks = (N_EDGES + 255) / 256;             // 6250
    const int nodeBlocks = (N_NODES + 255) / 256;             // 391
    const int nodeWarpBlocks = (N_NODES * 32 + 255) / 256;    // 12500
    const int GEMM_SMEM = (2560 + 16896) * 4;                 // 77824 B

    cudaFuncSetAttribute((const void*)gemm_mma,
                         cudaFuncAttributeMaxDynamicSharedMemorySize, GEMM_SMEM);

    // gemm_mma kept as 4th launch so ncu (-s 5 -c 1) profiles it.
    split_w<<<(KPAD * 256 + 255) / 256, 256>>>(W1l, W1r);
    csr_zero<<<nodeBlocks, 256>>>();
    csr_hist<<<edgeBlocks, 256>>>(dst);
    gemm_mma<<<gemmBlocks, 256, GEMM_SMEM>>>(x, b1l, b1r);
    csr_scan1<<<N_SCAN_BLOCKS, SCAN_BLK>>>();
    csr_scan2<<<1, 256>>>();
    csr_scan3<<<nodeBlocks, 256>>>();
    csr_scatter<<<edgeBlocks, 256>>>(src, dst);
    layer1_csr<<<nodeWarpBlocks, 256>>>(att1, bias1, W2l, b2l, W2r, b2r);
    layer2_csr<<<nodeWarpBlocks, 256>>>(att2, bias2, out);
}

// round 13
// speedup vs baseline: 3.2983x; 1.0203x over previous
#include <cuda_runtime.h>
#include <cstdint>

#define N_NODES 100000
#define N_EDGES 1600000
#define N_FEAT  165
#define HIDDEN  128
#define NEG_SLOPE 0.2f
#define SCAN_BLK 512
#define N_SCAN_BLOCKS ((N_NODES + SCAN_BLK - 1) / SCAN_BLK)   // 196
#define KPAD 176          // K padded to 11 chunks of 16
#define KCHUNK 16
#define NCHUNKS 11

// ---------------- scratch (static __device__ arrays; no allocation) -------
__device__ float g_xl[(size_t)N_NODES * HIDDEN];
__device__ float g_xr[(size_t)N_NODES * HIDDEN];
__device__ float g_hl[N_NODES * 2];
__device__ float g_hr[N_NODES * 2];
__device__ int   g_cnt[N_NODES];
__device__ int   g_rowstart[N_NODES + 1];
__device__ int   g_cursor[N_NODES];
__device__ int   g_blocksum[N_SCAN_BLOCKS];
__device__ int   g_csrsrc[N_EDGES];
// tf32 split planes for W, stored in MMA-fragment order:
// pos = (((c*2+k8)*16 + nt)*32 + lane)*4 + q
__device__ float g_whi[KPAD * 256];
__device__ float g_wlo[KPAD * 256];

// ---------------- helpers ----------------
__device__ __forceinline__ float warpSum(float v) {
    #pragma unroll
    for (int o = 16; o > 0; o >>= 1) v += __shfl_xor_sync(0xffffffffu, v, o);
    return v;
}

__device__ __forceinline__ void warpSum2(float& a, float& b) {
    #pragma unroll
    for (int o = 16; o > 0; o >>= 1) {
        a += __shfl_xor_sync(0xffffffffu, a, o);
        b += __shfl_xor_sync(0xffffffffu, b, o);
    }
}

__device__ __forceinline__ void warpSum4(float& a, float& b, float& c, float& d) {
    #pragma unroll
    for (int o = 16; o > 0; o >>= 1) {
        a += __shfl_xor_sync(0xffffffffu, a, o);
        b += __shfl_xor_sync(0xffffffffu, b, o);
        c += __shfl_xor_sync(0xffffffffu, c, o);
        d += __shfl_xor_sync(0xffffffffu, d, o);
    }
}

__device__ __forceinline__ float lrelu(float v) {
    return v > 0.f ? v : NEG_SLOPE * v;
}

__device__ __forceinline__ float dot_lrelu(float4 a, float4 b, float4 t) {
    return lrelu(a.x + b.x) * t.x + lrelu(a.y + b.y) * t.y
         + lrelu(a.z + b.z) * t.z + lrelu(a.w + b.w) * t.w;
}

__device__ __forceinline__ uint32_t s2u(const void* p) {
    return (uint32_t)__cvta_generic_to_shared(p);
}
#define CPA4(d, s)  asm volatile("cp.async.ca.shared.global [%0], [%1], 4;"  :: "r"(d), "l"(s))
#define CPA16(d, s) asm volatile("cp.async.cg.shared.global [%0], [%1], 16;" :: "r"(d), "l"(s))
#define CP_COMMIT() asm volatile("cp.async.commit_group;" ::: "memory")
#define CP_WAIT1()  asm volatile("cp.async.wait_group 1;" ::: "memory")
#define CP_WAIT0()  asm volatile("cp.async.wait_group 0;" ::: "memory")

#define CVT_TF32(u, f) asm("cvt.rna.tf32.f32 %0, %1;" : "=r"(u) : "f"(f))

// D += A(tf32) * B(tf32);  D,A 4 regs, B 2 regs  (m16n8k8)
#define MMA_TF32(D, A, b0, b1) \
    asm volatile("mma.sync.aligned.m16n8k8.row.col.f32.tf32.tf32.f32 " \
        "{%0,%1,%2,%3}, {%4,%5,%6,%7}, {%8,%9}, {%0,%1,%2,%3};" \
        : "+f"((D)[0]), "+f"((D)[1]), "+f"((D)[2]), "+f"((D)[3]) \
        : "r"((A)[0]), "r"((A)[1]), "r"((A)[2]), "r"((A)[3]), "r"(b0), "r"(b1))

// ================= tf32 hi/lo split for W (fragment-order output) ==========
// Fragment regs (working R12 mapping): b0 = W[kb+tig, nb+g], b1 = W[kb+tig+4, nb+g].
// Lane l: g = l>>2, tig = l&3  ->  slot l = g*4 + tig.
// float4 per lane per 16-col tile: {b0(j), b1(j), b0(j+1), b1(j+1)}.
__global__ void split_w(const float* __restrict__ W1l, const float* __restrict__ W1r) {
    int i = blockIdx.x * blockDim.x + threadIdx.x;
    if (i >= KPAD * 256) return;
    int k = i >> 8, n = i & 255;
    float v = 0.f;
    if (k < N_FEAT) v = (n < 128) ? W1l[k * HIDDEN + n] : W1r[k * HIDDEN + (n - 128)];
    uint32_t hi; CVT_TF32(hi, v);
    float lof = v - __uint_as_float(hi);
    uint32_t lo; CVT_TF32(lo, lof);

    int c   = k >> 4;          // chunk
    int kr  = k & 15;
    int k8  = kr >> 3;
    int r   = kr & 7;
    int tig = r & 3;
    int half = r >> 2;         // 0 -> b0 slot, 1 -> b1 slot
    int nt  = n >> 4;          // 16-col tile
    int nn  = n & 15;
    int gg  = nn & 7;
    int jh  = nn >> 3;         // 0 -> first j of pair, 1 -> second
    int q   = jh * 2 + half;
    size_t pos = ((((size_t)(c * 2 + k8) * 16 + nt) * 32) + (gg * 4 + tig)) * 4 + q;
    g_whi[pos] = __uint_as_float(hi);
    g_wlo[pos] = __uint_as_float(lo);
}

// ================= CSR build =================
__global__ void csr_zero() {
    int i = blockIdx.x * blockDim.x + threadIdx.x;
    if (i < N_NODES) g_cnt[i] = 0;
}

__global__ void csr_hist(const int* __restrict__ dst) {
    int e = blockIdx.x * blockDim.x + threadIdx.x;
    if (e < N_EDGES) atomicAdd(&g_cnt[dst[e]], 1);
}

__global__ void __launch_bounds__(SCAN_BLK) csr_scan1() {
    __shared__ int sh[SCAN_BLK];
    int t = threadIdx.x;
    int i = blockIdx.x * SCAN_BLK + t;
    int v = (i < N_NODES) ? g_cnt[i] : 0;
    sh[t] = v;
    __syncthreads();
    #pragma unroll
    for (int off = 1; off < SCAN_BLK; off <<= 1) {
        int add = (t >= off) ? sh[t - off] : 0;
        __syncthreads();
        sh[t] += add;
        __syncthreads();
    }
    if (i < N_NODES) g_rowstart[i] = sh[t] - v;
    if (t == SCAN_BLK - 1) g_blocksum[blockIdx.x] = sh[t];
}

__global__ void __launch_bounds__(256) csr_scan2() {
    __shared__ int sh[256];
    int t = threadIdx.x;
    int v = (t < N_SCAN_BLOCKS) ? g_blocksum[t] : 0;
    sh[t] = v;
    __syncthreads();
    #pragma unroll
    for (int off = 1; off < 256; off <<= 1) {
        int add = (t >= off) ? sh[t - off] : 0;
        __syncthreads();
        sh[t] += add;
        __syncthreads();
    }
    if (t < N_SCAN_BLOCKS) g_blocksum[t] = sh[t] - v;
}

__global__ void csr_scan3() {
    int i = blockIdx.x * blockDim.x + threadIdx.x;
    if (i < N_NODES) {
        int rs = g_rowstart[i] + g_blocksum[i / SCAN_BLK];
        g_rowstart[i] = rs;
        g_cursor[i] = rs;
    }
    if (i == 0) g_rowstart[N_NODES] = N_EDGES;
}

__global__ void csr_scatter(const int* __restrict__ src, const int* __restrict__ dst) {
    int e = blockIdx.x * blockDim.x + threadIdx.x;
    if (e < N_EDGES) {
        int pos = atomicAdd(&g_cursor[dst[e]], 1);
        g_csrsrc[pos] = src[e];
    }
}

// ================= 3xTF32 tensor GEMM: [Yl|Yr] = X @ [W1l|W1r] + b =========
// Block 64x256, 256 thr, warp grid 2x4, cp.async 2-stage.
// X fp32 in smem (stride 20), hi/lo split in registers.
// W planes in fragment order: one LDS.128 yields b0/b1 for 2 j's.
// Smem: X 2*1280 + W 2stg*2pl*4096 = 2560 + 16384 floats = 75776 B.
__global__ void __launch_bounds__(256, 2) gemm_mma(const float* __restrict__ Xp,
                                                   const float* __restrict__ b1l,
                                                   const float* __restrict__ b1r) {
    extern __shared__ float dsm[];
    float* XS = dsm;            // [stg][64][20]
    float* WS = dsm + 2560;     // [stg][pl][4096] fragment-order

    const int tid = threadIdx.x;
    const int wid = tid >> 5;
    const int lane = tid & 31;
    const int g   = lane >> 2;   // 0..7
    const int tig = lane & 3;    // 0..3
    const int wm = wid >> 2;     // 0..1
    const int wn = wid & 3;      // 0..3
    const int row0 = blockIdx.x * 64;

    auto xs_s  = [&](int stg) { return XS + stg * 1280; };
    auto ws_pl = [&](int stg, int pl) { return WS + (stg * 2 + pl) * 4096; };

    auto load_chunk = [&](int c, int stg) {
        int k0 = c * KCHUNK;
        // X fp32: 64 rows x 16 k, 4B cp.async each
        float* xbase = xs_s(stg);
        #pragma unroll
        for (int i = 0; i < 4; i++) {
            int lin = tid + i * 256;
            int m = lin >> 4, k = lin & 15;
            int gr = row0 + m, gk = k0 + k;
            float* dstp = xbase + m * 20 + k;
            if (gr < N_NODES && gk < N_FEAT)
                CPA4(s2u(dstp), Xp + (size_t)gr * N_FEAT + gk);
            else
                *dstp = 0.f;
        }
        // W planes: flat 4096-float copy each (fragment order preserved)
        const size_t gbase = (size_t)c * 4096;
        float* w0 = ws_pl(stg, 0);
        float* w1 = ws_pl(stg, 1);
        #pragma unroll
        for (int i = 0; i < 4; i++) {
            int L = (tid + i * 256) * 4;          // 16B line offset in floats
            CPA16(s2u(w0 + L), g_whi + gbase + L);
            CPA16(s2u(w1 + L), g_wlo + gbase + L);
        }
    };

    float d[2][8][4];
    #pragma unroll
    for (int i = 0; i < 2; i++)
        #pragma unroll
        for (int j = 0; j < 8; j++)
            #pragma unroll
            for (int q = 0; q < 4; q++) d[i][j][q] = 0.f;

    load_chunk(0, 0);
    CP_COMMIT();

    for (int c = 0; c < NCHUNKS; c++) {
        int stg = c & 1;
        if (c + 1 < NCHUNKS) {
            load_chunk(c + 1, (c + 1) & 1);
            CP_COMMIT();
            CP_WAIT1();
        } else {
            CP_WAIT0();
        }
        __syncthreads();

        const float* xs = xs_s(stg);
        const float4* whi4 = (const float4*)ws_pl(stg, 0);
        const float4* wlo4 = (const float4*)ws_pl(stg, 1);

        #pragma unroll
        for (int k8 = 0; k8 < 2; k8++) {
            int kb = k8 * 8;
            uint32_t ahi[2][4], alo[2][4];
            #pragma unroll
            for (int i = 0; i < 2; i++) {
                int rb = wm * 32 + i * 16;
                float xv[4];
                xv[0] = xs[(rb + g)     * 20 + kb + tig];
                xv[1] = xs[(rb + g + 8) * 20 + kb + tig];
                xv[2] = xs[(rb + g)     * 20 + kb + tig + 4];
                xv[3] = xs[(rb + g + 8) * 20 + kb + tig + 4];
                #pragma unroll
                for (int q = 0; q < 4; q++) {
                    CVT_TF32(ahi[i][q], xv[q]);
                    float lof = xv[q] - __uint_as_float(ahi[i][q]);
                    CVT_TF32(alo[i][q], lof);
                }
            }
            // B fragments: one float4 per plane per 16-col tile (2 j's)
            #pragma unroll
            for (int jp = 0; jp < 4; jp++) {
                int nt = wn * 4 + jp;
                int idx = (k8 * 16 + nt) * 32 + lane;
                float4 BH = whi4[idx];
                float4 BL = wlo4[idx];
                uint32_t bh0 = __float_as_uint(BH.x), bh1 = __float_as_uint(BH.y);
                uint32_t bh2 = __float_as_uint(BH.z), bh3 = __float_as_uint(BH.w);
                uint32_t bl0 = __float_as_uint(BL.x), bl1 = __float_as_uint(BL.y);
                uint32_t bl2 = __float_as_uint(BL.z), bl3 = __float_as_uint(BL.w);
                #pragma unroll
                for (int i = 0; i < 2; i++) {
                    MMA_TF32(d[i][jp * 2],     ahi[i], bh0, bh1);
                    MMA_TF32(d[i][jp * 2],     ahi[i], bl0, bl1);
                    MMA_TF32(d[i][jp * 2],     alo[i], bh0, bh1);
                    MMA_TF32(d[i][jp * 2 + 1], ahi[i], bh2, bh3);
                    MMA_TF32(d[i][jp * 2 + 1], ahi[i], bl2, bl3);
                    MMA_TF32(d[i][jp * 2 + 1], alo[i], bh2, bh3);
                }
            }
        }
        __syncthreads();
    }

    // epilogue: D + bias -> g_xl / g_xr
    #pragma unroll
    for (int i = 0; i < 2; i++) {
        int r0 = row0 + wm * 32 + i * 16 + g;
        int r1 = r0 + 8;
        #pragma unroll
        for (int j = 0; j < 8; j++) {
            int col = wn * 64 + j * 8 + tig * 2;
            if (col < 128) {
                float bb0 = __ldg(&b1l[col]), bb1 = __ldg(&b1l[col + 1]);
                if (r0 < N_NODES) {
                    float2 v = make_float2(d[i][j][0] + bb0, d[i][j][1] + bb1);
                    *(float2*)(g_xl + (size_t)r0 * HIDDEN + col) = v;
                }
                if (r1 < N_NODES) {
                    float2 v = make_float2(d[i][j][2] + bb0, d[i][j][3] + bb1);
                    *(float2*)(g_xl + (size_t)r1 * HIDDEN + col) = v;
                }
            } else {
                int c2 = col - 128;
                float bb0 = __ldg(&b1r[c2]), bb1 = __ldg(&b1r[c2 + 1]);
                if (r0 < N_NODES) {
                    float2 v = make_float2(d[i][j][0] + bb0, d[i][j][1] + bb1);
                    *(float2*)(g_xr + (size_t)r0 * HIDDEN + c2) = v;
                }
                if (r1 < N_NODES) {
                    float2 v = make_float2(d[i][j][2] + bb0, d[i][j][3] + bb1);
                    *(float2*)(g_xr + (size_t)r1 * HIDDEN + c2) = v;
                }
            }
        }
    }
}

// ================= layer 1: warp-per-node, 4-wide edge unroll ==============
__global__ void __launch_bounds__(256) layer1_csr(const float* __restrict__ att,
                                                  const float* __restrict__ bias1,
                                                  const float* __restrict__ W2l,
                                                  const float* __restrict__ b2l,
                                                  const float* __restrict__ W2r,
                                                  const float* __restrict__ b2r) {
    int d = (blockIdx.x * blockDim.x + threadIdx.x) >> 5;
    int lane = threadIdx.x & 31;
    if (d >= N_NODES) return;

    float4 xr4  = ((const float4*)(g_xr + (size_t)d * HIDDEN))[lane];
    float4 att4 = __ldg(&((const float4*)att)[lane]);

    float4 xls = ((const float4*)(g_xl + (size_t)d * HIDDEN))[lane];
    float p = warpSum(dot_lrelu(xls, xr4, att4));
    float w = __expf(p);
    float wsum = w;
    float4 acc = make_float4(w * xls.x, w * xls.y, w * xls.z, w * xls.w);

    int j  = g_rowstart[d];
    int re = g_rowstart[d + 1];

    for (; j + 3 < re; j += 4) {
        int s0 = g_csrsrc[j],     s1 = g_csrsrc[j + 1];
        int s2 = g_csrsrc[j + 2], s3 = g_csrsrc[j + 3];
        float4 a0 = ((const float4*)(g_xl + (size_t)s0 * HIDDEN))[lane];
        float4 a1 = ((const float4*)(g_xl + (size_t)s1 * HIDDEN))[lane];
        float4 a2 = ((const float4*)(g_xl + (size_t)s2 * HIDDEN))[lane];
        float4 a3 = ((const float4*)(g_xl + (size_t)s3 * HIDDEN))[lane];
        float p0 = dot_lrelu(a0, xr4, att4);
        float p1 = dot_lrelu(a1, xr4, att4);
        float p2 = dot_lrelu(a2, xr4, att4);
        float p3 = dot_lrelu(a3, xr4, att4);
        warpSum4(p0, p1, p2, p3);
        float w0 = __expf(p0), w1 = __expf(p1);
        float w2 = __expf(p2), w3 = __expf(p3);
        wsum += (w0 + w1) + (w2 + w3);
        acc.x += w0 * a0.x + w1 * a1.x + w2 * a2.x + w3 * a3.x;
        acc.y += w0 * a0.y + w1 * a1.y + w2 * a2.y + w3 * a3.y;
        acc.z += w0 * a0.z + w1 * a1.z + w2 * a2.z + w3 * a3.z;
        acc.w += w0 * a0.w + w1 * a1.w + w2 * a2.w + w3 * a3.w;
    }
    for (; j + 1 < re; j += 2) {
        int s0 = g_csrsrc[j], s1 = g_csrsrc[j + 1];
        float4 a0 = ((const float4*)(g_xl + (size_t)s0 * HIDDEN))[lane];
        float4 a1 = ((const float4*)(g_xl + (size_t)s1 * HIDDEN))[lane];
        float p0 = dot_lrelu(a0, xr4, att4);
        float p1 = dot_lrelu(a1, xr4, att4);
        warpSum2(p0, p1);
        float w0 = __expf(p0), w1 = __expf(p1);
        wsum += w0 + w1;
        acc.x += w0 * a0.x + w1 * a1.x;
        acc.y += w0 * a0.y + w1 * a1.y;
        acc.z += w0 * a0.z + w1 * a1.z;
        acc.w += w0 * a0.w + w1 * a1.w;
    }
    if (j < re) {
        int s0 = g_csrsrc[j];
        float4 a0 = ((const float4*)(g_xl + (size_t)s0 * HIDDEN))[lane];
        float w0 = __expf(warpSum(dot_lrelu(a0, xr4, att4)));
        wsum += w0;
        acc.x += w0 * a0.x; acc.y += w0 * a0.y;
        acc.z += w0 * a0.z; acc.w += w0 * a0.w;
    }

    float inv = __fdividef(1.f, wsum);
    float4 b4 = __ldg(&((const float4*)bias1)[lane]);
    float h0 = acc.x * inv + b4.x;  h0 = h0 > 0.f ? h0 : 0.f;
    float h1 = acc.y * inv + b4.y;  h1 = h1 > 0.f ? h1 : 0.f;
    float h2 = acc.z * inv + b4.z;  h2 = h2 > 0.f ? h2 : 0.f;
    float h3 = acc.w * inv + b4.w;  h3 = h3 > 0.f ? h3 : 0.f;

    float4 wl0 = __ldg(&((const float4*)W2l)[2 * lane]);
    float4 wl1 = __ldg(&((const float4*)W2l)[2 * lane + 1]);
    float4 wr0 = __ldg(&((const float4*)W2r)[2 * lane]);
    float4 wr1 = __ldg(&((const float4*)W2r)[2 * lane + 1]);

    float s0 = h0 * wl0.x + h1 * wl0.z + h2 * wl1.x + h3 * wl1.z;
    float s1 = h0 * wl0.y + h1 * wl0.w + h2 * wl1.y + h3 * wl1.w;
    float s2 = h0 * wr0.x + h1 * wr0.z + h2 * wr1.x + h3 * wr1.z;
    float s3 = h0 * wr0.y + h1 * wr0.w + h2 * wr1.y + h3 * wr1.w;
    warpSum4(s0, s1, s2, s3);

    if (lane == 0) {
        g_hl[2 * d + 0] = s0 + __ldg(&b2l[0]);
        g_hl[2 * d + 1] = s1 + __ldg(&b2l[1]);
        g_hr[2 * d + 0] = s2 + __ldg(&b2r[0]);
        g_hr[2 * d + 1] = s3 + __ldg(&b2r[1]);
    }
}

// ================= layer 2: warp-per-node, lanes stride edges ==============
__global__ void __launch_bounds__(256) layer2_csr(const float* __restrict__ att2,
                                                  const float* __restrict__ bias2,
                                                  float* __restrict__ out) {
    int d = (blockIdx.x * blockDim.x + threadIdx.x) >> 5;
    int lane = threadIdx.x & 31;
    if (d >= N_NODES) return;

    float a20 = __ldg(&att2[0]);
    float a21 = __ldg(&att2[1]);
    float2 hr2 = *(const float2*)(g_hr + 2 * d);

    float den = 0.f, n0 = 0.f, n1 = 0.f;

    if (lane == 0) {
        float2 hls = *(const float2*)(g_hl + 2 * d);
        float sc = lrelu(hls.x + hr2.x) * a20 + lrelu(hls.y + hr2.y) * a21;
        float w = __expf(sc);
        den = w; n0 = w * hls.x; n1 = w * hls.y;
    }

    int rs = g_rowstart[d];
    int re = g_rowstart[d + 1];
    for (int j = rs + lane; j < re; j += 32) {
        int s = g_csrsrc[j];
        float2 hl = *(const float2*)(g_hl + 2 * s);
        float sc = lrelu(hl.x + hr2.x) * a20 + lrelu(hl.y + hr2.y) * a21;
        float w = __expf(sc);
        den += w; n0 += w * hl.x; n1 += w * hl.y;
    }

    warpSum2(n0, n1);
    den = warpSum(den);

    if (lane == 0) {
        float inv = __fdividef(1.f, den);
        out[2 * d + 0] = n0 * inv + __ldg(&bias2[0]);
        out[2 * d + 1] = n1 * inv + __ldg(&bias2[1]);
    }
}

// ---------------- launch ----------------
extern "C" void kernel_launch(void* const* d_in, const int* in_sizes, int n_in,
                              void* d_out, int out_size) {
    const float* x    = (const float*)d_in[0];
    const int*   src  = (const int*)  d_in[1];
    const int*   dst  = (const int*)  d_in[2];
    const float* W1l  = (const float*)d_in[3];
    const float* b1l  = (const float*)d_in[4];
    const float* W1r  = (const float*)d_in[5];
    const float* b1r  = (const float*)d_in[6];
    const float* att1 = (const float*)d_in[7];
    const float* bias1= (const float*)d_in[8];
    const float* W2l  = (const float*)d_in[9];
    const float* b2l  = (const float*)d_in[10];
    const float* W2r  = (const float*)d_in[11];
    const float* b2r  = (const float*)d_in[12];
    const float* att2 = (const float*)d_in[13];
    const float* bias2= (const float*)d_in[14];
    float* out = (float*)d_out;

    const int gemmBlocks = (N_NODES + 63) / 64;               // 1563
    const int edgeBlocks = (N_EDGES + 255) / 256;             // 6250
    const int nodeBlocks = (N_NODES + 255) / 256;             // 391
    const int nodeWarpBlocks = (N_NODES * 32 + 255) / 256;    // 12500
    const int GEMM_SMEM = (2560 + 16384) * 4;                 // 75776 B

    cudaFuncSetAttribute((const void*)gemm_mma,
                         cudaFuncAttributeMaxDynamicSharedMemorySize, GEMM_SMEM);

    // gemm_mma kept as 4th launch so ncu (-s 5 -c 1) profiles it.
    split_w<<<(KPAD * 256 + 255) / 256, 256>>>(W1l, W1r);
    csr_zero<<<nodeBlocks, 256>>>();
    csr_hist<<<edgeBlocks, 256>>>(dst);
    gemm_mma<<<gemmBlocks, 256, GEMM_SMEM>>>(x, b1l, b1r);
    csr_scan1<<<N_SCAN_BLOCKS, SCAN_BLK>>>();
    csr_scan2<<<1, 256>>>();
    csr_scan3<<<nodeBlocks, 256>>>();
    csr_scatter<<<edgeBlocks, 256>>>(src, dst);
    layer1_csr<<<nodeWarpBlocks, 256>>>(att1, bias1, W2l, b2l, W2r, b2r);
    layer2_csr<<<nodeWarpBlocks, 256>>>(att2, bias2, out);
}

// round 14
// speedup vs baseline: 3.8955x; 1.1811x over previous
#include <cuda_runtime.h>
#include <cuda_bf16.h>
#include <cstdint>

#define N_NODES 100000
#define N_EDGES 1600000
#define N_FEAT  165
#define HIDDEN  128
#define NEG_SLOPE 0.2f
#define SCAN_BLK 512
#define N_SCAN_BLOCKS ((N_NODES + SCAN_BLK - 1) / SCAN_BLK)   // 196
#define KPAD 176          // K padded to 11 chunks of 16
#define KCHUNK 16
#define NCHUNKS 11

// ---------------- scratch (static __device__ arrays; no allocation) -------
__device__ float g_xl[(size_t)N_NODES * HIDDEN];
__device__ float g_xr[(size_t)N_NODES * HIDDEN];
__device__ float g_hl[N_NODES * 2];
__device__ float g_hr[N_NODES * 2];
__device__ int   g_cnt[N_NODES];
__device__ int   g_rowstart[N_NODES + 1];
__device__ int   g_cursor[N_NODES];
__device__ int   g_blocksum[N_SCAN_BLOCKS];
__device__ int   g_csrsrc[N_EDGES];
// bf16 hi/lo planes for W in m16n8k16 fragment order:
// word = ((c*16 + nt)*32 + lane)*4 + q, halves: lower = even k
__device__ unsigned short g_whi[KPAD * 256];
__device__ unsigned short g_wlo[KPAD * 256];

// ---------------- helpers ----------------
__device__ __forceinline__ float warpSum(float v) {
    #pragma unroll
    for (int o = 16; o > 0; o >>= 1) v += __shfl_xor_sync(0xffffffffu, v, o);
    return v;
}

__device__ __forceinline__ void warpSum2(float& a, float& b) {
    #pragma unroll
    for (int o = 16; o > 0; o >>= 1) {
        a += __shfl_xor_sync(0xffffffffu, a, o);
        b += __shfl_xor_sync(0xffffffffu, b, o);
    }
}

__device__ __forceinline__ void warpSum4(float& a, float& b, float& c, float& d) {
    #pragma unroll
    for (int o = 16; o > 0; o >>= 1) {
        a += __shfl_xor_sync(0xffffffffu, a, o);
        b += __shfl_xor_sync(0xffffffffu, b, o);
        c += __shfl_xor_sync(0xffffffffu, c, o);
        d += __shfl_xor_sync(0xffffffffu, d, o);
    }
}

__device__ __forceinline__ float lrelu(float v) {
    return v > 0.f ? v : NEG_SLOPE * v;
}

__device__ __forceinline__ float dot_lrelu(float4 a, float4 b, float4 t) {
    return lrelu(a.x + b.x) * t.x + lrelu(a.y + b.y) * t.y
         + lrelu(a.z + b.z) * t.z + lrelu(a.w + b.w) * t.w;
}

__device__ __forceinline__ uint32_t s2u(const void* p) {
    return (uint32_t)__cvta_generic_to_shared(p);
}
#define CPA4(d, s)  asm volatile("cp.async.ca.shared.global [%0], [%1], 4;"  :: "r"(d), "l"(s))
#define CPA16(d, s) asm volatile("cp.async.cg.shared.global [%0], [%1], 16;" :: "r"(d), "l"(s))
#define CP_COMMIT() asm volatile("cp.async.commit_group;" ::: "memory")
#define CP_WAIT1()  asm volatile("cp.async.wait_group 1;" ::: "memory")
#define CP_WAIT0()  asm volatile("cp.async.wait_group 0;" ::: "memory")

// bf16x3 split: lo_v = element k (lower half), hi_v = element k+1 (upper half)
__device__ __forceinline__ void packsplit(float lo_v, float hi_v,
                                          uint32_t& hp, uint32_t& lp) {
    asm("cvt.rn.bf16x2.f32 %0, %1, %2;" : "=r"(hp) : "f"(hi_v), "f"(lo_v));
    float h_lo = __uint_as_float(hp << 16);
    float h_hi = __uint_as_float(hp & 0xffff0000u);
    float r_lo = lo_v - h_lo;
    float r_hi = hi_v - h_hi;
    asm("cvt.rn.bf16x2.f32 %0, %1, %2;" : "=r"(lp) : "f"(r_hi), "f"(r_lo));
}

// D += A(bf16) * B(bf16);  m16n8k16, A 4 regs, B 2 regs, fp32 accum
#define MMA_BF16(D, A, b0, b1) \
    asm volatile("mma.sync.aligned.m16n8k16.row.col.f32.bf16.bf16.f32 " \
        "{%0,%1,%2,%3}, {%4,%5,%6,%7}, {%8,%9}, {%0,%1,%2,%3};" \
        : "+f"((D)[0]), "+f"((D)[1]), "+f"((D)[2]), "+f"((D)[3]) \
        : "r"((A)[0]), "r"((A)[1]), "r"((A)[2]), "r"((A)[3]), "r"(b0), "r"(b1))

// ================= bf16 hi/lo split for W (fragment-order output) ==========
// B fragment (m16n8k16 row.col): b0 = {B[2tig][g], B[2tig+1][g]} (lower=even k),
// b1 = {B[2tig+8][g], B[2tig+9][g]}. Lane = g*4 + tig.
// uint4 per lane per 16-col tile: {b0(j0), b1(j0), b0(j1), b1(j1)}.
__global__ void split_w(const float* __restrict__ W1l, const float* __restrict__ W1r) {
    int i = blockIdx.x * blockDim.x + threadIdx.x;
    if (i >= KPAD * 256) return;
    int k = i >> 8, n = i & 255;
    float v = 0.f;
    if (k < N_FEAT) v = (n < 128) ? W1l[k * HIDDEN + n] : W1r[k * HIDDEN + (n - 128)];
    __nv_bfloat16 hb = __float2bfloat16_rn(v);
    unsigned short h = __bfloat16_as_ushort(hb);
    float hf = __uint_as_float((uint32_t)h << 16);
    float r = v - hf;
    unsigned short lo = __bfloat16_as_ushort(__float2bfloat16_rn(r));

    int c    = k >> 4;
    int kr   = k & 15;
    int tig  = (kr >> 1) & 3;
    int bslot = kr >> 3;        // 0 -> b0, 1 -> b1
    int lh   = kr & 1;          // 0 -> lower half (even k), 1 -> upper
    int nt   = n >> 4;
    int nn   = n & 15;
    int gg   = nn & 7;
    int jh   = nn >> 3;
    int lane = gg * 4 + tig;
    int q    = jh * 2 + bslot;
    size_t word = (((size_t)c * 16 + nt) * 32 + lane) * 4 + q;
    g_whi[word * 2 + lh] = h;
    g_wlo[word * 2 + lh] = lo;
}

// ================= CSR build =================
__global__ void csr_zero() {
    int i = blockIdx.x * blockDim.x + threadIdx.x;
    if (i < N_NODES) g_cnt[i] = 0;
}

__global__ void csr_hist(const int* __restrict__ dst) {
    int e = blockIdx.x * blockDim.x + threadIdx.x;
    if (e < N_EDGES) atomicAdd(&g_cnt[dst[e]], 1);
}

__global__ void __launch_bounds__(SCAN_BLK) csr_scan1() {
    __shared__ int sh[SCAN_BLK];
    int t = threadIdx.x;
    int i = blockIdx.x * SCAN_BLK + t;
    int v = (i < N_NODES) ? g_cnt[i] : 0;
    sh[t] = v;
    __syncthreads();
    #pragma unroll
    for (int off = 1; off < SCAN_BLK; off <<= 1) {
        int add = (t >= off) ? sh[t - off] : 0;
        __syncthreads();
        sh[t] += add;
        __syncthreads();
    }
    if (i < N_NODES) g_rowstart[i] = sh[t] - v;
    if (t == SCAN_BLK - 1) g_blocksum[blockIdx.x] = sh[t];
}

__global__ void __launch_bounds__(256) csr_scan2() {
    __shared__ int sh[256];
    int t = threadIdx.x;
    int v = (t < N_SCAN_BLOCKS) ? g_blocksum[t] : 0;
    sh[t] = v;
    __syncthreads();
    #pragma unroll
    for (int off = 1; off < 256; off <<= 1) {
        int add = (t >= off) ? sh[t - off] : 0;
        __syncthreads();
        sh[t] += add;
        __syncthreads();
    }
    if (t < N_SCAN_BLOCKS) g_blocksum[t] = sh[t] - v;
}

__global__ void csr_scan3() {
    int i = blockIdx.x * blockDim.x + threadIdx.x;
    if (i < N_NODES) {
        int rs = g_rowstart[i] + g_blocksum[i / SCAN_BLK];
        g_rowstart[i] = rs;
        g_cursor[i] = rs;
    }
    if (i == 0) g_rowstart[N_NODES] = N_EDGES;
}

__global__ void csr_scatter(const int* __restrict__ src, const int* __restrict__ dst) {
    int e = blockIdx.x * blockDim.x + threadIdx.x;
    if (e < N_EDGES) {
        int pos = atomicAdd(&g_cursor[dst[e]], 1);
        g_csrsrc[pos] = src[e];
    }
}

// ================= 3xBF16 tensor GEMM: [Yl|Yr] = X @ [W1l|W1r] + b =========
// Block 64x256, 256 thr, warp grid 2x4, cp.async 2-stage, m16n8k16 bf16.
// X fp32 in smem (stride 20), split+packed to bf16x2 in registers.
// W planes in fragment order: one LDS.128 = b0/b1 for 2 j's, full K16.
// Smem: X 2*1280*4 + W 2stg*2pl*2048*4 = 10240 + 32768 = 43008 B.
__global__ void __launch_bounds__(256, 2) gemm_mma(const float* __restrict__ Xp,
                                                   const float* __restrict__ b1l,
                                                   const float* __restrict__ b1r) {
    extern __shared__ float dsm[];
    float* XS = dsm;                             // [stg][64][20]
    uint32_t* WS = (uint32_t*)(dsm + 2560);      // [stg][pl][2048 words]

    const int tid = threadIdx.x;
    const int wid = tid >> 5;
    const int lane = tid & 31;
    const int g   = lane >> 2;   // 0..7
    const int tig = lane & 3;    // 0..3
    const int wm = wid >> 2;     // 0..1
    const int wn = wid & 3;      // 0..3
    const int row0 = blockIdx.x * 64;

    auto xs_s  = [&](int stg) { return XS + stg * 1280; };
    auto ws_pl = [&](int stg, int pl) { return WS + (stg * 2 + pl) * 2048; };

    auto load_chunk = [&](int c, int stg) {
        int k0 = c * KCHUNK;
        // X fp32: 64 rows x 16 k, 4B cp.async each
        float* xbase = xs_s(stg);
        #pragma unroll
        for (int i = 0; i < 4; i++) {
            int lin = tid + i * 256;
            int m = lin >> 4, k = lin & 15;
            int gr = row0 + m, gk = k0 + k;
            float* dstp = xbase + m * 20 + k;
            if (gr < N_NODES && gk < N_FEAT)
                CPA4(s2u(dstp), Xp + (size_t)gr * N_FEAT + gk);
            else
                *dstp = 0.f;
        }
        // W planes: 2048 words per plane per chunk, flat copy
        const uint32_t* gw0 = (const uint32_t*)g_whi;
        const uint32_t* gw1 = (const uint32_t*)g_wlo;
        const size_t gbase = (size_t)c * 2048;
        uint32_t* w0 = ws_pl(stg, 0);
        uint32_t* w1 = ws_pl(stg, 1);
        #pragma unroll
        for (int i = 0; i < 2; i++) {
            int L = (tid + i * 256) * 4;
            CPA16(s2u(w0 + L), gw0 + gbase + L);
            CPA16(s2u(w1 + L), gw1 + gbase + L);
        }
    };

    float d[2][8][4];
    #pragma unroll
    for (int i = 0; i < 2; i++)
        #pragma unroll
        for (int j = 0; j < 8; j++)
            #pragma unroll
            for (int q = 0; q < 4; q++) d[i][j][q] = 0.f;

    load_chunk(0, 0);
    CP_COMMIT();

    for (int c = 0; c < NCHUNKS; c++) {
        int stg = c & 1;
        if (c + 1 < NCHUNKS) {
            load_chunk(c + 1, (c + 1) & 1);
            CP_COMMIT();
            CP_WAIT1();
        } else {
            CP_WAIT0();
        }
        __syncthreads();

        const float* xs = xs_s(stg);
        const uint4* whi4 = (const uint4*)ws_pl(stg, 0);
        const uint4* wlo4 = (const uint4*)ws_pl(stg, 1);

        // A fragments: rows rb+g / rb+g+8, col pairs (2tig,2tig+1), (+8,+9)
        uint32_t ahi[2][4], alo[2][4];
        #pragma unroll
        for (int i = 0; i < 2; i++) {
            int rb = wm * 32 + i * 16;
            const float* r0p = xs + (rb + g) * 20 + 2 * tig;
            const float* r1p = xs + (rb + g + 8) * 20 + 2 * tig;
            float2 x0 = *(const float2*)r0p;
            float2 x1 = *(const float2*)r1p;
            float2 x2 = *(const float2*)(r0p + 8);
            float2 x3 = *(const float2*)(r1p + 8);
            packsplit(x0.x, x0.y, ahi[i][0], alo[i][0]);
            packsplit(x1.x, x1.y, ahi[i][1], alo[i][1]);
            packsplit(x2.x, x2.y, ahi[i][2], alo[i][2]);
            packsplit(x3.x, x3.y, ahi[i][3], alo[i][3]);
        }

        #pragma unroll
        for (int jp = 0; jp < 4; jp++) {
            int idx = (wn * 4 + jp) * 32 + lane;
            uint4 BH = whi4[idx];
            uint4 BL = wlo4[idx];
            #pragma unroll
            for (int i = 0; i < 2; i++) {
                MMA_BF16(d[i][jp * 2],     ahi[i], BH.x, BH.y);
                MMA_BF16(d[i][jp * 2],     ahi[i], BL.x, BL.y);
                MMA_BF16(d[i][jp * 2],     alo[i], BH.x, BH.y);
                MMA_BF16(d[i][jp * 2 + 1], ahi[i], BH.z, BH.w);
                MMA_BF16(d[i][jp * 2 + 1], ahi[i], BL.z, BL.w);
                MMA_BF16(d[i][jp * 2 + 1], alo[i], BH.z, BH.w);
            }
        }
        __syncthreads();
    }

    // epilogue: D + bias -> g_xl / g_xr  (m16n8 D layout unchanged)
    #pragma unroll
    for (int i = 0; i < 2; i++) {
        int r0 = row0 + wm * 32 + i * 16 + g;
        int r1 = r0 + 8;
        #pragma unroll
        for (int j = 0; j < 8; j++) {
            int col = wn * 64 + j * 8 + tig * 2;
            if (col < 128) {
                float bb0 = __ldg(&b1l[col]), bb1 = __ldg(&b1l[col + 1]);
                if (r0 < N_NODES) {
                    float2 v = make_float2(d[i][j][0] + bb0, d[i][j][1] + bb1);
                    *(float2*)(g_xl + (size_t)r0 * HIDDEN + col) = v;
                }
                if (r1 < N_NODES) {
                    float2 v = make_float2(d[i][j][2] + bb0, d[i][j][3] + bb1);
                    *(float2*)(g_xl + (size_t)r1 * HIDDEN + col) = v;
                }
            } else {
                int c2 = col - 128;
                float bb0 = __ldg(&b1r[c2]), bb1 = __ldg(&b1r[c2 + 1]);
                if (r0 < N_NODES) {
                    float2 v = make_float2(d[i][j][0] + bb0, d[i][j][1] + bb1);
                    *(float2*)(g_xr + (size_t)r0 * HIDDEN + c2) = v;
                }
                if (r1 < N_NODES) {
                    float2 v = make_float2(d[i][j][2] + bb0, d[i][j][3] + bb1);
                    *(float2*)(g_xr + (size_t)r1 * HIDDEN + c2) = v;
                }
            }
        }
    }
}

// ================= layer 1: warp-per-node, 4-wide edge unroll ==============
__global__ void __launch_bounds__(256) layer1_csr(const float* __restrict__ att,
                                                  const float* __restrict__ bias1,
                                                  const float* __restrict__ W2l,
                                                  const float* __restrict__ b2l,
                                                  const float* __restrict__ W2r,
                                                  const float* __restrict__ b2r) {
    int d = (blockIdx.x * blockDim.x + threadIdx.x) >> 5;
    int lane = threadIdx.x & 31;
    if (d >= N_NODES) return;

    float4 xr4  = ((const float4*)(g_xr + (size_t)d * HIDDEN))[lane];
    float4 att4 = __ldg(&((const float4*)att)[lane]);

    float4 xls = ((const float4*)(g_xl + (size_t)d * HIDDEN))[lane];
    float p = warpSum(dot_lrelu(xls, xr4, att4));
    float w = __expf(p);
    float wsum = w;
    float4 acc = make_float4(w * xls.x, w * xls.y, w * xls.z, w * xls.w);

    int j  = g_rowstart[d];
    int re = g_rowstart[d + 1];

    for (; j + 3 < re; j += 4) {
        int s0 = g_csrsrc[j],     s1 = g_csrsrc[j + 1];
        int s2 = g_csrsrc[j + 2], s3 = g_csrsrc[j + 3];
        float4 a0 = ((const float4*)(g_xl + (size_t)s0 * HIDDEN))[lane];
        float4 a1 = ((const float4*)(g_xl + (size_t)s1 * HIDDEN))[lane];
        float4 a2 = ((const float4*)(g_xl + (size_t)s2 * HIDDEN))[lane];
        float4 a3 = ((const float4*)(g_xl + (size_t)s3 * HIDDEN))[lane];
        float p0 = dot_lrelu(a0, xr4, att4);
        float p1 = dot_lrelu(a1, xr4, att4);
        float p2 = dot_lrelu(a2, xr4, att4);
        float p3 = dot_lrelu(a3, xr4, att4);
        warpSum4(p0, p1, p2, p3);
        float w0 = __expf(p0), w1 = __expf(p1);
        float w2 = __expf(p2), w3 = __expf(p3);
        wsum += (w0 + w1) + (w2 + w3);
        acc.x += w0 * a0.x + w1 * a1.x + w2 * a2.x + w3 * a3.x;
        acc.y += w0 * a0.y + w1 * a1.y + w2 * a2.y + w3 * a3.y;
        acc.z += w0 * a0.z + w1 * a1.z + w2 * a2.z + w3 * a3.z;
        acc.w += w0 * a0.w + w1 * a1.w + w2 * a2.w + w3 * a3.w;
    }
    for (; j + 1 < re; j += 2) {
        int s0 = g_csrsrc[j], s1 = g_csrsrc[j + 1];
        float4 a0 = ((const float4*)(g_xl + (size_t)s0 * HIDDEN))[lane];
        float4 a1 = ((const float4*)(g_xl + (size_t)s1 * HIDDEN))[lane];
        float p0 = dot_lrelu(a0, xr4, att4);
        float p1 = dot_lrelu(a1, xr4, att4);
        warpSum2(p0, p1);
        float w0 = __expf(p0), w1 = __expf(p1);
        wsum += w0 + w1;
        acc.x += w0 * a0.x + w1 * a1.x;
        acc.y += w0 * a0.y + w1 * a1.y;
        acc.z += w0 * a0.z + w1 * a1.z;
        acc.w += w0 * a0.w + w1 * a1.w;
    }
    if (j < re) {
        int s0 = g_csrsrc[j];
        float4 a0 = ((const float4*)(g_xl + (size_t)s0 * HIDDEN))[lane];
        float w0 = __expf(warpSum(dot_lrelu(a0, xr4, att4)));
        wsum += w0;
        acc.x += w0 * a0.x; acc.y += w0 * a0.y;
        acc.z += w0 * a0.z; acc.w += w0 * a0.w;
    }

    float inv = __fdividef(1.f, wsum);
    float4 b4 = __ldg(&((const float4*)bias1)[lane]);
    float h0 = acc.x * inv + b4.x;  h0 = h0 > 0.f ? h0 : 0.f;
    float h1 = acc.y * inv + b4.y;  h1 = h1 > 0.f ? h1 : 0.f;
    float h2 = acc.z * inv + b4.z;  h2 = h2 > 0.f ? h2 : 0.f;
    float h3 = acc.w * inv + b4.w;  h3 = h3 > 0.f ? h3 : 0.f;

    float4 wl0 = __ldg(&((const float4*)W2l)[2 * lane]);
    float4 wl1 = __ldg(&((const float4*)W2l)[2 * lane + 1]);
    float4 wr0 = __ldg(&((const float4*)W2r)[2 * lane]);
    float4 wr1 = __ldg(&((const float4*)W2r)[2 * lane + 1]);

    float s0 = h0 * wl0.x + h1 * wl0.z + h2 * wl1.x + h3 * wl1.z;
    float s1 = h0 * wl0.y + h1 * wl0.w + h2 * wl1.y + h3 * wl1.w;
    float s2 = h0 * wr0.x + h1 * wr0.z + h2 * wr1.x + h3 * wr1.z;
    float s3 = h0 * wr0.y + h1 * wr0.w + h2 * wr1.y + h3 * wr1.w;
    warpSum4(s0, s1, s2, s3);

    if (lane == 0) {
        g_hl[2 * d + 0] = s0 + __ldg(&b2l[0]);
        g_hl[2 * d + 1] = s1 + __ldg(&b2l[1]);
        g_hr[2 * d + 0] = s2 + __ldg(&b2r[0]);
        g_hr[2 * d + 1] = s3 + __ldg(&b2r[1]);
    }
}

// ================= layer 2: warp-per-node, lanes stride edges ==============
__global__ void __launch_bounds__(256) layer2_csr(const float* __restrict__ att2,
                                                  const float* __restrict__ bias2,
                                                  float* __restrict__ out) {
    int d = (blockIdx.x * blockDim.x + threadIdx.x) >> 5;
    int lane = threadIdx.x & 31;
    if (d >= N_NODES) return;

    float a20 = __ldg(&att2[0]);
    float a21 = __ldg(&att2[1]);
    float2 hr2 = *(const float2*)(g_hr + 2 * d);

    float den = 0.f, n0 = 0.f, n1 = 0.f;

    if (lane == 0) {
        float2 hls = *(const float2*)(g_hl + 2 * d);
        float sc = lrelu(hls.x + hr2.x) * a20 + lrelu(hls.y + hr2.y) * a21;
        float w = __expf(sc);
        den = w; n0 = w * hls.x; n1 = w * hls.y;
    }

    int rs = g_rowstart[d];
    int re = g_rowstart[d + 1];
    for (int j = rs + lane; j < re; j += 32) {
        int s = g_csrsrc[j];
        float2 hl = *(const float2*)(g_hl + 2 * s);
        float sc = lrelu(hl.x + hr2.x) * a20 + lrelu(hl.y + hr2.y) * a21;
        float w = __expf(sc);
        den += w; n0 += w * hl.x; n1 += w * hl.y;
    }

    warpSum2(n0, n1);
    den = warpSum(den);

    if (lane == 0) {
        float inv = __fdividef(1.f, den);
        out[2 * d + 0] = n0 * inv + __ldg(&bias2[0]);
        out[2 * d + 1] = n1 * inv + __ldg(&bias2[1]);
    }
}

// ---------------- launch ----------------
extern "C" void kernel_launch(void* const* d_in, const int* in_sizes, int n_in,
                              void* d_out, int out_size) {
    const float* x    = (const float*)d_in[0];
    const int*   src  = (const int*)  d_in[1];
    const int*   dst  = (const int*)  d_in[2];
    const float* W1l  = (const float*)d_in[3];
    const float* b1l  = (const float*)d_in[4];
    const float* W1r  = (const float*)d_in[5];
    const float* b1r  = (const float*)d_in[6];
    const float* att1 = (const float*)d_in[7];
    const float* bias1= (const float*)d_in[8];
    const float* W2l  = (const float*)d_in[9];
    const float* b2l  = (const float*)d_in[10];
    const float* W2r  = (const float*)d_in[11];
    const float* b2r  = (const float*)d_in[12];
    const float* att2 = (const float*)d_in[13];
    const float* bias2= (const float*)d_in[14];
    float* out = (float*)d_out;

    const int gemmBlocks = (N_NODES + 63) / 64;               // 1563
    const int edgeBlocks = (N_EDGES + 255) / 256;             // 6250
    const int nodeBlocks = (N_NODES + 255) / 256;             // 391
    const int nodeWarpBlocks = (N_NODES * 32 + 255) / 256;    // 12500
    const int GEMM_SMEM = 2560 * 4 + 4 * 2048 * 4;            // 43008 B

    cudaFuncSetAttribute((const void*)gemm_mma,
                         cudaFuncAttributeMaxDynamicSharedMemorySize, GEMM_SMEM);

    // gemm_mma kept as 4th launch so ncu (-s 5 -c 1) profiles it.
    split_w<<<(KPAD * 256 + 255) / 256, 256>>>(W1l, W1r);
    csr_zero<<<nodeBlocks, 256>>>();
    csr_hist<<<edgeBlocks, 256>>>(dst);
    gemm_mma<<<gemmBlocks, 256, GEMM_SMEM>>>(x, b1l, b1r);
    csr_scan1<<<N_SCAN_BLOCKS, SCAN_BLK>>>();
    csr_scan2<<<1, 256>>>();
    csr_scan3<<<nodeBlocks, 256>>>();
    csr_scatter<<<edgeBlocks, 256>>>(src, dst);
    layer1_csr<<<nodeWarpBlocks, 256>>>(att1, bias1, W2l, b2l, W2r, b2r);
    layer2_csr<<<nodeWarpBlocks, 256>>>(att2, bias2, out);
}

// round 15
// speedup vs baseline: 4.0219x; 1.0324x over previous
#include <cuda_runtime.h>
#include <cuda_bf16.h>
#include <cstdint>

#define N_NODES 100000
#define N_EDGES 1600000
#define N_FEAT  165
#define HIDDEN  128
#define NEG_SLOPE 0.2f
#define SCAN_BLK 512
#define N_SCAN_BLOCKS ((N_NODES + SCAN_BLK - 1) / SCAN_BLK)   // 196
#define KPAD 176          // K padded to 11 chunks of 16
#define KCHUNK 16
#define NCHUNKS 11

// ---------------- scratch (static __device__ arrays; no allocation) -------
__device__ float g_xl[(size_t)N_NODES * HIDDEN];
__device__ float g_xr[(size_t)N_NODES * HIDDEN];
__device__ float g_hl[N_NODES * 2];
__device__ float g_hr[N_NODES * 2];
__device__ int   g_cnt[N_NODES];
__device__ int   g_rowstart[N_NODES + 1];
__device__ int   g_cursor[N_NODES];
__device__ int   g_blocksum[N_SCAN_BLOCKS];
__device__ int   g_csrsrc[N_EDGES];
// bf16 hi/lo planes for W in m16n8k16 fragment order
__device__ unsigned short g_whi[KPAD * 256];
__device__ unsigned short g_wlo[KPAD * 256];

// ---------------- helpers ----------------
__device__ __forceinline__ float warpSum(float v) {
    #pragma unroll
    for (int o = 16; o > 0; o >>= 1) v += __shfl_xor_sync(0xffffffffu, v, o);
    return v;
}

__device__ __forceinline__ void warpSum2(float& a, float& b) {
    #pragma unroll
    for (int o = 16; o > 0; o >>= 1) {
        a += __shfl_xor_sync(0xffffffffu, a, o);
        b += __shfl_xor_sync(0xffffffffu, b, o);
    }
}

__device__ __forceinline__ void warpSum4(float& a, float& b, float& c, float& d) {
    #pragma unroll
    for (int o = 16; o > 0; o >>= 1) {
        a += __shfl_xor_sync(0xffffffffu, a, o);
        b += __shfl_xor_sync(0xffffffffu, b, o);
        c += __shfl_xor_sync(0xffffffffu, c, o);
        d += __shfl_xor_sync(0xffffffffu, d, o);
    }
}

__device__ __forceinline__ float lrelu(float v) {
    return v > 0.f ? v : NEG_SLOPE * v;
}

__device__ __forceinline__ float dot_lrelu(float4 a, float4 b, float4 t) {
    return lrelu(a.x + b.x) * t.x + lrelu(a.y + b.y) * t.y
         + lrelu(a.z + b.z) * t.z + lrelu(a.w + b.w) * t.w;
}

__device__ __forceinline__ uint32_t s2u(const void* p) {
    return (uint32_t)__cvta_generic_to_shared(p);
}
#define CPA4(d, s)  asm volatile("cp.async.ca.shared.global [%0], [%1], 4;"  :: "r"(d), "l"(s))
#define CPA16(d, s) asm volatile("cp.async.cg.shared.global [%0], [%1], 16;" :: "r"(d), "l"(s))
#define CP_COMMIT() asm volatile("cp.async.commit_group;" ::: "memory")
#define CP_WAIT2()  asm volatile("cp.async.wait_group 2;" ::: "memory")

// bf16x3 split: lo_v = element k (lower half), hi_v = element k+1 (upper half)
__device__ __forceinline__ void packsplit(float lo_v, float hi_v,
                                          uint32_t& hp, uint32_t& lp) {
    asm("cvt.rn.bf16x2.f32 %0, %1, %2;" : "=r"(hp) : "f"(hi_v), "f"(lo_v));
    float h_lo = __uint_as_float(hp << 16);
    float h_hi = __uint_as_float(hp & 0xffff0000u);
    float r_lo = lo_v - h_lo;
    float r_hi = hi_v - h_hi;
    asm("cvt.rn.bf16x2.f32 %0, %1, %2;" : "=r"(lp) : "f"(r_hi), "f"(r_lo));
}

// D += A(bf16) * B(bf16);  m16n8k16, A 4 regs, B 2 regs, fp32 accum
#define MMA_BF16(D, A, b0, b1) \
    asm volatile("mma.sync.aligned.m16n8k16.row.col.f32.bf16.bf16.f32 " \
        "{%0,%1,%2,%3}, {%4,%5,%6,%7}, {%8,%9}, {%0,%1,%2,%3};" \
        : "+f"((D)[0]), "+f"((D)[1]), "+f"((D)[2]), "+f"((D)[3]) \
        : "r"((A)[0]), "r"((A)[1]), "r"((A)[2]), "r"((A)[3]), "r"(b0), "r"(b1))

// ================= bf16 hi/lo split for W (fragment-order output) ==========
__global__ void split_w(const float* __restrict__ W1l, const float* __restrict__ W1r) {
    int i = blockIdx.x * blockDim.x + threadIdx.x;
    if (i >= KPAD * 256) return;
    int k = i >> 8, n = i & 255;
    float v = 0.f;
    if (k < N_FEAT) v = (n < 128) ? W1l[k * HIDDEN + n] : W1r[k * HIDDEN + (n - 128)];
    __nv_bfloat16 hb = __float2bfloat16_rn(v);
    unsigned short h = __bfloat16_as_ushort(hb);
    float hf = __uint_as_float((uint32_t)h << 16);
    float r = v - hf;
    unsigned short lo = __bfloat16_as_ushort(__float2bfloat16_rn(r));

    int c    = k >> 4;
    int kr   = k & 15;
    int tig  = (kr >> 1) & 3;
    int bslot = kr >> 3;
    int lh   = kr & 1;
    int nt   = n >> 4;
    int nn   = n & 15;
    int gg   = nn & 7;
    int jh   = nn >> 3;
    int lane = gg * 4 + tig;
    int q    = jh * 2 + bslot;
    size_t word = (((size_t)c * 16 + nt) * 32 + lane) * 4 + q;
    g_whi[word * 2 + lh] = h;
    g_wlo[word * 2 + lh] = lo;
}

// ================= CSR build =================
__global__ void csr_zero() {
    int i = blockIdx.x * blockDim.x + threadIdx.x;
    if (i < N_NODES) g_cnt[i] = 0;
}

__global__ void csr_hist(const int* __restrict__ dst) {
    int e = blockIdx.x * blockDim.x + threadIdx.x;
    if (e < N_EDGES) atomicAdd(&g_cnt[dst[e]], 1);
}

__global__ void __launch_bounds__(SCAN_BLK) csr_scan1() {
    __shared__ int sh[SCAN_BLK];
    int t = threadIdx.x;
    int i = blockIdx.x * SCAN_BLK + t;
    int v = (i < N_NODES) ? g_cnt[i] : 0;
    sh[t] = v;
    __syncthreads();
    #pragma unroll
    for (int off = 1; off < SCAN_BLK; off <<= 1) {
        int add = (t >= off) ? sh[t - off] : 0;
        __syncthreads();
        sh[t] += add;
        __syncthreads();
    }
    if (i < N_NODES) g_rowstart[i] = sh[t] - v;
    if (t == SCAN_BLK - 1) g_blocksum[blockIdx.x] = sh[t];
}

__global__ void __launch_bounds__(256) csr_scan2() {
    __shared__ int sh[256];
    int t = threadIdx.x;
    int v = (t < N_SCAN_BLOCKS) ? g_blocksum[t] : 0;
    sh[t] = v;
    __syncthreads();
    #pragma unroll
    for (int off = 1; off < 256; off <<= 1) {
        int add = (t >= off) ? sh[t - off] : 0;
        __syncthreads();
        sh[t] += add;
        __syncthreads();
    }
    if (t < N_SCAN_BLOCKS) g_blocksum[t] = sh[t] - v;
}

__global__ void csr_scan3() {
    int i = blockIdx.x * blockDim.x + threadIdx.x;
    if (i < N_NODES) {
        int rs = g_rowstart[i] + g_blocksum[i / SCAN_BLK];
        g_rowstart[i] = rs;
        g_cursor[i] = rs;
    }
    if (i == 0) g_rowstart[N_NODES] = N_EDGES;
}

__global__ void csr_scatter(const int* __restrict__ src, const int* __restrict__ dst) {
    int e = blockIdx.x * blockDim.x + threadIdx.x;
    if (e < N_EDGES) {
        int pos = atomicAdd(&g_cursor[dst[e]], 1);
        g_csrsrc[pos] = src[e];
    }
}

// ================= 3xBF16 tensor GEMM: [Yl|Yr] = X @ [W1l|W1r] + b =========
// Block 64x256, 256 thr, warp grid 2x4, cp.async 3-stage (prefetch depth 2).
// Smem: X 3*1280*4 + W 3stg*2pl*2048*4 = 15360 + 49152 = 64512 B.
__global__ void __launch_bounds__(256, 2) gemm_mma(const float* __restrict__ Xp,
                                                   const float* __restrict__ b1l,
                                                   const float* __restrict__ b1r) {
    extern __shared__ float dsm[];
    float* XS = dsm;                             // [3][64][20]
    uint32_t* WS = (uint32_t*)(dsm + 3840);      // [3][pl][2048 words]

    const int tid = threadIdx.x;
    const int wid = tid >> 5;
    const int lane = tid & 31;
    const int g   = lane >> 2;
    const int tig = lane & 3;
    const int wm = wid >> 2;
    const int wn = wid & 3;
    const int row0 = blockIdx.x * 64;

    auto xs_s  = [&](int stg) { return XS + stg * 1280; };
    auto ws_pl = [&](int stg, int pl) { return WS + (stg * 2 + pl) * 2048; };

    auto load_chunk = [&](int c, int stg) {
        int k0 = c * KCHUNK;
        float* xbase = xs_s(stg);
        #pragma unroll
        for (int i = 0; i < 4; i++) {
            int lin = tid + i * 256;
            int m = lin >> 4, k = lin & 15;
            int gr = row0 + m, gk = k0 + k;
            float* dstp = xbase + m * 20 + k;
            if (gr < N_NODES && gk < N_FEAT)
                CPA4(s2u(dstp), Xp + (size_t)gr * N_FEAT + gk);
            else
                *dstp = 0.f;
        }
        const uint32_t* gw0 = (const uint32_t*)g_whi;
        const uint32_t* gw1 = (const uint32_t*)g_wlo;
        const size_t gbase = (size_t)c * 2048;
        uint32_t* w0 = ws_pl(stg, 0);
        uint32_t* w1 = ws_pl(stg, 1);
        #pragma unroll
        for (int i = 0; i < 2; i++) {
            int L = (tid + i * 256) * 4;
            CPA16(s2u(w0 + L), gw0 + gbase + L);
            CPA16(s2u(w1 + L), gw1 + gbase + L);
        }
    };

    float d[2][8][4];
    #pragma unroll
    for (int i = 0; i < 2; i++)
        #pragma unroll
        for (int j = 0; j < 8; j++)
            #pragma unroll
            for (int q = 0; q < 4; q++) d[i][j][q] = 0.f;

    load_chunk(0, 0); CP_COMMIT();
    load_chunk(1, 1); CP_COMMIT();

    for (int c = 0; c < NCHUNKS; c++) {
        int stg = c % 3;
        if (c + 2 < NCHUNKS) load_chunk(c + 2, (c + 2) % 3);
        CP_COMMIT();                 // one group per iteration (may be empty)
        CP_WAIT2();                  // chunk c resident (2 newer groups pending)
        __syncthreads();

        const float* xs = xs_s(stg);
        const uint4* whi4 = (const uint4*)ws_pl(stg, 0);
        const uint4* wlo4 = (const uint4*)ws_pl(stg, 1);

        uint32_t ahi[2][4], alo[2][4];
        #pragma unroll
        for (int i = 0; i < 2; i++) {
            int rb = wm * 32 + i * 16;
            const float* r0p = xs + (rb + g) * 20 + 2 * tig;
            const float* r1p = xs + (rb + g + 8) * 20 + 2 * tig;
            float2 x0 = *(const float2*)r0p;
            float2 x1 = *(const float2*)r1p;
            float2 x2 = *(const float2*)(r0p + 8);
            float2 x3 = *(const float2*)(r1p + 8);
            packsplit(x0.x, x0.y, ahi[i][0], alo[i][0]);
            packsplit(x1.x, x1.y, ahi[i][1], alo[i][1]);
            packsplit(x2.x, x2.y, ahi[i][2], alo[i][2]);
            packsplit(x3.x, x3.y, ahi[i][3], alo[i][3]);
        }

        #pragma unroll
        for (int jp = 0; jp < 4; jp++) {
            int idx = (wn * 4 + jp) * 32 + lane;
            uint4 BH = whi4[idx];
            uint4 BL = wlo4[idx];
            #pragma unroll
            for (int i = 0; i < 2; i++) {
                MMA_BF16(d[i][jp * 2],     ahi[i], BH.x, BH.y);
                MMA_BF16(d[i][jp * 2],     ahi[i], BL.x, BL.y);
                MMA_BF16(d[i][jp * 2],     alo[i], BH.x, BH.y);
                MMA_BF16(d[i][jp * 2 + 1], ahi[i], BH.z, BH.w);
                MMA_BF16(d[i][jp * 2 + 1], ahi[i], BL.z, BL.w);
                MMA_BF16(d[i][jp * 2 + 1], alo[i], BH.z, BH.w);
            }
        }
        __syncthreads();
    }

    // epilogue: D + bias -> g_xl / g_xr
    #pragma unroll
    for (int i = 0; i < 2; i++) {
        int r0 = row0 + wm * 32 + i * 16 + g;
        int r1 = r0 + 8;
        #pragma unroll
        for (int j = 0; j < 8; j++) {
            int col = wn * 64 + j * 8 + tig * 2;
            if (col < 128) {
                float bb0 = __ldg(&b1l[col]), bb1 = __ldg(&b1l[col + 1]);
                if (r0 < N_NODES) {
                    float2 v = make_float2(d[i][j][0] + bb0, d[i][j][1] + bb1);
                    *(float2*)(g_xl + (size_t)r0 * HIDDEN + col) = v;
                }
                if (r1 < N_NODES) {
                    float2 v = make_float2(d[i][j][2] + bb0, d[i][j][3] + bb1);
                    *(float2*)(g_xl + (size_t)r1 * HIDDEN + col) = v;
                }
            } else {
                int c2 = col - 128;
                float bb0 = __ldg(&b1r[c2]), bb1 = __ldg(&b1r[c2 + 1]);
                if (r0 < N_NODES) {
                    float2 v = make_float2(d[i][j][0] + bb0, d[i][j][1] + bb1);
                    *(float2*)(g_xr + (size_t)r0 * HIDDEN + c2) = v;
                }
                if (r1 < N_NODES) {
                    float2 v = make_float2(d[i][j][2] + bb0, d[i][j][3] + bb1);
                    *(float2*)(g_xr + (size_t)r1 * HIDDEN + c2) = v;
                }
            }
        }
    }
}

// ================= layer 1: warp-per-node, 4-wide edge unroll ==============
__global__ void __launch_bounds__(256) layer1_csr(const float* __restrict__ att,
                                                  const float* __restrict__ bias1,
                                                  const float* __restrict__ W2l,
                                                  const float* __restrict__ b2l,
                                                  const float* __restrict__ W2r,
                                                  const float* __restrict__ b2r) {
    int d = (blockIdx.x * blockDim.x + threadIdx.x) >> 5;
    int lane = threadIdx.x & 31;
    if (d >= N_NODES) return;

    float4 xr4  = ((const float4*)(g_xr + (size_t)d * HIDDEN))[lane];
    float4 att4 = __ldg(&((const float4*)att)[lane]);

    float4 xls = ((const float4*)(g_xl + (size_t)d * HIDDEN))[lane];
    float p = warpSum(dot_lrelu(xls, xr4, att4));
    float w = __expf(p);
    float wsum = w;
    float4 acc = make_float4(w * xls.x, w * xls.y, w * xls.z, w * xls.w);

    int j  = g_rowstart[d];
    int re = g_rowstart[d + 1];

    for (; j + 3 < re; j += 4) {
        int s0 = g_csrsrc[j],     s1 = g_csrsrc[j + 1];
        int s2 = g_csrsrc[j + 2], s3 = g_csrsrc[j + 3];
        float4 a0 = ((const float4*)(g_xl + (size_t)s0 * HIDDEN))[lane];
        float4 a1 = ((const float4*)(g_xl + (size_t)s1 * HIDDEN))[lane];
        float4 a2 = ((const float4*)(g_xl + (size_t)s2 * HIDDEN))[lane];
        float4 a3 = ((const float4*)(g_xl + (size_t)s3 * HIDDEN))[lane];
        float p0 = dot_lrelu(a0, xr4, att4);
        float p1 = dot_lrelu(a1, xr4, att4);
        float p2 = dot_lrelu(a2, xr4, att4);
        float p3 = dot_lrelu(a3, xr4, att4);
        warpSum4(p0, p1, p2, p3);
        float w0 = __expf(p0), w1 = __expf(p1);
        float w2 = __expf(p2), w3 = __expf(p3);
        wsum += (w0 + w1) + (w2 + w3);
        acc.x += w0 * a0.x + w1 * a1.x + w2 * a2.x + w3 * a3.x;
        acc.y += w0 * a0.y + w1 * a1.y + w2 * a2.y + w3 * a3.y;
        acc.z += w0 * a0.z + w1 * a1.z + w2 * a2.z + w3 * a3.z;
        acc.w += w0 * a0.w + w1 * a1.w + w2 * a2.w + w3 * a3.w;
    }
    for (; j + 1 < re; j += 2) {
        int s0 = g_csrsrc[j], s1 = g_csrsrc[j + 1];
        float4 a0 = ((const float4*)(g_xl + (size_t)s0 * HIDDEN))[lane];
        float4 a1 = ((const float4*)(g_xl + (size_t)s1 * HIDDEN))[lane];
        float p0 = dot_lrelu(a0, xr4, att4);
        float p1 = dot_lrelu(a1, xr4, att4);
        warpSum2(p0, p1);
        float w0 = __expf(p0), w1 = __expf(p1);
        wsum += w0 + w1;
        acc.x += w0 * a0.x + w1 * a1.x;
        acc.y += w0 * a0.y + w1 * a1.y;
        acc.z += w0 * a0.z + w1 * a1.z;
        acc.w += w0 * a0.w + w1 * a1.w;
    }
    if (j < re) {
        int s0 = g_csrsrc[j];
        float4 a0 = ((const float4*)(g_xl + (size_t)s0 * HIDDEN))[lane];
        float w0 = __expf(warpSum(dot_lrelu(a0, xr4, att4)));
        wsum += w0;
        acc.x += w0 * a0.x; acc.y += w0 * a0.y;
        acc.z += w0 * a0.z; acc.w += w0 * a0.w;
    }

    float inv = __fdividef(1.f, wsum);
    float4 b4 = __ldg(&((const float4*)bias1)[lane]);
    float h0 = acc.x * inv + b4.x;  h0 = h0 > 0.f ? h0 : 0.f;
    float h1 = acc.y * inv + b4.y;  h1 = h1 > 0.f ? h1 : 0.f;
    float h2 = acc.z * inv + b4.z;  h2 = h2 > 0.f ? h2 : 0.f;
    float h3 = acc.w * inv + b4.w;  h3 = h3 > 0.f ? h3 : 0.f;

    float4 wl0 = __ldg(&((const float4*)W2l)[2 * lane]);
    float4 wl1 = __ldg(&((const float4*)W2l)[2 * lane + 1]);
    float4 wr0 = __ldg(&((const float4*)W2r)[2 * lane]);
    float4 wr1 = __ldg(&((const float4*)W2r)[2 * lane + 1]);

    float s0 = h0 * wl0.x + h1 * wl0.z + h2 * wl1.x + h3 * wl1.z;
    float s1 = h0 * wl0.y + h1 * wl0.w + h2 * wl1.y + h3 * wl1.w;
    float s2 = h0 * wr0.x + h1 * wr0.z + h2 * wr1.x + h3 * wr1.z;
    float s3 = h0 * wr0.y + h1 * wr0.w + h2 * wr1.y + h3 * wr1.w;
    warpSum4(s0, s1, s2, s3);

    if (lane == 0) {
        g_hl[2 * d + 0] = s0 + __ldg(&b2l[0]);
        g_hl[2 * d + 1] = s1 + __ldg(&b2l[1]);
        g_hr[2 * d + 0] = s2 + __ldg(&b2r[0]);
        g_hr[2 * d + 1] = s3 + __ldg(&b2r[1]);
    }
}

// ================= layer 2: 8 lanes/node, 4 nodes/warp ====================
// N_NODES*8 = 800000 = 3125 blocks * 256 -> no partial warps.
__global__ void __launch_bounds__(256) layer2_csr(const float* __restrict__ att2,
                                                  const float* __restrict__ bias2,
                                                  float* __restrict__ out) {
    int t = blockIdx.x * blockDim.x + threadIdx.x;
    int d = t >> 3;
    int gl = t & 7;
    if (d >= N_NODES) return;

    float a20 = __ldg(&att2[0]);
    float a21 = __ldg(&att2[1]);
    float2 hr2 = *(const float2*)(g_hr + 2 * d);   // broadcast within group

    float den = 0.f, n0 = 0.f, n1 = 0.f;

    if (gl == 0) {
        float2 hls = *(const float2*)(g_hl + 2 * d);
        float sc = lrelu(hls.x + hr2.x) * a20 + lrelu(hls.y + hr2.y) * a21;
        float w = __expf(sc);
        den = w; n0 = w * hls.x; n1 = w * hls.y;
    }

    int rs = g_rowstart[d];
    int re = g_rowstart[d + 1];
    for (int j = rs + gl; j < re; j += 8) {
        int s = g_csrsrc[j];
        float2 hl = *(const float2*)(g_hl + 2 * s);
        float sc = lrelu(hl.x + hr2.x) * a20 + lrelu(hl.y + hr2.y) * a21;
        float w = __expf(sc);
        den += w; n0 += w * hl.x; n1 += w * hl.y;
    }

    // reduce within 8-lane group
    #pragma unroll
    for (int o = 1; o < 8; o <<= 1) {
        den += __shfl_xor_sync(0xffffffffu, den, o);
        n0  += __shfl_xor_sync(0xffffffffu, n0, o);
        n1  += __shfl_xor_sync(0xffffffffu, n1, o);
    }

    if (gl == 0) {
        float inv = __fdividef(1.f, den);
        out[2 * d + 0] = n0 * inv + __ldg(&bias2[0]);
        out[2 * d + 1] = n1 * inv + __ldg(&bias2[1]);
    }
}

// ---------------- launch ----------------
extern "C" void kernel_launch(void* const* d_in, const int* in_sizes, int n_in,
                              void* d_out, int out_size) {
    const float* x    = (const float*)d_in[0];
    const int*   src  = (const int*)  d_in[1];
    const int*   dst  = (const int*)  d_in[2];
    const float* W1l  = (const float*)d_in[3];
    const float* b1l  = (const float*)d_in[4];
    const float* W1r  = (const float*)d_in[5];
    const float* b1r  = (const float*)d_in[6];
    const float* att1 = (const float*)d_in[7];
    const float* bias1= (const float*)d_in[8];
    const float* W2l  = (const float*)d_in[9];
    const float* b2l  = (const float*)d_in[10];
    const float* W2r  = (const float*)d_in[11];
    const float* b2r  = (const float*)d_in[12];
    const float* att2 = (const float*)d_in[13];
    const float* bias2= (const float*)d_in[14];
    float* out = (float*)d_out;

    const int gemmBlocks = (N_NODES + 63) / 64;               // 1563
    const int edgeBlocks = (N_EDGES + 255) / 256;             // 6250
    const int nodeBlocks = (N_NODES + 255) / 256;             // 391
    const int nodeWarpBlocks = (N_NODES * 32 + 255) / 256;    // 12500
    const int node8Blocks = (N_NODES * 8 + 255) / 256;        // 3125
    const int GEMM_SMEM = 3840 * 4 + 6 * 2048 * 4;            // 64512 B

    cudaFuncSetAttribute((const void*)gemm_mma,
                         cudaFuncAttributeMaxDynamicSharedMemorySize, GEMM_SMEM);

    // gemm_mma kept as 4th launch so ncu (-s 5 -c 1) profiles it.
    split_w<<<(KPAD * 256 + 255) / 256, 256>>>(W1l, W1r);
    csr_zero<<<nodeBlocks, 256>>>();
    csr_hist<<<edgeBlocks, 256>>>(dst);
    gemm_mma<<<gemmBlocks, 256, GEMM_SMEM>>>(x, b1l, b1r);
    csr_scan1<<<N_SCAN_BLOCKS, SCAN_BLK>>>();
    csr_scan2<<<1, 256>>>();
    csr_scan3<<<nodeBlocks, 256>>>();
    csr_scatter<<<edgeBlocks, 256>>>(src, dst);
    layer1_csr<<<nodeWarpBlocks, 256>>>(att1, bias1, W2l, b2l, W2r, b2r);
    layer2_csr<<<node8Blocks, 256>>>(att2, bias2, out);
}

// round 16
// speedup vs baseline: 4.1064x; 1.0210x over previous
#include <cuda_runtime.h>
#include <cuda_bf16.h>
#include <cstdint>

#define N_NODES 100000
#define N_EDGES 1600000
#define N_FEAT  165
#define HIDDEN  128
#define NEG_SLOPE 0.2f
#define SCAN_BLK 512
#define N_SCAN_BLOCKS ((N_NODES + SCAN_BLK - 1) / SCAN_BLK)   // 196
#define KPAD 176
#define KCHUNK 16
#define NCHUNKS 11

// ---------------- scratch (static __device__ arrays; no allocation) -------
__device__ float g_xl[(size_t)N_NODES * HIDDEN];
__device__ float g_xr[(size_t)N_NODES * HIDDEN];
__device__ float g_hl[N_NODES * 2];
__device__ float g_hr[N_NODES * 2];
__device__ int   g_cnt[N_NODES];
__device__ int   g_rowstart[N_NODES + 1];
__device__ int   g_cursor[N_NODES];
__device__ int   g_blocksum[N_SCAN_BLOCKS];
__device__ int   g_csrsrc[N_EDGES];
// bf16 hi/lo planes for W in m16n8k16 fragment order
__device__ unsigned short g_whi[KPAD * 256];
__device__ unsigned short g_wlo[KPAD * 256];

// ---------------- helpers ----------------
__device__ __forceinline__ float warpSum(float v) {
    #pragma unroll
    for (int o = 16; o > 0; o >>= 1) v += __shfl_xor_sync(0xffffffffu, v, o);
    return v;
}

__device__ __forceinline__ void warpSum2(float& a, float& b) {
    #pragma unroll
    for (int o = 16; o > 0; o >>= 1) {
        a += __shfl_xor_sync(0xffffffffu, a, o);
        b += __shfl_xor_sync(0xffffffffu, b, o);
    }
}

__device__ __forceinline__ void warpSum4(float& a, float& b, float& c, float& d) {
    #pragma unroll
    for (int o = 16; o > 0; o >>= 1) {
        a += __shfl_xor_sync(0xffffffffu, a, o);
        b += __shfl_xor_sync(0xffffffffu, b, o);
        c += __shfl_xor_sync(0xffffffffu, c, o);
        d += __shfl_xor_sync(0xffffffffu, d, o);
    }
}

__device__ __forceinline__ float lrelu(float v) {
    return v > 0.f ? v : NEG_SLOPE * v;
}

__device__ __forceinline__ float dot_lrelu(float4 a, float4 b, float4 t) {
    return lrelu(a.x + b.x) * t.x + lrelu(a.y + b.y) * t.y
         + lrelu(a.z + b.z) * t.z + lrelu(a.w + b.w) * t.w;
}

__device__ __forceinline__ uint32_t s2u(const void* p) {
    return (uint32_t)__cvta_generic_to_shared(p);
}
#define CPA4(d, s)  asm volatile("cp.async.ca.shared.global [%0], [%1], 4;"  :: "r"(d), "l"(s))
#define CPA16(d, s) asm volatile("cp.async.cg.shared.global [%0], [%1], 16;" :: "r"(d), "l"(s))
#define CP_COMMIT() asm volatile("cp.async.commit_group;" ::: "memory")
#define CP_WAIT1()  asm volatile("cp.async.wait_group 1;" ::: "memory")
#define CP_WAIT0()  asm volatile("cp.async.wait_group 0;" ::: "memory")

// bf16x3 split: lo_v = element k (lower half), hi_v = element k+1 (upper half)
__device__ __forceinline__ void packsplit(float lo_v, float hi_v,
                                          uint32_t& hp, uint32_t& lp) {
    asm("cvt.rn.bf16x2.f32 %0, %1, %2;" : "=r"(hp) : "f"(hi_v), "f"(lo_v));
    float h_lo = __uint_as_float(hp << 16);
    float h_hi = __uint_as_float(hp & 0xffff0000u);
    float r_lo = lo_v - h_lo;
    float r_hi = hi_v - h_hi;
    asm("cvt.rn.bf16x2.f32 %0, %1, %2;" : "=r"(lp) : "f"(r_hi), "f"(r_lo));
}

// D += A(bf16) * B(bf16);  m16n8k16, A 4 regs, B 2 regs, fp32 accum
#define MMA_BF16(D, A, b0, b1) \
    asm volatile("mma.sync.aligned.m16n8k16.row.col.f32.bf16.bf16.f32 " \
        "{%0,%1,%2,%3}, {%4,%5,%6,%7}, {%8,%9}, {%0,%1,%2,%3};" \
        : "+f"((D)[0]), "+f"((D)[1]), "+f"((D)[2]), "+f"((D)[3]) \
        : "r"((A)[0]), "r"((A)[1]), "r"((A)[2]), "r"((A)[3]), "r"(b0), "r"(b1))

// ================= bf16 hi/lo split for W + g_cnt zeroing ==================
__global__ void split_w(const float* __restrict__ W1l, const float* __restrict__ W1r) {
    int i = blockIdx.x * blockDim.x + threadIdx.x;
    if (i < N_NODES) g_cnt[i] = 0;
    if (i >= KPAD * 256) return;
    int k = i >> 8, n = i & 255;
    float v = 0.f;
    if (k < N_FEAT) v = (n < 128) ? W1l[k * HIDDEN + n] : W1r[k * HIDDEN + (n - 128)];
    __nv_bfloat16 hb = __float2bfloat16_rn(v);
    unsigned short h = __bfloat16_as_ushort(hb);
    float hf = __uint_as_float((uint32_t)h << 16);
    float r = v - hf;
    unsigned short lo = __bfloat16_as_ushort(__float2bfloat16_rn(r));

    int c    = k >> 4;
    int kr   = k & 15;
    int tig  = (kr >> 1) & 3;
    int bslot = kr >> 3;
    int lh   = kr & 1;
    int nt   = n >> 4;
    int nn   = n & 15;
    int gg   = nn & 7;
    int jh   = nn >> 3;
    int lane = gg * 4 + tig;
    int q    = jh * 2 + bslot;
    size_t word = (((size_t)c * 16 + nt) * 32 + lane) * 4 + q;
    g_whi[word * 2 + lh] = h;
    g_wlo[word * 2 + lh] = lo;
}

// ================= CSR build =================
__global__ void csr_hist(const int* __restrict__ dst) {
    int e = blockIdx.x * blockDim.x + threadIdx.x;
    if (e < N_EDGES) atomicAdd(&g_cnt[dst[e]], 1);
}

__global__ void __launch_bounds__(SCAN_BLK) csr_scan1() {
    __shared__ int sh[SCAN_BLK];
    int t = threadIdx.x;
    int i = blockIdx.x * SCAN_BLK + t;
    int v = (i < N_NODES) ? g_cnt[i] : 0;
    sh[t] = v;
    __syncthreads();
    #pragma unroll
    for (int off = 1; off < SCAN_BLK; off <<= 1) {
        int add = (t >= off) ? sh[t - off] : 0;
        __syncthreads();
        sh[t] += add;
        __syncthreads();
    }
    if (i < N_NODES) g_rowstart[i] = sh[t] - v;
    if (t == SCAN_BLK - 1) g_blocksum[blockIdx.x] = sh[t];
}

__global__ void __launch_bounds__(256) csr_scan2() {
    __shared__ int sh[256];
    int t = threadIdx.x;
    int v = (t < N_SCAN_BLOCKS) ? g_blocksum[t] : 0;
    sh[t] = v;
    __syncthreads();
    #pragma unroll
    for (int off = 1; off < 256; off <<= 1) {
        int add = (t >= off) ? sh[t - off] : 0;
        __syncthreads();
        sh[t] += add;
        __syncthreads();
    }
    if (t < N_SCAN_BLOCKS) g_blocksum[t] = sh[t] - v;
}

__global__ void csr_scan3() {
    int i = blockIdx.x * blockDim.x + threadIdx.x;
    if (i < N_NODES) {
        int rs = g_rowstart[i] + g_blocksum[i / SCAN_BLK];
        g_rowstart[i] = rs;
        g_cursor[i] = rs;
    }
    if (i == 0) g_rowstart[N_NODES] = N_EDGES;
}

__global__ void csr_scatter(const int* __restrict__ src, const int* __restrict__ dst) {
    int e = blockIdx.x * blockDim.x + threadIdx.x;
    if (e < N_EDGES) {
        int pos = atomicAdd(&g_cursor[dst[e]], 1);
        g_csrsrc[pos] = src[e];
    }
}

// ================= 3xBF16 tensor GEMM: [Yl|Yr] = X @ [W1l|W1r] + b =========
// Block 64x256, 256 thr, warp grid 2x4, cp.async 2-stage, m16n8k16 bf16.
// MMA schedule: 3 passes (HH, HL, LH) so each accumulator's updates are
// separated by 15 independent MMAs -> no tensor RAW stalls.
// Smem: X 2*1280*4 + W 2stg*2pl*2048*4 = 10240 + 32768 = 43008 B.
__global__ void __launch_bounds__(256, 2) gemm_mma(const float* __restrict__ Xp,
                                                   const float* __restrict__ b1l,
                                                   const float* __restrict__ b1r) {
    extern __shared__ float dsm[];
    float* XS = dsm;                             // [stg][64][20]
    uint32_t* WS = (uint32_t*)(dsm + 2560);      // [stg][pl][2048 words]

    const int tid = threadIdx.x;
    const int wid = tid >> 5;
    const int lane = tid & 31;
    const int g   = lane >> 2;
    const int tig = lane & 3;
    const int wm = wid >> 2;
    const int wn = wid & 3;
    const int row0 = blockIdx.x * 64;

    auto xs_s  = [&](int stg) { return XS + stg * 1280; };
    auto ws_pl = [&](int stg, int pl) { return WS + (stg * 2 + pl) * 2048; };

    auto load_chunk = [&](int c, int stg) {
        int k0 = c * KCHUNK;
        float* xbase = xs_s(stg);
        #pragma unroll
        for (int i = 0; i < 4; i++) {
            int lin = tid + i * 256;
            int m = lin >> 4, k = lin & 15;
            int gr = row0 + m, gk = k0 + k;
            float* dstp = xbase + m * 20 + k;
            if (gr < N_NODES && gk < N_FEAT)
                CPA4(s2u(dstp), Xp + (size_t)gr * N_FEAT + gk);
            else
                *dstp = 0.f;
        }
        const uint32_t* gw0 = (const uint32_t*)g_whi;
        const uint32_t* gw1 = (const uint32_t*)g_wlo;
        const size_t gbase = (size_t)c * 2048;
        uint32_t* w0 = ws_pl(stg, 0);
        uint32_t* w1 = ws_pl(stg, 1);
        #pragma unroll
        for (int i = 0; i < 2; i++) {
            int L = (tid + i * 256) * 4;
            CPA16(s2u(w0 + L), gw0 + gbase + L);
            CPA16(s2u(w1 + L), gw1 + gbase + L);
        }
    };

    float d[2][8][4];
    #pragma unroll
    for (int i = 0; i < 2; i++)
        #pragma unroll
        for (int j = 0; j < 8; j++)
            #pragma unroll
            for (int q = 0; q < 4; q++) d[i][j][q] = 0.f;

    load_chunk(0, 0);
    CP_COMMIT();

    for (int c = 0; c < NCHUNKS; c++) {
        int stg = c & 1;
        if (c + 1 < NCHUNKS) {
            load_chunk(c + 1, (c + 1) & 1);
            CP_COMMIT();
            CP_WAIT1();
        } else {
            CP_WAIT0();
        }
        __syncthreads();

        const float* xs = xs_s(stg);
        const uint4* whi4 = (const uint4*)ws_pl(stg, 0);
        const uint4* wlo4 = (const uint4*)ws_pl(stg, 1);

        // A fragments
        uint32_t ahi[2][4], alo[2][4];
        #pragma unroll
        for (int i = 0; i < 2; i++) {
            int rb = wm * 32 + i * 16;
            const float* r0p = xs + (rb + g) * 20 + 2 * tig;
            const float* r1p = xs + (rb + g + 8) * 20 + 2 * tig;
            float2 x0 = *(const float2*)r0p;
            float2 x1 = *(const float2*)r1p;
            float2 x2 = *(const float2*)(r0p + 8);
            float2 x3 = *(const float2*)(r1p + 8);
            packsplit(x0.x, x0.y, ahi[i][0], alo[i][0]);
            packsplit(x1.x, x1.y, ahi[i][1], alo[i][1]);
            packsplit(x2.x, x2.y, ahi[i][2], alo[i][2]);
            packsplit(x3.x, x3.y, ahi[i][3], alo[i][3]);
        }

        // B fragments for all 4 jp held in registers
        uint4 BH[4], BL[4];
        #pragma unroll
        for (int jp = 0; jp < 4; jp++) {
            int idx = (wn * 4 + jp) * 32 + lane;
            BH[jp] = whi4[idx];
            BL[jp] = wlo4[idx];
        }

        // pass 1: hi*hi  (each accumulator touched once)
        #pragma unroll
        for (int jp = 0; jp < 4; jp++)
            #pragma unroll
            for (int i = 0; i < 2; i++) {
                MMA_BF16(d[i][jp * 2],     ahi[i], BH[jp].x, BH[jp].y);
                MMA_BF16(d[i][jp * 2 + 1], ahi[i], BH[jp].z, BH[jp].w);
            }
        // pass 2: hi*lo
        #pragma unroll
        for (int jp = 0; jp < 4; jp++)
            #pragma unroll
            for (int i = 0; i < 2; i++) {
                MMA_BF16(d[i][jp * 2],     ahi[i], BL[jp].x, BL[jp].y);
                MMA_BF16(d[i][jp * 2 + 1], ahi[i], BL[jp].z, BL[jp].w);
            }
        // pass 3: lo*hi
        #pragma unroll
        for (int jp = 0; jp < 4; jp++)
            #pragma unroll
            for (int i = 0; i < 2; i++) {
                MMA_BF16(d[i][jp * 2],     alo[i], BH[jp].x, BH[jp].y);
                MMA_BF16(d[i][jp * 2 + 1], alo[i], BH[jp].z, BH[jp].w);
            }
        __syncthreads();
    }

    // epilogue: D + bias -> g_xl / g_xr
    #pragma unroll
    for (int i = 0; i < 2; i++) {
        int r0 = row0 + wm * 32 + i * 16 + g;
        int r1 = r0 + 8;
        #pragma unroll
        for (int j = 0; j < 8; j++) {
            int col = wn * 64 + j * 8 + tig * 2;
            if (col < 128) {
                float bb0 = __ldg(&b1l[col]), bb1 = __ldg(&b1l[col + 1]);
                if (r0 < N_NODES) {
                    float2 v = make_float2(d[i][j][0] + bb0, d[i][j][1] + bb1);
                    *(float2*)(g_xl + (size_t)r0 * HIDDEN + col) = v;
                }
                if (r1 < N_NODES) {
                    float2 v = make_float2(d[i][j][2] + bb0, d[i][j][3] + bb1);
                    *(float2*)(g_xl + (size_t)r1 * HIDDEN + col) = v;
                }
            } else {
                int c2 = col - 128;
                float bb0 = __ldg(&b1r[c2]), bb1 = __ldg(&b1r[c2 + 1]);
                if (r0 < N_NODES) {
                    float2 v = make_float2(d[i][j][0] + bb0, d[i][j][1] + bb1);
                    *(float2*)(g_xr + (size_t)r0 * HIDDEN + c2) = v;
                }
                if (r1 < N_NODES) {
                    float2 v = make_float2(d[i][j][2] + bb0, d[i][j][3] + bb1);
                    *(float2*)(g_xr + (size_t)r1 * HIDDEN + c2) = v;
                }
            }
        }
    }
}

// ================= layer 1: warp-per-node, 4-wide edge unroll ==============
__global__ void __launch_bounds__(256) layer1_csr(const float* __restrict__ att,
                                                  const float* __restrict__ bias1,
                                                  const float* __restrict__ W2l,
                                                  const float* __restrict__ b2l,
                                                  const float* __restrict__ W2r,
                                                  const float* __restrict__ b2r) {
    int d = (blockIdx.x * blockDim.x + threadIdx.x) >> 5;
    int lane = threadIdx.x & 31;
    if (d >= N_NODES) return;

    float4 xr4  = ((const float4*)(g_xr + (size_t)d * HIDDEN))[lane];
    float4 att4 = __ldg(&((const float4*)att)[lane]);

    float4 xls = ((const float4*)(g_xl + (size_t)d * HIDDEN))[lane];
    float p = warpSum(dot_lrelu(xls, xr4, att4));
    float w = __expf(p);
    float wsum = w;
    float4 acc = make_float4(w * xls.x, w * xls.y, w * xls.z, w * xls.w);

    int j  = g_rowstart[d];
    int re = g_rowstart[d + 1];

    for (; j + 3 < re; j += 4) {
        int s0 = g_csrsrc[j],     s1 = g_csrsrc[j + 1];
        int s2 = g_csrsrc[j + 2], s3 = g_csrsrc[j + 3];
        float4 a0 = ((const float4*)(g_xl + (size_t)s0 * HIDDEN))[lane];
        float4 a1 = ((const float4*)(g_xl + (size_t)s1 * HIDDEN))[lane];
        float4 a2 = ((const float4*)(g_xl + (size_t)s2 * HIDDEN))[lane];
        float4 a3 = ((const float4*)(g_xl + (size_t)s3 * HIDDEN))[lane];
        float p0 = dot_lrelu(a0, xr4, att4);
        float p1 = dot_lrelu(a1, xr4, att4);
        float p2 = dot_lrelu(a2, xr4, att4);
        float p3 = dot_lrelu(a3, xr4, att4);
        warpSum4(p0, p1, p2, p3);
        float w0 = __expf(p0), w1 = __expf(p1);
        float w2 = __expf(p2), w3 = __expf(p3);
        wsum += (w0 + w1) + (w2 + w3);
        acc.x += w0 * a0.x + w1 * a1.x + w2 * a2.x + w3 * a3.x;
        acc.y += w0 * a0.y + w1 * a1.y + w2 * a2.y + w3 * a3.y;
        acc.z += w0 * a0.z + w1 * a1.z + w2 * a2.z + w3 * a3.z;
        acc.w += w0 * a0.w + w1 * a1.w + w2 * a2.w + w3 * a3.w;
    }
    for (; j + 1 < re; j += 2) {
        int s0 = g_csrsrc[j], s1 = g_csrsrc[j + 1];
        float4 a0 = ((const float4*)(g_xl + (size_t)s0 * HIDDEN))[lane];
        float4 a1 = ((const float4*)(g_xl + (size_t)s1 * HIDDEN))[lane];
        float p0 = dot_lrelu(a0, xr4, att4);
        float p1 = dot_lrelu(a1, xr4, att4);
        warpSum2(p0, p1);
        float w0 = __expf(p0), w1 = __expf(p1);
        wsum += w0 + w1;
        acc.x += w0 * a0.x + w1 * a1.x;
        acc.y += w0 * a0.y + w1 * a1.y;
        acc.z += w0 * a0.z + w1 * a1.z;
        acc.w += w0 * a0.w + w1 * a1.w;
    }
    if (j < re) {
        int s0 = g_csrsrc[j];
        float4 a0 = ((const float4*)(g_xl + (size_t)s0 * HIDDEN))[lane];
        float w0 = __expf(warpSum(dot_lrelu(a0, xr4, att4)));
        wsum += w0;
        acc.x += w0 * a0.x; acc.y += w0 * a0.y;
        acc.z += w0 * a0.z; acc.w += w0 * a0.w;
    }

    float inv = __fdividef(1.f, wsum);
    float4 b4 = __ldg(&((const float4*)bias1)[lane]);
    float h0 = acc.x * inv + b4.x;  h0 = h0 > 0.f ? h0 : 0.f;
    float h1 = acc.y * inv + b4.y;  h1 = h1 > 0.f ? h1 : 0.f;
    float h2 = acc.z * inv + b4.z;  h2 = h2 > 0.f ? h2 : 0.f;
    float h3 = acc.w * inv + b4.w;  h3 = h3 > 0.f ? h3 : 0.f;

    float4 wl0 = __ldg(&((const float4*)W2l)[2 * lane]);
    float4 wl1 = __ldg(&((const float4*)W2l)[2 * lane + 1]);
    float4 wr0 = __ldg(&((const float4*)W2r)[2 * lane]);
    float4 wr1 = __ldg(&((const float4*)W2r)[2 * lane + 1]);

    float s0 = h0 * wl0.x + h1 * wl0.z + h2 * wl1.x + h3 * wl1.z;
    float s1 = h0 * wl0.y + h1 * wl0.w + h2 * wl1.y + h3 * wl1.w;
    float s2 = h0 * wr0.x + h1 * wr0.z + h2 * wr1.x + h3 * wr1.z;
    float s3 = h0 * wr0.y + h1 * wr0.w + h2 * wr1.y + h3 * wr1.w;
    warpSum4(s0, s1, s2, s3);

    if (lane == 0) {
        g_hl[2 * d + 0] = s0 + __ldg(&b2l[0]);
        g_hl[2 * d + 1] = s1 + __ldg(&b2l[1]);
        g_hr[2 * d + 0] = s2 + __ldg(&b2r[0]);
        g_hr[2 * d + 1] = s3 + __ldg(&b2r[1]);
    }
}

// ================= layer 2: 8 lanes/node, 4 nodes/warp ====================
__global__ void __launch_bounds__(256) layer2_csr(const float* __restrict__ att2,
                                                  const float* __restrict__ bias2,
                                                  float* __restrict__ out) {
    int t = blockIdx.x * blockDim.x + threadIdx.x;
    int d = t >> 3;
    int gl = t & 7;
    if (d >= N_NODES) return;

    float a20 = __ldg(&att2[0]);
    float a21 = __ldg(&att2[1]);
    float2 hr2 = *(const float2*)(g_hr + 2 * d);

    float den = 0.f, n0 = 0.f, n1 = 0.f;

    if (gl == 0) {
        float2 hls = *(const float2*)(g_hl + 2 * d);
        float sc = lrelu(hls.x + hr2.x) * a20 + lrelu(hls.y + hr2.y) * a21;
        float w = __expf(sc);
        den = w; n0 = w * hls.x; n1 = w * hls.y;
    }

    int rs = g_rowstart[d];
    int re = g_rowstart[d + 1];
    for (int j = rs + gl; j < re; j += 8) {
        int s = g_csrsrc[j];
        float2 hl = *(const float2*)(g_hl + 2 * s);
        float sc = lrelu(hl.x + hr2.x) * a20 + lrelu(hl.y + hr2.y) * a21;
        float w = __expf(sc);
        den += w; n0 += w * hl.x; n1 += w * hl.y;
    }

    #pragma unroll
    for (int o = 1; o < 8; o <<= 1) {
        den += __shfl_xor_sync(0xffffffffu, den, o);
        n0  += __shfl_xor_sync(0xffffffffu, n0, o);
        n1  += __shfl_xor_sync(0xffffffffu, n1, o);
    }

    if (gl == 0) {
        float inv = __fdividef(1.f, den);
        out[2 * d + 0] = n0 * inv + __ldg(&bias2[0]);
        out[2 * d + 1] = n1 * inv + __ldg(&bias2[1]);
    }
}

// ---------------- launch ----------------
extern "C" void kernel_launch(void* const* d_in, const int* in_sizes, int n_in,
                              void* d_out, int out_size) {
    const float* x    = (const float*)d_in[0];
    const int*   src  = (const int*)  d_in[1];
    const int*   dst  = (const int*)  d_in[2];
    const float* W1l  = (const float*)d_in[3];
    const float* b1l  = (const float*)d_in[4];
    const float* W1r  = (const float*)d_in[5];
    const float* b1r  = (const float*)d_in[6];
    const float* att1 = (const float*)d_in[7];
    const float* bias1= (const float*)d_in[8];
    const float* W2l  = (const float*)d_in[9];
    const float* b2l  = (const float*)d_in[10];
    const float* W2r  = (const float*)d_in[11];
    const float* b2r  = (const float*)d_in[12];
    const float* att2 = (const float*)d_in[13];
    const float* bias2= (const float*)d_in[14];
    float* out = (float*)d_out;

    const int gemmBlocks = (N_NODES + 63) / 64;               // 1563
    const int edgeBlocks = (N_EDGES + 255) / 256;             // 6250
    const int nodeBlocks = (N_NODES + 255) / 256;             // 391
    const int nodeWarpBlocks = (N_NODES * 32 + 255) / 256;    // 12500
    const int node8Blocks = (N_NODES * 8 + 255) / 256;        // 3125
    const int GEMM_SMEM = 2560 * 4 + 4 * 2048 * 4;            // 43008 B

    cudaFuncSetAttribute((const void*)gemm_mma,
                         cudaFuncAttributeMaxDynamicSharedMemorySize, GEMM_SMEM);

    // gemm_mma kept as 4th launch so ncu (-s 5 -c 1) profiles it.
    split_w<<<nodeBlocks, 256>>>(W1l, W1r);    // also zeroes g_cnt
    csr_hist<<<edgeBlocks, 256>>>(dst);
    csr_scan1<<<N_SCAN_BLOCKS, SCAN_BLK>>>();
    gemm_mma<<<gemmBlocks, 256, GEMM_SMEM>>>(x, b1l, b1r);
    csr_scan2<<<1, 256>>>();
    csr_scan3<<<nodeBlocks, 256>>>();
    csr_scatter<<<edgeBlocks, 256>>>(src, dst);
    layer1_csr<<<nodeWarpBlocks, 256>>>(att1, bias1, W2l, b2l, W2r, b2r);
    layer2_csr<<<node8Blocks, 256>>>(att2, bias2, out);
}